// round 1
// baseline (speedup 1.0000x reference)
#include <cuda_runtime.h>
#include <cstdint>

// Problem constants
#define DD   1024
#define SS   1024
#define TT   16
#define PP   256
#define BB   8
#define BT   128      // B*T
#define MROWS 32768   // B*T*P

// ---------------- scratch (device globals; no allocation allowed) ----------------
__device__ float g_Wot [SS*DD];   // W_out^T : [s,d]
__device__ float g_WinT[DD*SS];   // W_in^T  : [d,s]
__device__ float g_H   [SS*DD];   // Bm @ Wot
__device__ float g_G   [SS*DD];   // A  @ Wot
__device__ float g_Mw  [DD*DD];   // WinT @ H
__device__ float g_xbar[BT*DD];
__device__ float g_m   [BT*SS];
__device__ float g_q   [BT*SS];
__device__ float g_states[BT*SS]; // state_t for t=0..15 per b : [(b*16+t), s]
__device__ float g_r   [BT*DD];
__device__ float g_c   [DD];

// ---------------- transpose 1024x1024 ----------------
__global__ void transpose_k(const float* __restrict__ in, float* __restrict__ out) {
    __shared__ float tile[32][33];
    int x = blockIdx.x * 32 + threadIdx.x;
    int y = blockIdx.y * 32 + threadIdx.y;
#pragma unroll
    for (int i = 0; i < 32; i += 8)
        tile[threadIdx.y + i][threadIdx.x] = in[(size_t)(y + i) * DD + x];
    __syncthreads();
    x = blockIdx.y * 32 + threadIdx.x;
    y = blockIdx.x * 32 + threadIdx.y;
#pragma unroll
    for (int i = 0; i < 32; i += 8)
        out[(size_t)(y + i) * DD + x] = tile[threadIdx.x][threadIdx.y + i];
}

// ---------------- generic NN SGEMM: C[M,N] = A[M,K] @ B[K,N] (+ bias over N) ----------------
template <int BM, int BN, int BK, int TM, int TN, bool BIAS>
__global__ void __launch_bounds__((BM / TM) * (BN / TN))
sgemm_nn(int M, int N, int K,
         const float* __restrict__ A, const float* __restrict__ B,
         float* __restrict__ C, const float* __restrict__ bias) {
    constexpr int THREADS = (BM / TM) * (BN / TN);
    __shared__ float As[BK][BM];
    __shared__ float Bs[BK][BN];
    const int tid = threadIdx.x;
    const int tx = tid % (BN / TN);
    const int ty = tid / (BN / TN);
    const float* Ag = A + (size_t)blockIdx.y * BM * K;
    const float* Bg = B + (size_t)blockIdx.x * BN;
    float acc[TM][TN] = {};
    constexpr int AIT = (BM * BK) / (THREADS * 4);
    constexpr int BIT = (BK * BN) / (THREADS * 4);
    static_assert(AIT >= 1 && BIT >= 1, "tile/thread mismatch");

    for (int k0 = 0; k0 < K; k0 += BK) {
#pragma unroll
        for (int it = 0; it < AIT; it++) {
            int i = tid * 4 + it * THREADS * 4;
            int r = i / BK, c = i % BK;
            float4 v = *(const float4*)(Ag + (size_t)r * K + k0 + c);
            As[c + 0][r] = v.x; As[c + 1][r] = v.y;
            As[c + 2][r] = v.z; As[c + 3][r] = v.w;
        }
#pragma unroll
        for (int it = 0; it < BIT; it++) {
            int i = tid * 4 + it * THREADS * 4;
            int r = i / BN, c = i % BN;
            *(float4*)(&Bs[r][c]) = *(const float4*)(Bg + (size_t)(k0 + r) * N + c);
        }
        __syncthreads();
#pragma unroll
        for (int k = 0; k < BK; k++) {
            float a[TM], bv[TN];
#pragma unroll
            for (int i = 0; i < TM; i++) a[i] = As[k][ty * TM + i];
#pragma unroll
            for (int j = 0; j < TN; j++) bv[j] = Bs[k][tx * TN + j];
#pragma unroll
            for (int i = 0; i < TM; i++)
#pragma unroll
                for (int j = 0; j < TN; j++) acc[i][j] += a[i] * bv[j];
        }
        __syncthreads();
    }
#pragma unroll
    for (int i = 0; i < TM; i++) {
        int row = blockIdx.y * BM + ty * TM + i;
#pragma unroll
        for (int j = 0; j < TN; j++) {
            int cn = blockIdx.x * BN + tx * TN + j;
            float v = acc[i][j];
            if (BIAS) v += bias[cn];
            C[(size_t)row * N + cn] = v;
        }
    }
}

// ---------------- c[d] = b_in @ H + b_out ----------------
__global__ void cvec_k(const float* __restrict__ b_in, const float* __restrict__ b_out) {
    int d = blockIdx.x * 256 + threadIdx.x;
    float s = b_out[d];
    for (int j = 0; j < SS; j++) s += b_in[j] * g_H[(size_t)j * DD + d];
    g_c[d] = s;
}

// ---------------- xbar[bt,d] = mean_p (x[bt*256+p, d] + pos[t*256+p, d]) ----------------
__global__ void xbar_k(const float* __restrict__ x, const float* __restrict__ pos) {
    int d  = blockIdx.x * 256 + threadIdx.x;   // gridDim.x = 4
    int bt = blockIdx.y;                        // 128
    int t  = bt & 15;
    const float* xp = x   + (size_t)bt * PP * DD + d;
    const float* pp = pos + (size_t)t  * PP * DD + d;
    float s = 0.f;
#pragma unroll 4
    for (int p = 0; p < PP; p++) s += xp[(size_t)p * DD] + pp[(size_t)p * DD];
    g_xbar[(size_t)bt * DD + d] = s * (1.0f / PP);
}

// ---------------- scan ----------------
__global__ void scan_init_k(const float* __restrict__ init) {
    int s = blockIdx.x * 256 + threadIdx.x;     // gridDim.x = 4
    float v = init[s];
#pragma unroll
    for (int b = 0; b < BB; b++) g_states[(size_t)(b * 16) * SS + s] = v;
}

// state_{t+1}[b] = state_t[b] @ A + q[b*16+t]
__global__ void __launch_bounds__(256) scan_step_k(const float* __restrict__ Amat, int t) {
    __shared__ float st[BB][SS];      // 32 KB: all 8 batch states at time t
    __shared__ float red[BB][256];    // 8 KB reduction
    int tid = threadIdx.x;
    for (int i = tid; i < BB * SS; i += 256) {
        int b = i >> 10, s = i & 1023;
        st[b][s] = g_states[(size_t)(b * 16 + t) * SS + s];
    }
    __syncthreads();
    int col  = blockIdx.x * 128 + (tid & 127);  // gridDim.x = 8
    int half = tid >> 7;
    float acc[BB] = {};
    int k0 = half * 512;
#pragma unroll 4
    for (int k = k0; k < k0 + 512; k++) {
        float av = Amat[(size_t)k * SS + col];
#pragma unroll
        for (int b = 0; b < BB; b++) acc[b] += st[b][k] * av;
    }
#pragma unroll
    for (int b = 0; b < BB; b++) red[b][tid] = acc[b];
    __syncthreads();
    if (half == 0) {
#pragma unroll
        for (int b = 0; b < BB; b++) {
            float v = red[b][tid] + red[b][tid + 128] + g_q[(size_t)(b * 16 + t) * SS + col];
            g_states[(size_t)(b * 16 + t + 1) * SS + col] = v;
        }
    }
}

// ---------------- main GEMM: out = (x + pos) @ Mw + r[bt] + c ----------------
__global__ void __launch_bounds__(256) main_gemm_k(const float* __restrict__ x,
                                                   const float* __restrict__ pos,
                                                   float* __restrict__ out) {
    constexpr int BM = 128, BN = 128, BK = 16;
    __shared__ float As[BK][BM];
    __shared__ float Bs[BK][BN];
    int tid = threadIdx.x;
    int tx = tid % 16, ty = tid / 16;
    int rowBase = blockIdx.y * BM;
    int colBase = blockIdx.x * BN;
    float acc[8][8] = {};

    for (int k0 = 0; k0 < 1024; k0 += BK) {
#pragma unroll
        for (int it = 0; it < 2; it++) {
            int i = tid * 4 + it * 1024;
            int r = i / BK, c = i % BK;
            int row = rowBase + r;
            float4 vx = *(const float4*)(x   + (size_t)row * 1024 + k0 + c);
            float4 vp = *(const float4*)(pos + (size_t)(row & 4095) * 1024 + k0 + c);
            As[c + 0][r] = vx.x + vp.x; As[c + 1][r] = vx.y + vp.y;
            As[c + 2][r] = vx.z + vp.z; As[c + 3][r] = vx.w + vp.w;
        }
#pragma unroll
        for (int it = 0; it < 2; it++) {
            int i = tid * 4 + it * 1024;
            int r = i / BN, c = i % BN;
            *(float4*)(&Bs[r][c]) = *(const float4*)(g_Mw + (size_t)(k0 + r) * 1024 + colBase + c);
        }
        __syncthreads();
#pragma unroll
        for (int k = 0; k < BK; k++) {
            float a[8], b[8];
#pragma unroll
            for (int i = 0; i < 8; i++) a[i] = As[k][ty * 8 + i];
#pragma unroll
            for (int j = 0; j < 8; j++) b[j] = Bs[k][tx * 8 + j];
#pragma unroll
            for (int i = 0; i < 8; i++)
#pragma unroll
                for (int j = 0; j < 8; j++) acc[i][j] += a[i] * b[j];
        }
        __syncthreads();
    }

#pragma unroll
    for (int i = 0; i < 8; i++) {
        int row = rowBase + ty * 8 + i;
        int bt = row >> 8;
#pragma unroll
        for (int j = 0; j < 8; j += 4) {
            int cn = colBase + tx * 8 + j;
            float4 o;
            o.x = acc[i][j + 0] + g_r[(size_t)bt * 1024 + cn + 0] + g_c[cn + 0];
            o.y = acc[i][j + 1] + g_r[(size_t)bt * 1024 + cn + 1] + g_c[cn + 1];
            o.z = acc[i][j + 2] + g_r[(size_t)bt * 1024 + cn + 2] + g_c[cn + 2];
            o.w = acc[i][j + 3] + g_r[(size_t)bt * 1024 + cn + 3] + g_c[cn + 3];
            *(float4*)(out + (size_t)row * 1024 + cn) = o;
        }
    }
}

// ---------------- host ----------------
extern "C" void kernel_launch(void* const* d_in, const int* in_sizes, int n_in,
                              void* d_out, int out_size) {
    const float* x     = (const float*)d_in[0];
    const float* pos   = (const float*)d_in[1];
    const float* W_in  = (const float*)d_in[2];
    const float* b_in  = (const float*)d_in[3];
    const float* W_out = (const float*)d_in[4];
    const float* b_out = (const float*)d_in[5];
    const float* Amat  = (const float*)d_in[6];
    const float* Bm    = (const float*)d_in[7];
    const float* init  = (const float*)d_in[8];
    float* out = (float*)d_out;

    float *Wot, *WinT, *H, *G, *Mw, *xbar, *m, *q, *states, *r;
    cudaGetSymbolAddress((void**)&Wot,    g_Wot);
    cudaGetSymbolAddress((void**)&WinT,   g_WinT);
    cudaGetSymbolAddress((void**)&H,      g_H);
    cudaGetSymbolAddress((void**)&G,      g_G);
    cudaGetSymbolAddress((void**)&Mw,     g_Mw);
    cudaGetSymbolAddress((void**)&xbar,   g_xbar);
    cudaGetSymbolAddress((void**)&m,      g_m);
    cudaGetSymbolAddress((void**)&q,      g_q);
    cudaGetSymbolAddress((void**)&states, g_states);
    cudaGetSymbolAddress((void**)&r,      g_r);

    // 1) transposed weight copies
    transpose_k<<<dim3(32, 32), dim3(32, 8)>>>(W_out, Wot);
    transpose_k<<<dim3(32, 32), dim3(32, 8)>>>(W_in,  WinT);

    // 2) fused weights: H = Bm@Wot, G = A@Wot, Mw = WinT@H
    sgemm_nn<64, 64, 16, 4, 4, false><<<dim3(16, 16), 256>>>(1024, 1024, 1024, Bm,   Wot, H,  nullptr);
    sgemm_nn<64, 64, 16, 4, 4, false><<<dim3(16, 16), 256>>>(1024, 1024, 1024, Amat, Wot, G,  nullptr);
    sgemm_nn<64, 64, 16, 4, 4, false><<<dim3(16, 16), 256>>>(1024, 1024, 1024, WinT, H,   Mw, nullptr);

    // 3) constant vector c = b_in@H + b_out
    cvec_k<<<4, 256>>>(b_in, b_out);

    // 4) xbar = mean_p(x + pos)
    xbar_k<<<dim3(4, 128), 256>>>(x, pos);

    // 5) m = xbar@WinT + b_in ; q = m@Bm
    sgemm_nn<32, 64, 32, 2, 4, true ><<<dim3(16, 4), 256>>>(128, 1024, 1024, xbar, WinT, m, b_in);
    sgemm_nn<32, 64, 32, 2, 4, false><<<dim3(16, 4), 256>>>(128, 1024, 1024, m,    Bm,   q, nullptr);

    // 6) scan: state_{t+1} = state_t@A + q_t  (store states t=0..15)
    scan_init_k<<<4, 256>>>(init);
    for (int t = 0; t < 15; t++) scan_step_k<<<8, 256>>>(Amat, t);

    // 7) r = states@G
    sgemm_nn<32, 64, 32, 2, 4, false><<<dim3(16, 4), 256>>>(128, 1024, 1024, states, G, r, nullptr);

    // 8) out = (x+pos)@Mw + r[bt] + c
    main_gemm_k<<<dim3(8, 256), 256>>>(x, pos, out);
}

// round 3
// speedup vs baseline: 1.7007x; 1.7007x over previous
#include <cuda_runtime.h>
#include <cstdint>

#define DD   1024
#define SS   1024
#define TT   16
#define PP   256
#define BB   8
#define BT   128
#define MROWS 32768

// ---------------- device scratch ----------------
__device__ float g_Wot [SS*DD];   // rna(W_out^T)
__device__ float g_WinT[DD*SS];   // W_in^T (fp32)
__device__ float g_H   [SS*DD];   // rna(Bm @ Wot)
__device__ float g_G   [SS*DD];   // rna(A  @ Wot)
__device__ float g_Mw  [DD*DD];   // rna(WinT @ H)
__device__ float g_xbar[BT*DD];
__device__ float g_m   [BT*SS];
__device__ float g_q   [BT*SS];
__device__ float g_states[BT*SS];
__device__ float g_r   [BT*DD];
__device__ float g_c   [DD];

// ---------------- helpers ----------------
__device__ __forceinline__ float f_rna(float v) {
    uint32_t u;
    asm("cvt.rna.tf32.f32 %0, %1;" : "=r"(u) : "f"(v));
    return __uint_as_float(u);
}
__device__ __forceinline__ void cp_async16(void* dst_smem, const void* src) {
    uint32_t d;
    asm("{ .reg .u64 t; cvta.to.shared.u64 t, %1; cvt.u32.u64 %0, t; }" : "=r"(d) : "l"(dst_smem));
    asm volatile("cp.async.cg.shared.global [%0], [%1], 16;" :: "r"(d), "l"(src) : "memory");
}
#define CP_COMMIT() asm volatile("cp.async.commit_group;" ::: "memory")
#define CP_WAIT0()  asm volatile("cp.async.wait_group 0;" ::: "memory")

__device__ __forceinline__ void mma_tf32(float* d, const uint32_t* a, const uint32_t* b) {
    asm volatile(
        "mma.sync.aligned.m16n8k8.row.col.f32.tf32.tf32.f32 "
        "{%0,%1,%2,%3}, {%4,%5,%6,%7}, {%8,%9}, {%0,%1,%2,%3};"
        : "+f"(d[0]), "+f"(d[1]), "+f"(d[2]), "+f"(d[3])
        : "r"(a[0]), "r"(a[1]), "r"(a[2]), "r"(a[3]), "r"(b[0]), "r"(b[1]));
}

// ================= tf32 tensor-core GEMM =================
// CTA tile 128x128, K chunk 32, double buffered. 256 threads = 8 warps (2m x 4n),
// warp tile 64x32, mma m16n8k8.
// FUSE_X: A = rna(x + pos) streamed from the two inputs.
// EPI_RC: C = acc + g_r[row>>8] + g_c  (main output). else C = rna(acc).
// DUAL:   blockIdx.z selects (Aop,Cop) vs (Aop2,Cop2).
#define AS_STRIDE 36
#define BS_STRIDE 136
#define ASZ (2*128*AS_STRIDE)
#define BSZ (2*32*BS_STRIDE)
#define GEMM_SMEM ((ASZ + BSZ) * 4)

template <bool FUSE_X, bool EPI_RC, bool DUAL>
__global__ void __launch_bounds__(256, 1) tf32_gemm(
    const float* __restrict__ Aop, const float* __restrict__ Aop2,
    const float* __restrict__ pos,
    const float* __restrict__ Bop,
    float* __restrict__ Cop, float* __restrict__ Cop2)
{
    extern __shared__ float smem[];
    float* As = smem;          // [2][128][AS_STRIDE]
    float* Bs = smem + ASZ;    // [2][32][BS_STRIDE]

    const int tid  = threadIdx.x;
    const int lane = tid & 31;
    const int w    = tid >> 5;
    const int wm   = (w >> 2) * 64;
    const int wn   = (w & 3) * 32;
    const int g    = lane >> 2;
    const int tg   = lane & 3;

    const int rowBase = blockIdx.y * 128;
    const int colBase = blockIdx.x * 128;
    const float* __restrict__ Asel = (DUAL && blockIdx.z) ? Aop2 : Aop;
    float* __restrict__ Csel       = (DUAL && blockIdx.z) ? Cop2 : Cop;

    float acc[4][4][4];
#pragma unroll
    for (int i = 0; i < 4; i++)
#pragma unroll
        for (int j = 0; j < 4; j++)
#pragma unroll
            for (int k = 0; k < 4; k++) acc[i][j][k] = 0.f;

    // ---- loaders ----
    auto loadA = [&](float4* ax, int k0) {
#pragma unroll
        for (int i = 0; i < 4; i++) {
            int f = tid + i * 256;            // 1024 float4 = 128 rows x 8
            int r = f >> 3, c4 = f & 7;
            float4 v = *(const float4*)(Asel + (size_t)(rowBase + r) * 1024 + k0 + c4 * 4);
            if (FUSE_X) {
                float4 p = *(const float4*)(pos + (size_t)((rowBase + r) & 4095) * 1024 + k0 + c4 * 4);
                v.x += p.x; v.y += p.y; v.z += p.z; v.w += p.w;
            }
            v.x = f_rna(v.x); v.y = f_rna(v.y); v.z = f_rna(v.z); v.w = f_rna(v.w);
            ax[i] = v;
        }
    };
    auto stsA = [&](const float4* ax, int buf) {
        float* dst = As + buf * 128 * AS_STRIDE;
#pragma unroll
        for (int i = 0; i < 4; i++) {
            int f = tid + i * 256;
            int r = f >> 3, c4 = f & 7;
            *(float4*)(dst + r * AS_STRIDE + c4 * 4) = ax[i];
        }
    };
    auto cpB = [&](int chunk, int buf) {
        float* dst = Bs + buf * 32 * BS_STRIDE;
        const float* src = Bop + (size_t)chunk * 32 * 1024 + colBase;
#pragma unroll
        for (int i = 0; i < 4; i++) {
            int f = tid + i * 256;            // 1024 float4 = 32 rows x 32
            int kr = f >> 5, n4 = f & 31;
            cp_async16(dst + kr * BS_STRIDE + n4 * 4,
                       src + (size_t)kr * 1024 + n4 * 4);
        }
    };
    auto compute = [&](int buf) {
        const float* Ab = As + buf * 128 * AS_STRIDE;
        const float* Bb = Bs + buf * 32 * BS_STRIDE;
#pragma unroll
        for (int kk = 0; kk < 4; kk++) {
            const int k = kk * 8;
            uint32_t a[4][4], b[4][2];
#pragma unroll
            for (int mi = 0; mi < 4; mi++) {
                const float* p0 = Ab + (wm + mi * 16 + g) * AS_STRIDE + k + tg;
                const float* p1 = p0 + 8 * AS_STRIDE;
                a[mi][0] = __float_as_uint(p0[0]);
                a[mi][1] = __float_as_uint(p1[0]);
                a[mi][2] = __float_as_uint(p0[4]);
                a[mi][3] = __float_as_uint(p1[4]);
            }
#pragma unroll
            for (int ni = 0; ni < 4; ni++) {
                const float* q0 = Bb + (k + tg) * BS_STRIDE + wn + ni * 8 + g;
                b[ni][0] = __float_as_uint(q0[0]);
                b[ni][1] = __float_as_uint(q0[4 * BS_STRIDE]);
            }
#pragma unroll
            for (int mi = 0; mi < 4; mi++)
#pragma unroll
                for (int ni = 0; ni < 4; ni++) mma_tf32(acc[mi][ni], a[mi], b[ni]);
        }
    };

    // ---- pipeline ----
    {
        float4 ax[4];
        loadA(ax, 0);
        cpB(0, 0);
        CP_COMMIT();
        stsA(ax, 0);
        CP_WAIT0();
    }
    __syncthreads();

#pragma unroll 1
    for (int c = 0; c < 32; c++) {
        const int buf = c & 1;
        float4 ax[4];
        if (c < 31) {
            loadA(ax, (c + 1) * 32);
            cpB(c + 1, buf ^ 1);
            CP_COMMIT();
        }
        compute(buf);
        if (c < 31) {
            stsA(ax, buf ^ 1);
            CP_WAIT0();
        }
        __syncthreads();
    }

    // ---- epilogue ----
#pragma unroll
    for (int mi = 0; mi < 4; mi++) {
        const int row0 = rowBase + wm + mi * 16 + g;
        const int row1 = row0 + 8;
#pragma unroll
        for (int ni = 0; ni < 4; ni++) {
            const int col = colBase + wn + ni * 8 + tg * 2;
            float v0 = acc[mi][ni][0], v1 = acc[mi][ni][1];
            float v2 = acc[mi][ni][2], v3 = acc[mi][ni][3];
            if (EPI_RC) {
                const float* r0 = g_r + (size_t)(row0 >> 8) * 1024 + col;
                const float* r1 = g_r + (size_t)(row1 >> 8) * 1024 + col;
                float2 ra = *(const float2*)r0;
                float2 rb = *(const float2*)r1;
                float2 cc = *(const float2*)(g_c + col);
                v0 += ra.x + cc.x; v1 += ra.y + cc.y;
                v2 += rb.x + cc.x; v3 += rb.y + cc.y;
            } else {
                v0 = f_rna(v0); v1 = f_rna(v1); v2 = f_rna(v2); v3 = f_rna(v3);
            }
            *(float2*)(Csel + (size_t)row0 * 1024 + col) = make_float2(v0, v1);
            *(float2*)(Csel + (size_t)row1 * 1024 + col) = make_float2(v2, v3);
        }
    }
}

// ---------------- transpose 1024x1024 (optionally rna) ----------------
template <bool RNA>
__global__ void transpose_k(const float* __restrict__ in, float* __restrict__ out) {
    __shared__ float tile[32][33];
    int x = blockIdx.x * 32 + threadIdx.x;
    int y = blockIdx.y * 32 + threadIdx.y;
#pragma unroll
    for (int i = 0; i < 32; i += 8)
        tile[threadIdx.y + i][threadIdx.x] = in[(size_t)(y + i) * DD + x];
    __syncthreads();
    x = blockIdx.y * 32 + threadIdx.x;
    y = blockIdx.x * 32 + threadIdx.y;
#pragma unroll
    for (int i = 0; i < 32; i += 8) {
        float v = tile[threadIdx.x][threadIdx.y + i];
        out[(size_t)(y + i) * DD + x] = RNA ? f_rna(v) : v;
    }
}

// ---------------- fp32 SGEMM for small matrices ----------------
template <int BM, int BN, int BK, int TM, int TN, bool BIAS>
__global__ void __launch_bounds__((BM / TM) * (BN / TN))
sgemm_nn(int M, int N, int K,
         const float* __restrict__ A, const float* __restrict__ B,
         float* __restrict__ C, const float* __restrict__ bias) {
    constexpr int THREADS = (BM / TM) * (BN / TN);
    __shared__ float As[BK][BM];
    __shared__ float Bs[BK][BN];
    const int tid = threadIdx.x;
    const int tx = tid % (BN / TN);
    const int ty = tid / (BN / TN);
    const float* Ag = A + (size_t)blockIdx.y * BM * K;
    const float* Bg = B + (size_t)blockIdx.x * BN;
    float acc[TM][TN] = {};
    constexpr int AIT = (BM * BK) / (THREADS * 4);
    constexpr int BIT = (BK * BN) / (THREADS * 4);
    static_assert(AIT >= 1 && BIT >= 1, "tile/thread mismatch");

    for (int k0 = 0; k0 < K; k0 += BK) {
#pragma unroll
        for (int it = 0; it < AIT; it++) {
            int i = tid * 4 + it * THREADS * 4;
            int r = i / BK, c = i % BK;
            float4 v = *(const float4*)(Ag + (size_t)r * K + k0 + c);
            As[c + 0][r] = v.x; As[c + 1][r] = v.y;
            As[c + 2][r] = v.z; As[c + 3][r] = v.w;
        }
#pragma unroll
        for (int it = 0; it < BIT; it++) {
            int i = tid * 4 + it * THREADS * 4;
            int r = i / BN, c = i % BN;
            *(float4*)(&Bs[r][c]) = *(const float4*)(Bg + (size_t)(k0 + r) * N + c);
        }
        __syncthreads();
#pragma unroll
        for (int k = 0; k < BK; k++) {
            float a[TM], bv[TN];
#pragma unroll
            for (int i = 0; i < TM; i++) a[i] = As[k][ty * TM + i];
#pragma unroll
            for (int j = 0; j < TN; j++) bv[j] = Bs[k][tx * TN + j];
#pragma unroll
            for (int i = 0; i < TM; i++)
#pragma unroll
                for (int j = 0; j < TN; j++) acc[i][j] += a[i] * bv[j];
        }
        __syncthreads();
    }
#pragma unroll
    for (int i = 0; i < TM; i++) {
        int row = blockIdx.y * BM + ty * TM + i;
#pragma unroll
        for (int j = 0; j < TN; j++) {
            int cn = blockIdx.x * BN + tx * TN + j;
            float v = acc[i][j];
            if (BIAS) v += bias[cn];
            C[(size_t)row * N + cn] = v;
        }
    }
}

// ---------------- c[d] = b_in @ H + b_out ----------------
__global__ void cvec_k(const float* __restrict__ b_in, const float* __restrict__ b_out) {
    int d = blockIdx.x * 256 + threadIdx.x;
    float s = b_out[d];
    for (int j = 0; j < SS; j++) s += b_in[j] * g_H[(size_t)j * DD + d];
    g_c[d] = s;
}

// ---------------- xbar[bt,d] = mean_p (x + pos) ----------------
__global__ void xbar_k(const float* __restrict__ x, const float* __restrict__ pos) {
    int d  = blockIdx.x * 256 + threadIdx.x;
    int bt = blockIdx.y;
    int t  = bt & 15;
    const float* xp = x   + (size_t)bt * PP * DD + d;
    const float* pp = pos + (size_t)t  * PP * DD + d;
    float s = 0.f;
#pragma unroll 4
    for (int p = 0; p < PP; p++) s += xp[(size_t)p * DD] + pp[(size_t)p * DD];
    g_xbar[(size_t)bt * DD + d] = s * (1.0f / PP);
}

// ---------------- scan ----------------
__global__ void scan_init_k(const float* __restrict__ init) {
    int s = blockIdx.x * 256 + threadIdx.x;
    float v = init[s];
#pragma unroll
    for (int b = 0; b < BB; b++) g_states[(size_t)(b * 16) * SS + s] = v;
}

__global__ void __launch_bounds__(256) scan_step_k(const float* __restrict__ Amat, int t) {
    __shared__ float st[BB][SS];
    __shared__ float red[BB][256];
    int tid = threadIdx.x;
    for (int i = tid; i < BB * SS; i += 256) {
        int b = i >> 10, s = i & 1023;
        st[b][s] = g_states[(size_t)(b * 16 + t) * SS + s];
    }
    __syncthreads();
    int col  = blockIdx.x * 128 + (tid & 127);
    int half = tid >> 7;
    float acc[BB] = {};
    int k0 = half * 512;
#pragma unroll 4
    for (int k = k0; k < k0 + 512; k++) {
        float av = Amat[(size_t)k * SS + col];
#pragma unroll
        for (int b = 0; b < BB; b++) acc[b] += st[b][k] * av;
    }
#pragma unroll
    for (int b = 0; b < BB; b++) red[b][tid] = acc[b];
    __syncthreads();
    if (half == 0) {
#pragma unroll
        for (int b = 0; b < BB; b++) {
            float v = red[b][tid] + red[b][tid + 128] + g_q[(size_t)(b * 16 + t) * SS + col];
            g_states[(size_t)(b * 16 + t + 1) * SS + col] = v;
        }
    }
}

// ---------------- host ----------------
extern "C" void kernel_launch(void* const* d_in, const int* in_sizes, int n_in,
                              void* d_out, int out_size) {
    const float* x     = (const float*)d_in[0];
    const float* pos   = (const float*)d_in[1];
    const float* W_in  = (const float*)d_in[2];
    const float* b_in  = (const float*)d_in[3];
    const float* W_out = (const float*)d_in[4];
    const float* b_out = (const float*)d_in[5];
    const float* Amat  = (const float*)d_in[6];
    const float* Bm    = (const float*)d_in[7];
    const float* init  = (const float*)d_in[8];
    float* out = (float*)d_out;

    float *Wot, *WinT, *H, *G, *Mw, *xbar, *m, *q, *states, *r;
    cudaGetSymbolAddress((void**)&Wot,    g_Wot);
    cudaGetSymbolAddress((void**)&WinT,   g_WinT);
    cudaGetSymbolAddress((void**)&H,      g_H);
    cudaGetSymbolAddress((void**)&G,      g_G);
    cudaGetSymbolAddress((void**)&Mw,     g_Mw);
    cudaGetSymbolAddress((void**)&xbar,   g_xbar);
    cudaGetSymbolAddress((void**)&m,      g_m);
    cudaGetSymbolAddress((void**)&q,      g_q);
    cudaGetSymbolAddress((void**)&states, g_states);
    cudaGetSymbolAddress((void**)&r,      g_r);

    cudaFuncSetAttribute(tf32_gemm<false, false, true>,
                         cudaFuncAttributeMaxDynamicSharedMemorySize, GEMM_SMEM);
    cudaFuncSetAttribute(tf32_gemm<false, false, false>,
                         cudaFuncAttributeMaxDynamicSharedMemorySize, GEMM_SMEM);
    cudaFuncSetAttribute(tf32_gemm<true, true, false>,
                         cudaFuncAttributeMaxDynamicSharedMemorySize, GEMM_SMEM);

    // transposed weights: Wot = rna(W_out^T) (tf32 B operand), WinT fp32
    transpose_k<true ><<<dim3(32, 32), dim3(32, 8)>>>(W_out, Wot);
    transpose_k<false><<<dim3(32, 32), dim3(32, 8)>>>(W_in,  WinT);

    // fused weights on tensor cores: H = rna(Bm@Wot), G = rna(A@Wot) batched; Mw = rna(WinT@H)
    tf32_gemm<false, false, true><<<dim3(8, 8, 2), 256, GEMM_SMEM>>>(
        Bm, Amat, nullptr, Wot, H, G);
    tf32_gemm<false, false, false><<<dim3(8, 8), 256, GEMM_SMEM>>>(
        WinT, nullptr, nullptr, H, Mw, nullptr);

    // constant vector
    cvec_k<<<4, 256>>>(b_in, b_out);

    // xbar = mean_p(x + pos)
    xbar_k<<<dim3(4, 128), 256>>>(x, pos);

    // m = xbar@WinT + b_in ; q = m@Bm   (exact fp32 path)
    sgemm_nn<32, 64, 32, 2, 4, true ><<<dim3(16, 4), 256>>>(128, 1024, 1024, xbar, WinT, m, b_in);
    sgemm_nn<32, 64, 32, 2, 4, false><<<dim3(16, 4), 256>>>(128, 1024, 1024, m,    Bm,   q, nullptr);

    // scan
    scan_init_k<<<4, 256>>>(init);
    for (int t = 0; t < 15; t++) scan_step_k<<<8, 256>>>(Amat, t);

    // r = states@G
    sgemm_nn<32, 64, 32, 2, 4, false><<<dim3(16, 4), 256>>>(128, 1024, 1024, states, G, r, nullptr);

    // main GEMM on tensor cores: out = rna(x+pos) @ Mw + r + c
    tf32_gemm<true, true, false><<<dim3(8, 256), 256, GEMM_SMEM>>>(
        x, nullptr, pos, Mw, out, nullptr);
}

// round 4
// speedup vs baseline: 2.0405x; 1.1998x over previous
#include <cuda_runtime.h>
#include <cstdint>

#define DD   1024
#define SS   1024
#define TT   16
#define PP   256
#define BB   8
#define BT   128
#define MROWS 32768

// ---------------- device scratch ----------------
__device__ float g_Wot [SS*DD];   // rna(W_out^T)
__device__ float g_WinT[DD*SS];   // W_in^T (fp32, for exact small path)
__device__ float g_WinTR[DD*SS];  // rna(W_in^T)
__device__ float g_BmR [SS*SS];   // rna(Bm)
__device__ float g_AR  [SS*SS];   // rna(A)
__device__ float g_H   [SS*DD];   // rna(Bm @ Wot)
__device__ float g_G   [SS*DD];   // rna(A  @ Wot)
__device__ float g_Mw  [DD*DD];   // rna(WinT @ H)
__device__ float g_Xsum[(size_t)MROWS*DD]; // rna(x + pos)
__device__ float g_xbar[BT*DD];
__device__ float g_m   [BT*SS];
__device__ float g_q   [BT*SS];
__device__ float g_states[BT*SS];
__device__ float g_r   [BT*DD];
__device__ float g_c   [DD];

// ---------------- helpers ----------------
__device__ __forceinline__ float f_rna(float v) {
    uint32_t u;
    asm("cvt.rna.tf32.f32 %0, %1;" : "=r"(u) : "f"(v));
    return __uint_as_float(u);
}
__device__ __forceinline__ void cp_async16(void* dst_smem, const void* src) {
    uint32_t d;
    asm("{ .reg .u64 t; cvta.to.shared.u64 t, %1; cvt.u32.u64 %0, t; }" : "=r"(d) : "l"(dst_smem));
    asm volatile("cp.async.cg.shared.global [%0], [%1], 16;" :: "r"(d), "l"(src) : "memory");
}
#define CP_COMMIT() asm volatile("cp.async.commit_group;" ::: "memory")
#define CP_WAIT0()  asm volatile("cp.async.wait_group 0;" ::: "memory")
#define CP_WAIT1()  asm volatile("cp.async.wait_group 1;" ::: "memory")

__device__ __forceinline__ void mma_tf32(float* d, const uint32_t* a, const uint32_t* b) {
    asm volatile(
        "mma.sync.aligned.m16n8k8.row.col.f32.tf32.tf32.f32 "
        "{%0,%1,%2,%3}, {%4,%5,%6,%7}, {%8,%9}, {%0,%1,%2,%3};"
        : "+f"(d[0]), "+f"(d[1]), "+f"(d[2]), "+f"(d[3])
        : "r"(a[0]), "r"(a[1]), "r"(a[2]), "r"(a[3]), "r"(b[0]), "r"(b[1]));
}

// ================= tf32 tensor-core GEMM (all operands pre-rounded) =================
// CTA tile 128x128, K chunk 32, 3-stage cp.async pipeline, 256 threads = 8 warps,
// warp tile 64x32, mma m16n8k8. 2 CTAs per SM.
#define AS_STRIDE 36
#define BS_STRIDE 136
#define A_STAGE (128*AS_STRIDE)   // floats
#define B_STAGE (32*BS_STRIDE)
#define NSTAGE 3
#define GEMM_SMEM (NSTAGE * (A_STAGE + B_STAGE) * 4)

template <bool EPI_RC, bool DUAL>
__global__ void __launch_bounds__(256, 2) tf32_gemm(
    const float* __restrict__ Aop, const float* __restrict__ Aop2,
    const float* __restrict__ Bop,
    float* __restrict__ Cop, float* __restrict__ Cop2)
{
    extern __shared__ float smem[];

    const int tid  = threadIdx.x;
    const int lane = tid & 31;
    const int w    = tid >> 5;
    const int wm   = (w >> 2) * 64;
    const int wn   = (w & 3) * 32;
    const int g    = lane >> 2;
    const int tg   = lane & 3;

    const int rowBase = blockIdx.y * 128;
    const int colBase = blockIdx.x * 128;
    const float* __restrict__ Asel = (DUAL && blockIdx.z) ? Aop2 : Aop;
    float* __restrict__ Csel       = (DUAL && blockIdx.z) ? Cop2 : Cop;
    const float* __restrict__ Ag = Asel + (size_t)rowBase * 1024;
    const float* __restrict__ Bg = Bop + colBase;

    float acc[4][4][4];
#pragma unroll
    for (int i = 0; i < 4; i++)
#pragma unroll
        for (int j = 0; j < 4; j++)
#pragma unroll
            for (int k = 0; k < 4; k++) acc[i][j][k] = 0.f;

    // thread's fixed load coords
    const int ar = tid >> 3, ac4 = tid & 7;         // A: 2 rows per thread-iter step 32
    const int bkr = tid >> 5, bn4 = tid & 31;       // B: 32 rows x 32 float4

    auto load_stage = [&](int chunk, int st) {
        float* dA = smem + st * (A_STAGE + B_STAGE);
        float* dB = dA + A_STAGE;
        const int k0 = chunk * 32;
#pragma unroll
        for (int i = 0; i < 4; i++) {
            int r = ar + i * 32;
            cp_async16(dA + r * AS_STRIDE + ac4 * 4,
                       Ag + (size_t)r * 1024 + k0 + ac4 * 4);
        }
#pragma unroll
        for (int i = 0; i < 4; i++) {
            int kr = bkr + i * 8;
            cp_async16(dB + kr * BS_STRIDE + bn4 * 4,
                       Bg + (size_t)(k0 + kr) * 1024 + bn4 * 4);
        }
        CP_COMMIT();
    };

    auto compute = [&](int st) {
        const float* Ab = smem + st * (A_STAGE + B_STAGE);
        const float* Bb = Ab + A_STAGE;
#pragma unroll
        for (int kk = 0; kk < 4; kk++) {
            const int k = kk * 8;
            uint32_t a[4][4], b[4][2];
#pragma unroll
            for (int mi = 0; mi < 4; mi++) {
                const float* p0 = Ab + (wm + mi * 16 + g) * AS_STRIDE + k + tg;
                const float* p1 = p0 + 8 * AS_STRIDE;
                a[mi][0] = __float_as_uint(p0[0]);
                a[mi][1] = __float_as_uint(p1[0]);
                a[mi][2] = __float_as_uint(p0[4]);
                a[mi][3] = __float_as_uint(p1[4]);
            }
#pragma unroll
            for (int ni = 0; ni < 4; ni++) {
                const float* q0 = Bb + (k + tg) * BS_STRIDE + wn + ni * 8 + g;
                b[ni][0] = __float_as_uint(q0[0]);
                b[ni][1] = __float_as_uint(q0[4 * BS_STRIDE]);
            }
#pragma unroll
            for (int mi = 0; mi < 4; mi++)
#pragma unroll
                for (int ni = 0; ni < 4; ni++) mma_tf32(acc[mi][ni], a[mi], b[ni]);
        }
    };

    // prologue: stages 0,1 in flight
    load_stage(0, 0);
    load_stage(1, 1);

    int st = 0;
#pragma unroll 1
    for (int c = 0; c < 32; c++) {
        if (c < 31) CP_WAIT1(); else CP_WAIT0();
        __syncthreads();
        if (c + 2 < 32) {
            int nst = st + 2; if (nst >= NSTAGE) nst -= NSTAGE;
            load_stage(c + 2, nst);
        }
        compute(st);
        if (++st == NSTAGE) st = 0;
    }

    // ---- epilogue ----
#pragma unroll
    for (int mi = 0; mi < 4; mi++) {
        const int row0 = rowBase + wm + mi * 16 + g;
        const int row1 = row0 + 8;
#pragma unroll
        for (int ni = 0; ni < 4; ni++) {
            const int col = colBase + wn + ni * 8 + tg * 2;
            float v0 = acc[mi][ni][0], v1 = acc[mi][ni][1];
            float v2 = acc[mi][ni][2], v3 = acc[mi][ni][3];
            if (EPI_RC) {
                const float* r0 = g_r + (size_t)(row0 >> 8) * 1024 + col;
                const float* r1 = g_r + (size_t)(row1 >> 8) * 1024 + col;
                float2 ra = *(const float2*)r0;
                float2 rb = *(const float2*)r1;
                float2 cc = *(const float2*)(g_c + col);
                v0 += ra.x + cc.x; v1 += ra.y + cc.y;
                v2 += rb.x + cc.x; v3 += rb.y + cc.y;
            } else {
                v0 = f_rna(v0); v1 = f_rna(v1); v2 = f_rna(v2); v3 = f_rna(v3);
            }
            *(float2*)(Csel + (size_t)row0 * 1024 + col) = make_float2(v0, v1);
            *(float2*)(Csel + (size_t)row1 * 1024 + col) = make_float2(v2, v3);
        }
    }
}

// ---------------- prepass: Xsum = rna(x + pos) ----------------
__global__ void prepass_k(const float* __restrict__ x, const float* __restrict__ pos) {
    size_t i = ((size_t)blockIdx.x * 256 + threadIdx.x) * 4;
    float4 vx = *(const float4*)(x + i);
    float4 vp = *(const float4*)(pos + (i & ((size_t)4194304 - 1)));
    float4 o;
    o.x = f_rna(vx.x + vp.x); o.y = f_rna(vx.y + vp.y);
    o.z = f_rna(vx.z + vp.z); o.w = f_rna(vx.w + vp.w);
    *(float4*)(g_Xsum + i) = o;
}

// ---------------- elementwise rna copy (1M floats) ----------------
__global__ void rna_copy_k(const float* __restrict__ in, float* __restrict__ out) {
    int i = (blockIdx.x * 256 + threadIdx.x) * 4;
    float4 v = *(const float4*)(in + i);
    v.x = f_rna(v.x); v.y = f_rna(v.y); v.z = f_rna(v.z); v.w = f_rna(v.w);
    *(float4*)(out + i) = v;
}

// ---------------- transpose 1024x1024 (optionally rna) ----------------
template <bool RNA>
__global__ void transpose_k(const float* __restrict__ in, float* __restrict__ out) {
    __shared__ float tile[32][33];
    int x = blockIdx.x * 32 + threadIdx.x;
    int y = blockIdx.y * 32 + threadIdx.y;
#pragma unroll
    for (int i = 0; i < 32; i += 8)
        tile[threadIdx.y + i][threadIdx.x] = in[(size_t)(y + i) * DD + x];
    __syncthreads();
    x = blockIdx.y * 32 + threadIdx.x;
    y = blockIdx.x * 32 + threadIdx.y;
#pragma unroll
    for (int i = 0; i < 32; i += 8) {
        float v = tile[threadIdx.x][threadIdx.y + i];
        out[(size_t)(y + i) * DD + x] = RNA ? f_rna(v) : v;
    }
}

// ---------------- fp32 SGEMM for small matrices ----------------
template <int BM, int BN, int BK, int TM, int TN, bool BIAS>
__global__ void __launch_bounds__((BM / TM) * (BN / TN))
sgemm_nn(int M, int N, int K,
         const float* __restrict__ A, const float* __restrict__ B,
         float* __restrict__ C, const float* __restrict__ bias) {
    constexpr int THREADS = (BM / TM) * (BN / TN);
    __shared__ float As[BK][BM];
    __shared__ float Bs[BK][BN];
    const int tid = threadIdx.x;
    const int tx = tid % (BN / TN);
    const int ty = tid / (BN / TN);
    const float* Ag = A + (size_t)blockIdx.y * BM * K;
    const float* Bg = B + (size_t)blockIdx.x * BN;
    float acc[TM][TN] = {};
    constexpr int AIT = (BM * BK) / (THREADS * 4);
    constexpr int BIT = (BK * BN) / (THREADS * 4);
    static_assert(AIT >= 1 && BIT >= 1, "tile/thread mismatch");

    for (int k0 = 0; k0 < K; k0 += BK) {
#pragma unroll
        for (int it = 0; it < AIT; it++) {
            int i = tid * 4 + it * THREADS * 4;
            int r = i / BK, c = i % BK;
            float4 v = *(const float4*)(Ag + (size_t)r * K + k0 + c);
            As[c + 0][r] = v.x; As[c + 1][r] = v.y;
            As[c + 2][r] = v.z; As[c + 3][r] = v.w;
        }
#pragma unroll
        for (int it = 0; it < BIT; it++) {
            int i = tid * 4 + it * THREADS * 4;
            int r = i / BN, c = i % BN;
            *(float4*)(&Bs[r][c]) = *(const float4*)(Bg + (size_t)(k0 + r) * N + c);
        }
        __syncthreads();
#pragma unroll
        for (int k = 0; k < BK; k++) {
            float a[TM], bv[TN];
#pragma unroll
            for (int i = 0; i < TM; i++) a[i] = As[k][ty * TM + i];
#pragma unroll
            for (int j = 0; j < TN; j++) bv[j] = Bs[k][tx * TN + j];
#pragma unroll
            for (int i = 0; i < TM; i++)
#pragma unroll
                for (int j = 0; j < TN; j++) acc[i][j] += a[i] * bv[j];
        }
        __syncthreads();
    }
#pragma unroll
    for (int i = 0; i < TM; i++) {
        int row = blockIdx.y * BM + ty * TM + i;
#pragma unroll
        for (int j = 0; j < TN; j++) {
            int cn = blockIdx.x * BN + tx * TN + j;
            float v = acc[i][j];
            if (BIAS) v += bias[cn];
            C[(size_t)row * N + cn] = v;
        }
    }
}

// ---------------- c[d] = b_in @ H + b_out ----------------
__global__ void cvec_k(const float* __restrict__ b_in, const float* __restrict__ b_out) {
    int d = blockIdx.x * 256 + threadIdx.x;
    float s = b_out[d];
    for (int j = 0; j < SS; j++) s += b_in[j] * g_H[(size_t)j * DD + d];
    g_c[d] = s;
}

// ---------------- xbar[bt,d] = mean_p (x + pos) ----------------
__global__ void xbar_k(const float* __restrict__ x, const float* __restrict__ pos) {
    int d  = blockIdx.x * 256 + threadIdx.x;
    int bt = blockIdx.y;
    int t  = bt & 15;
    const float* xp = x   + (size_t)bt * PP * DD + d;
    const float* pp = pos + (size_t)t  * PP * DD + d;
    float s = 0.f;
#pragma unroll 4
    for (int p = 0; p < PP; p++) s += xp[(size_t)p * DD] + pp[(size_t)p * DD];
    g_xbar[(size_t)bt * DD + d] = s * (1.0f / PP);
}

// ---------------- scan ----------------
__global__ void scan_init_k(const float* __restrict__ init) {
    int s = blockIdx.x * 256 + threadIdx.x;
    float v = init[s];
#pragma unroll
    for (int b = 0; b < BB; b++) g_states[(size_t)(b * 16) * SS + s] = v;
}

__global__ void __launch_bounds__(256) scan_step_k(const float* __restrict__ Amat, int t) {
    __shared__ float st[BB][SS];
    __shared__ float red[BB][256];
    int tid = threadIdx.x;
    for (int i = tid; i < BB * SS; i += 256) {
        int b = i >> 10, s = i & 1023;
        st[b][s] = g_states[(size_t)(b * 16 + t) * SS + s];
    }
    __syncthreads();
    int col  = blockIdx.x * 128 + (tid & 127);
    int half = tid >> 7;
    float acc[BB] = {};
    int k0 = half * 512;
#pragma unroll 4
    for (int k = k0; k < k0 + 512; k++) {
        float av = Amat[(size_t)k * SS + col];
#pragma unroll
        for (int b = 0; b < BB; b++) acc[b] += st[b][k] * av;
    }
#pragma unroll
    for (int b = 0; b < BB; b++) red[b][tid] = acc[b];
    __syncthreads();
    if (half == 0) {
#pragma unroll
        for (int b = 0; b < BB; b++) {
            float v = red[b][tid] + red[b][tid + 128] + g_q[(size_t)(b * 16 + t) * SS + col];
            g_states[(size_t)(b * 16 + t + 1) * SS + col] = v;
        }
    }
}

// ---------------- host ----------------
extern "C" void kernel_launch(void* const* d_in, const int* in_sizes, int n_in,
                              void* d_out, int out_size) {
    const float* x     = (const float*)d_in[0];
    const float* pos   = (const float*)d_in[1];
    const float* W_in  = (const float*)d_in[2];
    const float* b_in  = (const float*)d_in[3];
    const float* W_out = (const float*)d_in[4];
    const float* b_out = (const float*)d_in[5];
    const float* Amat  = (const float*)d_in[6];
    const float* Bm    = (const float*)d_in[7];
    const float* init  = (const float*)d_in[8];
    float* out = (float*)d_out;

    float *Wot, *WinT, *WinTR, *BmR, *AR, *H, *G, *Mw, *xbar, *m, *q, *states, *r, *Xsum;
    cudaGetSymbolAddress((void**)&Wot,    g_Wot);
    cudaGetSymbolAddress((void**)&WinT,   g_WinT);
    cudaGetSymbolAddress((void**)&WinTR,  g_WinTR);
    cudaGetSymbolAddress((void**)&BmR,    g_BmR);
    cudaGetSymbolAddress((void**)&AR,     g_AR);
    cudaGetSymbolAddress((void**)&H,      g_H);
    cudaGetSymbolAddress((void**)&G,      g_G);
    cudaGetSymbolAddress((void**)&Mw,     g_Mw);
    cudaGetSymbolAddress((void**)&xbar,   g_xbar);
    cudaGetSymbolAddress((void**)&m,      g_m);
    cudaGetSymbolAddress((void**)&q,      g_q);
    cudaGetSymbolAddress((void**)&states, g_states);
    cudaGetSymbolAddress((void**)&r,      g_r);
    cudaGetSymbolAddress((void**)&Xsum,   g_Xsum);

    cudaFuncSetAttribute(tf32_gemm<false, true>,
                         cudaFuncAttributeMaxDynamicSharedMemorySize, GEMM_SMEM);
    cudaFuncSetAttribute(tf32_gemm<false, false>,
                         cudaFuncAttributeMaxDynamicSharedMemorySize, GEMM_SMEM);
    cudaFuncSetAttribute(tf32_gemm<true, false>,
                         cudaFuncAttributeMaxDynamicSharedMemorySize, GEMM_SMEM);

    // prepass: Xsum = rna(x + pos)
    prepass_k<<<32768, 256>>>(x, pos);

    // transposed weights
    transpose_k<true ><<<dim3(32, 32), dim3(32, 8)>>>(W_out, Wot);
    transpose_k<false><<<dim3(32, 32), dim3(32, 8)>>>(W_in,  WinT);

    // rna copies for tf32 A operands
    rna_copy_k<<<1024, 256>>>(Bm,   BmR);
    rna_copy_k<<<1024, 256>>>(Amat, AR);
    rna_copy_k<<<1024, 256>>>(WinT, WinTR);

    // fused weights: H = rna(BmR@Wot), G = rna(AR@Wot) batched; Mw = rna(WinTR@H)
    tf32_gemm<false, true><<<dim3(8, 8, 2), 256, GEMM_SMEM>>>(BmR, AR, Wot, H, G);
    tf32_gemm<false, false><<<dim3(8, 8), 256, GEMM_SMEM>>>(WinTR, nullptr, H, Mw, nullptr);

    // constant vector
    cvec_k<<<4, 256>>>(b_in, b_out);

    // xbar = mean_p(x + pos)
    xbar_k<<<dim3(4, 128), 256>>>(x, pos);

    // m = xbar@WinT + b_in ; q = m@Bm   (exact fp32 path)
    sgemm_nn<32, 64, 32, 2, 4, true ><<<dim3(16, 4), 256>>>(128, 1024, 1024, xbar, WinT, m, b_in);
    sgemm_nn<32, 64, 32, 2, 4, false><<<dim3(16, 4), 256>>>(128, 1024, 1024, m,    Bm,   q, nullptr);

    // scan
    scan_init_k<<<4, 256>>>(init);
    for (int t = 0; t < 15; t++) scan_step_k<<<8, 256>>>(Amat, t);

    // r = states@G
    sgemm_nn<32, 64, 32, 2, 4, false><<<dim3(16, 4), 256>>>(128, 1024, 1024, states, G, r, nullptr);

    // main GEMM: out = Xsum @ Mw + r + c
    tf32_gemm<true, false><<<dim3(8, 256), 256, GEMM_SMEM>>>(Xsum, nullptr, Mw, out, nullptr);
}

// round 5
// speedup vs baseline: 2.0823x; 1.0205x over previous
#include <cuda_runtime.h>
#include <cstdint>

#define DD   1024
#define SS   1024
#define TT   16
#define PP   256
#define BB   8
#define BT   128
#define MROWS 32768

// ---------------- device scratch ----------------
__device__ float g_WoutR[DD*SS];  // rna(W_out)
__device__ float g_WinT [DD*SS];  // W_in^T (fp32 exact)
__device__ float g_WinTR[DD*SS];  // rna(W_in^T)
__device__ float g_BmR [SS*SS];   // rna(Bm)
__device__ float g_AR  [SS*SS];   // rna(A)
__device__ float g_Ht  [DD*SS];   // rna(H^T) = rna(W_out @ Bm^T)
__device__ float g_Gt  [DD*SS];   // rna(G^T) = rna(W_out @ A^T)
__device__ float g_G   [SS*DD];   // transpose(Gt)
__device__ float g_MwT [DD*DD];   // rna(Mw^T) = rna(Ht @ WinT^T)
__device__ float g_Xsum[(size_t)MROWS*DD]; // rna(x + pos)
__device__ float g_xbar[BT*DD];
__device__ float g_m   [BT*SS];
__device__ float g_q   [BT*SS];
__device__ float g_states[BT*SS];
__device__ float g_r   [BT*DD];
__device__ float g_c   [DD];

// ---------------- helpers ----------------
__device__ __forceinline__ float f_rna(float v) {
    uint32_t u;
    asm("cvt.rna.tf32.f32 %0, %1;" : "=r"(u) : "f"(v));
    return __uint_as_float(u);
}
__device__ __forceinline__ uint32_t smem_u32(const void* p) {
    uint32_t a;
    asm("{ .reg .u64 t; cvta.to.shared.u64 t, %1; cvt.u32.u64 %0, t; }" : "=r"(a) : "l"(p));
    return a;
}
__device__ __forceinline__ void cp_async16(uint32_t dst, const void* src) {
    asm volatile("cp.async.cg.shared.global [%0], [%1], 16;" :: "r"(dst), "l"(src) : "memory");
}
#define CP_COMMIT() asm volatile("cp.async.commit_group;" ::: "memory")
#define CP_WAIT0()  asm volatile("cp.async.wait_group 0;" ::: "memory")
#define CP_WAIT1()  asm volatile("cp.async.wait_group 1;" ::: "memory")

__device__ __forceinline__ void ldsm_x4(uint32_t* r, uint32_t addr) {
    asm volatile("ldmatrix.sync.aligned.m8n8.x4.shared.b16 {%0,%1,%2,%3}, [%4];"
        : "=r"(r[0]), "=r"(r[1]), "=r"(r[2]), "=r"(r[3]) : "r"(addr));
}
__device__ __forceinline__ void mma_tf32(float* d, const uint32_t* a, const uint32_t* b) {
    asm volatile(
        "mma.sync.aligned.m16n8k8.row.col.f32.tf32.tf32.f32 "
        "{%0,%1,%2,%3}, {%4,%5,%6,%7}, {%8,%9}, {%0,%1,%2,%3};"
        : "+f"(d[0]), "+f"(d[1]), "+f"(d[2]), "+f"(d[3])
        : "r"(a[0]), "r"(a[1]), "r"(a[2]), "r"(a[3]), "r"(b[0]), "r"(b[1]));
}

// ================= tf32 NT GEMM: C[M,N] = A[M,K] @ Bt[N,K]^T =================
// All operands pre-rounded to tf32. CTA tile 128x128, K chunk 32, 3-stage cp.async,
// 256 threads = 8 warps (2m x 4n), warp tile 64x32. ldmatrix fragment loads.
#define ROW_STRIDE 36                   // floats per smem row (32 + 4 pad) = 144B
#define OP_STAGE_F (128*ROW_STRIDE)     // floats per operand per stage
#define STAGE_F    (2*OP_STAGE_F)
#define NSTAGE     3
#define GEMM_SMEM  (NSTAGE * STAGE_F * 4)

template <bool EPI_RC, bool DUAL>
__global__ void __launch_bounds__(256, 2) tf32_gemm_nt(
    const float* __restrict__ Aop,
    const float* __restrict__ Bop, const float* __restrict__ Bop2,
    float* __restrict__ Cop, float* __restrict__ Cop2)
{
    extern __shared__ float smem[];
    const uint32_t sb = smem_u32(smem);

    const int tid  = threadIdx.x;
    const int lane = tid & 31;
    const int w    = tid >> 5;
    const int wm   = (w >> 2) * 64;
    const int wn   = (w & 3) * 32;
    const int g    = lane >> 2;
    const int tg   = lane & 3;

    const int rowBase = blockIdx.y * 128;
    const int colBase = blockIdx.x * 128;
    const float* __restrict__ Bsel = (DUAL && blockIdx.z) ? Bop2 : Bop;
    float* __restrict__ Csel       = (DUAL && blockIdx.z) ? Cop2 : Cop;
    const float* __restrict__ Ag = Aop  + (size_t)rowBase * 1024;
    const float* __restrict__ Bg = Bsel + (size_t)colBase * 1024;

    float acc[4][4][4];
#pragma unroll
    for (int i = 0; i < 4; i++)
#pragma unroll
        for (int j = 0; j < 4; j++)
#pragma unroll
            for (int k = 0; k < 4; k++) acc[i][j][k] = 0.f;

    // loader coords: 128 rows x 8 float4 per operand, 256 threads x 4 iters
    const int lr = tid >> 3, lc4 = tid & 7;

    auto load_stage = [&](int chunk, int st) {
        const uint32_t dA = sb + st * STAGE_F * 4;
        const uint32_t dB = dA + OP_STAGE_F * 4;
        const int k0 = chunk * 32;
#pragma unroll
        for (int i = 0; i < 4; i++) {
            int r = lr + i * 32;
            cp_async16(dA + r * 144 + lc4 * 16, Ag + (size_t)r * 1024 + k0 + lc4 * 4);
        }
#pragma unroll
        for (int i = 0; i < 4; i++) {
            int r = lr + i * 32;
            cp_async16(dB + r * 144 + lc4 * 16, Bg + (size_t)r * 1024 + k0 + lc4 * 4);
        }
        CP_COMMIT();
    };

    // ldmatrix per-lane byte offsets (within operand region)
    // A x4: rows wm + mi*16 + (lane&15), col (lane>>4)*4 (+k)
    const uint32_t aoff = (uint32_t)((wm + (lane & 15)) * 144 + ((lane >> 4) << 4));
    // B x4: rows wn + ((lane>>4)<<3) + (lane&7), col ((lane>>3)&1)*4 (+k)
    const uint32_t boff = (uint32_t)((wn + ((lane >> 4) << 3) + (lane & 7)) * 144 +
                                     (((lane >> 3) & 1) << 4));

    auto compute = [&](int st) {
        const uint32_t ab = sb + st * STAGE_F * 4 + aoff;
        const uint32_t bb = sb + st * STAGE_F * 4 + OP_STAGE_F * 4 + boff;
#pragma unroll
        for (int kk = 0; kk < 4; kk++) {
            const uint32_t kb = kk * 32;
            uint32_t a[4][4], bfr[2][4];
#pragma unroll
            for (int mi = 0; mi < 4; mi++) ldsm_x4(a[mi], ab + mi * 2304 + kb);
            ldsm_x4(bfr[0], bb + kb);
            ldsm_x4(bfr[1], bb + 2304 + kb);
#pragma unroll
            for (int mi = 0; mi < 4; mi++)
#pragma unroll
                for (int ni = 0; ni < 4; ni++)
                    mma_tf32(acc[mi][ni], a[mi], &bfr[ni >> 1][(ni & 1) * 2]);
        }
    };

    load_stage(0, 0);
    load_stage(1, 1);

    int st = 0;
#pragma unroll 1
    for (int c = 0; c < 32; c++) {
        if (c < 31) CP_WAIT1(); else CP_WAIT0();
        __syncthreads();
        if (c + 2 < 32) {
            int nst = st + 2; if (nst >= NSTAGE) nst -= NSTAGE;
            load_stage(c + 2, nst);
        }
        compute(st);
        if (++st == NSTAGE) st = 0;
    }

    // ---- epilogue ----
#pragma unroll
    for (int mi = 0; mi < 4; mi++) {
        const int row0 = rowBase + wm + mi * 16 + g;
        const int row1 = row0 + 8;
#pragma unroll
        for (int ni = 0; ni < 4; ni++) {
            const int col = colBase + wn + ni * 8 + tg * 2;
            float v0 = acc[mi][ni][0], v1 = acc[mi][ni][1];
            float v2 = acc[mi][ni][2], v3 = acc[mi][ni][3];
            if (EPI_RC) {
                const float* r0 = g_r + (size_t)(row0 >> 8) * 1024 + col;
                const float* r1 = g_r + (size_t)(row1 >> 8) * 1024 + col;
                float2 ra = *(const float2*)r0;
                float2 rb = *(const float2*)r1;
                float2 cc = *(const float2*)(g_c + col);
                v0 += ra.x + cc.x; v1 += ra.y + cc.y;
                v2 += rb.x + cc.x; v3 += rb.y + cc.y;
            } else {
                v0 = f_rna(v0); v1 = f_rna(v1); v2 = f_rna(v2); v3 = f_rna(v3);
            }
            *(float2*)(Csel + (size_t)row0 * 1024 + col) = make_float2(v0, v1);
            *(float2*)(Csel + (size_t)row1 * 1024 + col) = make_float2(v2, v3);
        }
    }
}

// ---------------- prepass: Xsum = rna(x + pos) ----------------
__global__ void prepass_k(const float* __restrict__ x, const float* __restrict__ pos) {
    size_t i = ((size_t)blockIdx.x * 256 + threadIdx.x) * 4;
    float4 vx = *(const float4*)(x + i);
    float4 vp = *(const float4*)(pos + (i & ((size_t)4194304 - 1)));
    float4 o;
    o.x = f_rna(vx.x + vp.x); o.y = f_rna(vx.y + vp.y);
    o.z = f_rna(vx.z + vp.z); o.w = f_rna(vx.w + vp.w);
    *(float4*)(g_Xsum + i) = o;
}

// ---------------- elementwise rna copy (1M floats) ----------------
__global__ void rna_copy_k(const float* __restrict__ in, float* __restrict__ out) {
    int i = (blockIdx.x * 256 + threadIdx.x) * 4;
    float4 v = *(const float4*)(in + i);
    v.x = f_rna(v.x); v.y = f_rna(v.y); v.z = f_rna(v.z); v.w = f_rna(v.w);
    *(float4*)(out + i) = v;
}

// ---------------- transpose 1024x1024 ----------------
__global__ void transpose_k(const float* __restrict__ in, float* __restrict__ out) {
    __shared__ float tile[32][33];
    int x = blockIdx.x * 32 + threadIdx.x;
    int y = blockIdx.y * 32 + threadIdx.y;
#pragma unroll
    for (int i = 0; i < 32; i += 8)
        tile[threadIdx.y + i][threadIdx.x] = in[(size_t)(y + i) * DD + x];
    __syncthreads();
    x = blockIdx.y * 32 + threadIdx.x;
    y = blockIdx.x * 32 + threadIdx.y;
#pragma unroll
    for (int i = 0; i < 32; i += 8)
        out[(size_t)(y + i) * DD + x] = tile[threadIdx.x][threadIdx.y + i];
}

// ---------------- fp32 SGEMM (NN) for small matrices ----------------
template <int BM, int BN, int BK, int TM, int TN, bool BIAS>
__global__ void __launch_bounds__((BM / TM) * (BN / TN))
sgemm_nn(int M, int N, int K,
         const float* __restrict__ A, const float* __restrict__ B,
         float* __restrict__ C, const float* __restrict__ bias) {
    constexpr int THREADS = (BM / TM) * (BN / TN);
    __shared__ float As[BK][BM];
    __shared__ float Bs[BK][BN];
    const int tid = threadIdx.x;
    const int tx = tid % (BN / TN);
    const int ty = tid / (BN / TN);
    const float* Ag = A + (size_t)blockIdx.y * BM * K;
    const float* Bg = B + (size_t)blockIdx.x * BN;
    float acc[TM][TN] = {};
    constexpr int AIT = (BM * BK) / (THREADS * 4);
    constexpr int BIT = (BK * BN) / (THREADS * 4);
    static_assert(AIT >= 1 && BIT >= 1, "tile/thread mismatch");

    for (int k0 = 0; k0 < K; k0 += BK) {
#pragma unroll
        for (int it = 0; it < AIT; it++) {
            int i = tid * 4 + it * THREADS * 4;
            int r = i / BK, c = i % BK;
            float4 v = *(const float4*)(Ag + (size_t)r * K + k0 + c);
            As[c + 0][r] = v.x; As[c + 1][r] = v.y;
            As[c + 2][r] = v.z; As[c + 3][r] = v.w;
        }
#pragma unroll
        for (int it = 0; it < BIT; it++) {
            int i = tid * 4 + it * THREADS * 4;
            int r = i / BN, c = i % BN;
            *(float4*)(&Bs[r][c]) = *(const float4*)(Bg + (size_t)(k0 + r) * N + c);
        }
        __syncthreads();
#pragma unroll
        for (int k = 0; k < BK; k++) {
            float a[TM], bv[TN];
#pragma unroll
            for (int i = 0; i < TM; i++) a[i] = As[k][ty * TM + i];
#pragma unroll
            for (int j = 0; j < TN; j++) bv[j] = Bs[k][tx * TN + j];
#pragma unroll
            for (int i = 0; i < TM; i++)
#pragma unroll
                for (int j = 0; j < TN; j++) acc[i][j] += a[i] * bv[j];
        }
        __syncthreads();
    }
#pragma unroll
    for (int i = 0; i < TM; i++) {
        int row = blockIdx.y * BM + ty * TM + i;
#pragma unroll
        for (int j = 0; j < TN; j++) {
            int cn = blockIdx.x * BN + tx * TN + j;
            float v = acc[i][j];
            if (BIAS) v += bias[cn];
            C[(size_t)row * N + cn] = v;
        }
    }
}

// ---------------- c[d] = b_in @ H + b_out  (via Ht rows, coalesced) ----------------
__global__ void cvec_k(const float* __restrict__ b_in, const float* __restrict__ b_out) {
    __shared__ float red[256];
    const int d = blockIdx.x;
    const int tid = threadIdx.x;
    const float* row = g_Ht + (size_t)d * 1024;
    float s = 0.f;
    for (int j = tid; j < SS; j += 256) s += row[j] * b_in[j];
    red[tid] = s;
    __syncthreads();
    for (int o = 128; o > 0; o >>= 1) {
        if (tid < o) red[tid] += red[tid + o];
        __syncthreads();
    }
    if (tid == 0) g_c[d] = red[0] + b_out[d];
}

// ---------------- xbar[bt,d] = mean_p (x + pos) ----------------
__global__ void xbar_k(const float* __restrict__ x, const float* __restrict__ pos) {
    int d  = blockIdx.x * 256 + threadIdx.x;
    int bt = blockIdx.y;
    int t  = bt & 15;
    const float* xp = x   + (size_t)bt * PP * DD + d;
    const float* pp = pos + (size_t)t  * PP * DD + d;
    float s = 0.f;
#pragma unroll 4
    for (int p = 0; p < PP; p++) s += xp[(size_t)p * DD] + pp[(size_t)p * DD];
    g_xbar[(size_t)bt * DD + d] = s * (1.0f / PP);
}

// ---------------- scan ----------------
__global__ void scan_init_k(const float* __restrict__ init) {
    int s = blockIdx.x * 256 + threadIdx.x;
    float v = init[s];
#pragma unroll
    for (int b = 0; b < BB; b++) g_states[(size_t)(b * 16) * SS + s] = v;
}

__global__ void __launch_bounds__(256) scan_step_k(const float* __restrict__ Amat, int t) {
    __shared__ float st[BB][SS];
    __shared__ float red[BB][256];
    int tid = threadIdx.x;
    for (int i = tid; i < BB * SS; i += 256) {
        int b = i >> 10, s = i & 1023;
        st[b][s] = g_states[(size_t)(b * 16 + t) * SS + s];
    }
    __syncthreads();
    int col  = blockIdx.x * 128 + (tid & 127);
    int half = tid >> 7;
    float acc[BB] = {};
    int k0 = half * 512;
#pragma unroll 4
    for (int k = k0; k < k0 + 512; k++) {
        float av = Amat[(size_t)k * SS + col];
#pragma unroll
        for (int b = 0; b < BB; b++) acc[b] += st[b][k] * av;
    }
#pragma unroll
    for (int b = 0; b < BB; b++) red[b][tid] = acc[b];
    __syncthreads();
    if (half == 0) {
#pragma unroll
        for (int b = 0; b < BB; b++) {
            float v = red[b][tid] + red[b][tid + 128] + g_q[(size_t)(b * 16 + t) * SS + col];
            g_states[(size_t)(b * 16 + t + 1) * SS + col] = v;
        }
    }
}

// ---------------- host ----------------
extern "C" void kernel_launch(void* const* d_in, const int* in_sizes, int n_in,
                              void* d_out, int out_size) {
    const float* x     = (const float*)d_in[0];
    const float* pos   = (const float*)d_in[1];
    const float* W_in  = (const float*)d_in[2];
    const float* b_in  = (const float*)d_in[3];
    const float* W_out = (const float*)d_in[4];
    const float* b_out = (const float*)d_in[5];
    const float* Amat  = (const float*)d_in[6];
    const float* Bm    = (const float*)d_in[7];
    const float* init  = (const float*)d_in[8];
    float* out = (float*)d_out;

    float *WoutR, *WinT, *WinTR, *BmR, *AR, *Ht, *Gt, *G, *MwT, *Xsum, *xbar, *m, *q, *states;
    cudaGetSymbolAddress((void**)&WoutR,  g_WoutR);
    cudaGetSymbolAddress((void**)&WinT,   g_WinT);
    cudaGetSymbolAddress((void**)&WinTR,  g_WinTR);
    cudaGetSymbolAddress((void**)&BmR,    g_BmR);
    cudaGetSymbolAddress((void**)&AR,     g_AR);
    cudaGetSymbolAddress((void**)&Ht,     g_Ht);
    cudaGetSymbolAddress((void**)&Gt,     g_Gt);
    cudaGetSymbolAddress((void**)&G,      g_G);
    cudaGetSymbolAddress((void**)&MwT,    g_MwT);
    cudaGetSymbolAddress((void**)&Xsum,   g_Xsum);
    cudaGetSymbolAddress((void**)&xbar,   g_xbar);
    cudaGetSymbolAddress((void**)&m,      g_m);
    cudaGetSymbolAddress((void**)&q,      g_q);
    cudaGetSymbolAddress((void**)&states, g_states);

    float *r;
    cudaGetSymbolAddress((void**)&r, g_r);

    cudaFuncSetAttribute(tf32_gemm_nt<false, true>,
                         cudaFuncAttributeMaxDynamicSharedMemorySize, GEMM_SMEM);
    cudaFuncSetAttribute(tf32_gemm_nt<false, false>,
                         cudaFuncAttributeMaxDynamicSharedMemorySize, GEMM_SMEM);
    cudaFuncSetAttribute(tf32_gemm_nt<true, false>,
                         cudaFuncAttributeMaxDynamicSharedMemorySize, GEMM_SMEM);

    // prepass: Xsum = rna(x + pos)
    prepass_k<<<32768, 256>>>(x, pos);

    // WinT = W_in^T (exact); rna copies of raw weights
    transpose_k<<<dim3(32, 32), dim3(32, 8)>>>(W_in, WinT);
    rna_copy_k<<<1024, 256>>>(W_out, WoutR);
    rna_copy_k<<<1024, 256>>>(Bm,    BmR);
    rna_copy_k<<<1024, 256>>>(Amat,  AR);
    rna_copy_k<<<1024, 256>>>(WinT,  WinTR);

    // Ht = rna(WoutR @ BmR^T), Gt = rna(WoutR @ AR^T)  [batched]
    tf32_gemm_nt<false, true><<<dim3(8, 8, 2), 256, GEMM_SMEM>>>(
        WoutR, BmR, AR, Ht, Gt);
    // MwT = rna(Ht @ WinTR^T)
    tf32_gemm_nt<false, false><<<dim3(8, 8), 256, GEMM_SMEM>>>(
        Ht, WinTR, nullptr, MwT, nullptr);

    // G = Gt^T for fp32 r-GEMM
    transpose_k<<<dim3(32, 32), dim3(32, 8)>>>(Gt, G);

    // c = b_in @ H + b_out  (rows of Ht)
    cvec_k<<<1024, 256>>>(b_in, b_out);

    // xbar = mean_p(x + pos)
    xbar_k<<<dim3(4, 128), 256>>>(x, pos);

    // m = xbar@WinT + b_in ; q = m@Bm  (exact fp32 path)
    sgemm_nn<32, 64, 32, 2, 4, true ><<<dim3(16, 4), 256>>>(128, 1024, 1024, xbar, WinT, m, b_in);
    sgemm_nn<32, 64, 32, 2, 4, false><<<dim3(16, 4), 256>>>(128, 1024, 1024, m,    Bm,   q, nullptr);

    // scan
    scan_init_k<<<4, 256>>>(init);
    for (int t = 0; t < 15; t++) scan_step_k<<<8, 256>>>(Amat, t);

    // r = states@G
    sgemm_nn<32, 64, 32, 2, 4, false><<<dim3(16, 4), 256>>>(128, 1024, 1024, states, G, r, nullptr);

    // main GEMM: out = Xsum @ MwT^T + r + c
    tf32_gemm_nt<true, false><<<dim3(8, 256), 256, GEMM_SMEM>>>(
        Xsum, MwT, nullptr, out, nullptr);
}

// round 6
// speedup vs baseline: 2.7197x; 1.3061x over previous
#include <cuda_runtime.h>
#include <cstdint>

#define DD   1024
#define SS   1024
#define TT   16
#define PP   256
#define BB   8
#define BT   128
#define MROWS 32768

// ---------------- device scratch ----------------
__device__ float g_WoutR[DD*SS];  // rna(W_out)
__device__ float g_WinT [DD*SS];  // W_in^T (fp32 exact)
__device__ float g_WinTR[DD*SS];  // rna(W_in^T)
__device__ float g_BmR [SS*SS];   // rna(Bm)
__device__ float g_AR  [SS*SS];   // rna(A)
__device__ float g_Ht  [DD*SS];   // rna(W_out @ Bm^T)
__device__ float g_Gt  [DD*SS];   // rna(W_out @ A^T)
__device__ float g_G   [SS*DD];   // Gt^T
__device__ float g_MwT [DD*DD];   // rna(Ht @ WinTR^T)
__device__ float g_Xsum[(size_t)MROWS*DD]; // rna(x + pos)
__device__ float g_xbar[BT*DD];
__device__ float g_m   [BT*SS];
__device__ float g_q   [BT*SS];
__device__ float g_states[BT*SS];
__device__ float g_r   [BT*DD];
__device__ float g_c   [DD];

// ---------------- helpers ----------------
__device__ __forceinline__ float f_rna(float v) {
    uint32_t u;
    asm("cvt.rna.tf32.f32 %0, %1;" : "=r"(u) : "f"(v));
    return __uint_as_float(u);
}
__device__ __forceinline__ uint32_t smem_u32(const void* p) {
    uint32_t a;
    asm("{ .reg .u64 t; cvta.to.shared.u64 t, %1; cvt.u32.u64 %0, t; }" : "=r"(a) : "l"(p));
    return a;
}
__device__ __forceinline__ void cp_async16(uint32_t dst, const void* src) {
    asm volatile("cp.async.cg.shared.global [%0], [%1], 16;" :: "r"(dst), "l"(src) : "memory");
}
#define CP_COMMIT() asm volatile("cp.async.commit_group;" ::: "memory")
#define CP_WAIT2()  asm volatile("cp.async.wait_group 2;" ::: "memory")

__device__ __forceinline__ void ldsm_x4(uint32_t* r, uint32_t addr) {
    asm volatile("ldmatrix.sync.aligned.m8n8.x4.shared.b16 {%0,%1,%2,%3}, [%4];"
        : "=r"(r[0]), "=r"(r[1]), "=r"(r[2]), "=r"(r[3]) : "r"(addr));
}
__device__ __forceinline__ void mma_tf32(float* d, const uint32_t* a, const uint32_t* b) {
    asm volatile(
        "mma.sync.aligned.m16n8k8.row.col.f32.tf32.tf32.f32 "
        "{%0,%1,%2,%3}, {%4,%5,%6,%7}, {%8,%9}, {%0,%1,%2,%3};"
        : "+f"(d[0]), "+f"(d[1]), "+f"(d[2]), "+f"(d[3])
        : "r"(a[0]), "r"(a[1]), "r"(a[2]), "r"(a[3]), "r"(b[0]), "r"(b[1]));
}

// ================= tf32 NT GEMM: C[M,N] = A[M,K] @ Bt[N,K]^T =================
// CTA tile 128(M) x 256(N), K chunk 32, 4-stage cp.async, 256 threads = 8 warps
// (2m x 4n), warp tile 64x64, ldmatrix fragments, 1 CTA/SM.
#define OP_A_BYTES   18432          // 128 rows * 144B
#define STAGE_BYTES  55296          // (128+256) rows * 144B
#define NSTAGE       4
#define GEMM_SMEM    (NSTAGE * STAGE_BYTES)

template <bool EPI_RC, bool DUAL>
__global__ void __launch_bounds__(256, 1) tf32_gemm_nt(
    const float* __restrict__ Aop,
    const float* __restrict__ Bop, const float* __restrict__ Bop2,
    float* __restrict__ Cop, float* __restrict__ Cop2)
{
    extern __shared__ float smem[];
    const uint32_t sb = smem_u32(smem);

    const int tid  = threadIdx.x;
    const int lane = tid & 31;
    const int w    = tid >> 5;
    const int wm   = (w >> 2) * 64;     // 2 m-warps
    const int wn   = (w & 3) * 64;      // 4 n-warps
    const int g    = lane >> 2;
    const int tg   = lane & 3;

    const int rowBase = blockIdx.y * 128;
    const int colBase = blockIdx.x * 256;
    const float* __restrict__ Bsel = (DUAL && blockIdx.z) ? Bop2 : Bop;
    float* __restrict__ Csel       = (DUAL && blockIdx.z) ? Cop2 : Cop;
    const float* __restrict__ Ag = Aop  + (size_t)rowBase * 1024;
    const float* __restrict__ Bg = Bsel + (size_t)colBase * 1024;

    float acc[4][8][4];
#pragma unroll
    for (int i = 0; i < 4; i++)
#pragma unroll
        for (int j = 0; j < 8; j++)
#pragma unroll
            for (int k = 0; k < 4; k++) acc[i][j][k] = 0.f;

    const int lr = tid >> 3, lc4 = tid & 7;   // loader coords

    auto load_stage = [&](int chunk, int st) {
        const uint32_t dA = sb + st * STAGE_BYTES;
        const uint32_t dB = dA + OP_A_BYTES;
        const int k0 = chunk * 32;
#pragma unroll
        for (int i = 0; i < 4; i++) {           // A: 128 rows
            int r = lr + i * 32;
            cp_async16(dA + r * 144 + lc4 * 16, Ag + (size_t)r * 1024 + k0 + lc4 * 4);
        }
#pragma unroll
        for (int i = 0; i < 8; i++) {           // B: 256 rows
            int r = lr + i * 32;
            cp_async16(dB + r * 144 + lc4 * 16, Bg + (size_t)r * 1024 + k0 + lc4 * 4);
        }
        CP_COMMIT();
    };

    // ldmatrix per-lane offsets within operand regions
    const uint32_t aoff = (uint32_t)((wm + (lane & 15)) * 144 + ((lane >> 4) << 4));
    const uint32_t boff = (uint32_t)((wn + ((lane >> 4) << 3) + (lane & 7)) * 144 +
                                     (((lane >> 3) & 1) << 4));

    auto compute = [&](int st) {
        const uint32_t ab = sb + st * STAGE_BYTES + aoff;
        const uint32_t bb = sb + st * STAGE_BYTES + OP_A_BYTES + boff;
#pragma unroll
        for (int kk = 0; kk < 4; kk++) {
            const uint32_t kb = kk * 32;
            uint32_t a[4][4], bq[4][4];
#pragma unroll
            for (int mi = 0; mi < 4; mi++) ldsm_x4(a[mi], ab + mi * 2304 + kb);
#pragma unroll
            for (int nj = 0; nj < 4; nj++) ldsm_x4(bq[nj], bb + nj * 2304 + kb);
#pragma unroll
            for (int mi = 0; mi < 4; mi++)
#pragma unroll
                for (int ni = 0; ni < 8; ni++)
                    mma_tf32(acc[mi][ni], a[mi], &bq[ni >> 1][(ni & 1) * 2]);
        }
    };

    load_stage(0, 0);
    load_stage(1, 1);
    load_stage(2, 2);

#pragma unroll 1
    for (int c = 0; c < 32; c++) {
        CP_WAIT2();                 // chunk c complete (3+c commits, <=2 pending)
        __syncthreads();
        if (c + 3 < 32) {
            int nst = c + 3; nst &= 3;
            load_stage(c + 3, nst);
        } else {
            CP_COMMIT();            // empty group keeps wait_group(2) accounting exact
        }
        compute(c & 3);
    }

    // ---- epilogue ----
#pragma unroll
    for (int mi = 0; mi < 4; mi++) {
        const int row0 = rowBase + wm + mi * 16 + g;
        const int row1 = row0 + 8;
#pragma unroll
        for (int ni = 0; ni < 8; ni++) {
            const int col = colBase + wn + ni * 8 + tg * 2;
            float v0 = acc[mi][ni][0], v1 = acc[mi][ni][1];
            float v2 = acc[mi][ni][2], v3 = acc[mi][ni][3];
            if (EPI_RC) {
                const float* r0 = g_r + (size_t)(row0 >> 8) * 1024 + col;
                const float* r1 = g_r + (size_t)(row1 >> 8) * 1024 + col;
                float2 ra = *(const float2*)r0;
                float2 rb = *(const float2*)r1;
                float2 cc = *(const float2*)(g_c + col);
                v0 += ra.x + cc.x; v1 += ra.y + cc.y;
                v2 += rb.x + cc.x; v3 += rb.y + cc.y;
            } else {
                v0 = f_rna(v0); v1 = f_rna(v1); v2 = f_rna(v2); v3 = f_rna(v3);
            }
            *(float2*)(Csel + (size_t)row0 * 1024 + col) = make_float2(v0, v1);
            *(float2*)(Csel + (size_t)row1 * 1024 + col) = make_float2(v2, v3);
        }
    }
}

// ---------------- prepass: Xsum = rna(x + pos) ----------------
__global__ void prepass_k(const float* __restrict__ x, const float* __restrict__ pos) {
    size_t i = ((size_t)blockIdx.x * 256 + threadIdx.x) * 4;
    float4 vx = *(const float4*)(x + i);
    float4 vp = *(const float4*)(pos + (i & ((size_t)4194304 - 1)));
    float4 o;
    o.x = f_rna(vx.x + vp.x); o.y = f_rna(vx.y + vp.y);
    o.z = f_rna(vx.z + vp.z); o.w = f_rna(vx.w + vp.w);
    *(float4*)(g_Xsum + i) = o;
}

// ---------------- batched rna copies: (W_out, Bm, A) -> (WoutR, BmR, AR) ----------------
__global__ void rna3_k(const float* __restrict__ w0, const float* __restrict__ w1,
                       const float* __restrict__ w2) {
    const float* in = blockIdx.y == 0 ? w0 : (blockIdx.y == 1 ? w1 : w2);
    float* out = blockIdx.y == 0 ? g_WoutR : (blockIdx.y == 1 ? g_BmR : g_AR);
    int i = (blockIdx.x * 256 + threadIdx.x) * 4;
    float4 v = *(const float4*)(in + i);
    v.x = f_rna(v.x); v.y = f_rna(v.y); v.z = f_rna(v.z); v.w = f_rna(v.w);
    *(float4*)(out + i) = v;
}

// ---------------- transpose 1024x1024 (optionally rna) ----------------
template <bool RNA>
__global__ void transpose_k(const float* __restrict__ in, float* __restrict__ out) {
    __shared__ float tile[32][33];
    int x = blockIdx.x * 32 + threadIdx.x;
    int y = blockIdx.y * 32 + threadIdx.y;
#pragma unroll
    for (int i = 0; i < 32; i += 8)
        tile[threadIdx.y + i][threadIdx.x] = in[(size_t)(y + i) * DD + x];
    __syncthreads();
    x = blockIdx.y * 32 + threadIdx.x;
    y = blockIdx.x * 32 + threadIdx.y;
#pragma unroll
    for (int i = 0; i < 32; i += 8) {
        float v = tile[threadIdx.x][threadIdx.y + i];
        out[(size_t)(y + i) * DD + x] = RNA ? f_rna(v) : v;
    }
}

// ---------------- fp32 SGEMM (NN) for small matrices ----------------
template <int BM, int BN, int BK, int TM, int TN, bool BIAS>
__global__ void __launch_bounds__((BM / TM) * (BN / TN))
sgemm_nn(int M, int N, int K,
         const float* __restrict__ A, const float* __restrict__ B,
         float* __restrict__ C, const float* __restrict__ bias) {
    constexpr int THREADS = (BM / TM) * (BN / TN);
    __shared__ float As[BK][BM];
    __shared__ float Bs[BK][BN];
    const int tid = threadIdx.x;
    const int tx = tid % (BN / TN);
    const int ty = tid / (BN / TN);
    const float* Ag = A + (size_t)blockIdx.y * BM * K;
    const float* Bg = B + (size_t)blockIdx.x * BN;
    float acc[TM][TN] = {};
    constexpr int AIT = (BM * BK) / (THREADS * 4);
    constexpr int BIT = (BK * BN) / (THREADS * 4);
    static_assert(AIT >= 1 && BIT >= 1, "tile/thread mismatch");

    for (int k0 = 0; k0 < K; k0 += BK) {
#pragma unroll
        for (int it = 0; it < AIT; it++) {
            int i = tid * 4 + it * THREADS * 4;
            int r = i / BK, c = i % BK;
            float4 v = *(const float4*)(Ag + (size_t)r * K + k0 + c);
            As[c + 0][r] = v.x; As[c + 1][r] = v.y;
            As[c + 2][r] = v.z; As[c + 3][r] = v.w;
        }
#pragma unroll
        for (int it = 0; it < BIT; it++) {
            int i = tid * 4 + it * THREADS * 4;
            int r = i / BN, c = i % BN;
            *(float4*)(&Bs[r][c]) = *(const float4*)(Bg + (size_t)(k0 + r) * N + c);
        }
        __syncthreads();
#pragma unroll
        for (int k = 0; k < BK; k++) {
            float a[TM], bv[TN];
#pragma unroll
            for (int i = 0; i < TM; i++) a[i] = As[k][ty * TM + i];
#pragma unroll
            for (int j = 0; j < TN; j++) bv[j] = Bs[k][tx * TN + j];
#pragma unroll
            for (int i = 0; i < TM; i++)
#pragma unroll
                for (int j = 0; j < TN; j++) acc[i][j] += a[i] * bv[j];
        }
        __syncthreads();
    }
#pragma unroll
    for (int i = 0; i < TM; i++) {
        int row = blockIdx.y * BM + ty * TM + i;
#pragma unroll
        for (int j = 0; j < TN; j++) {
            int cn = blockIdx.x * BN + tx * TN + j;
            float v = acc[i][j];
            if (BIAS) v += bias[cn];
            C[(size_t)row * N + cn] = v;
        }
    }
}

// ---------------- c[d] = b_in @ H + b_out  (rows of Ht) ----------------
__global__ void cvec_k(const float* __restrict__ b_in, const float* __restrict__ b_out) {
    __shared__ float red[256];
    const int d = blockIdx.x;
    const int tid = threadIdx.x;
    const float* row = g_Ht + (size_t)d * 1024;
    float s = 0.f;
    for (int j = tid; j < SS; j += 256) s += row[j] * b_in[j];
    red[tid] = s;
    __syncthreads();
    for (int o = 128; o > 0; o >>= 1) {
        if (tid < o) red[tid] += red[tid + o];
        __syncthreads();
    }
    if (tid == 0) g_c[d] = red[0] + b_out[d];
}

// ---------------- xbar[bt,d] = mean_p Xsum[bt*256+p, d] ----------------
__global__ void xbar_k() {
    int d  = blockIdx.x * 256 + threadIdx.x;
    int bt = blockIdx.y;
    const float* xp = g_Xsum + (size_t)bt * PP * DD + d;
    float s = 0.f;
#pragma unroll 4
    for (int p = 0; p < PP; p++) s += xp[(size_t)p * DD];
    g_xbar[(size_t)bt * DD + d] = s * (1.0f / PP);
}

// ---------------- scan ----------------
__global__ void scan_init_k(const float* __restrict__ init) {
    int s = blockIdx.x * 256 + threadIdx.x;
    float v = init[s];
#pragma unroll
    for (int b = 0; b < BB; b++) g_states[(size_t)(b * 16) * SS + s] = v;
}

// 64 CTAs, each handles 16 columns with 16-way K split
__global__ void __launch_bounds__(256) scan_step_k(const float* __restrict__ Amat, int t) {
    __shared__ float st[BB][SS];      // 32 KB
    __shared__ float red[BB][256];    // 8 KB
    const int tid = threadIdx.x;
    for (int i = tid; i < BB * SS; i += 256) {
        int b = i >> 10, s = i & 1023;
        st[b][s] = g_states[(size_t)(b * 16 + t) * SS + s];
    }
    __syncthreads();
    const int col  = blockIdx.x * 16 + (tid & 15);
    const int part = tid >> 4;                    // 0..15, 64 k each
    float acc[BB] = {};
    const int k0 = part * 64;
#pragma unroll 4
    for (int k = k0; k < k0 + 64; k++) {
        float av = Amat[(size_t)k * SS + col];
#pragma unroll
        for (int b = 0; b < BB; b++) acc[b] += st[b][k] * av;
    }
#pragma unroll
    for (int b = 0; b < BB; b++) red[b][tid] = acc[b];
    __syncthreads();
    for (int o = 8; o > 0; o >>= 1) {
        if (part < o) {
#pragma unroll
            for (int b = 0; b < BB; b++) red[b][tid] += red[b][tid + (o << 4)];
        }
        __syncthreads();
    }
    if (part == 0) {
#pragma unroll
        for (int b = 0; b < BB; b++) {
            float v = red[b][tid] + g_q[(size_t)(b * 16 + t) * SS + col];
            g_states[(size_t)(b * 16 + t + 1) * SS + col] = v;
        }
    }
}

// ---------------- host ----------------
extern "C" void kernel_launch(void* const* d_in, const int* in_sizes, int n_in,
                              void* d_out, int out_size) {
    const float* x     = (const float*)d_in[0];
    const float* pos   = (const float*)d_in[1];
    const float* W_in  = (const float*)d_in[2];
    const float* b_in  = (const float*)d_in[3];
    const float* W_out = (const float*)d_in[4];
    const float* b_out = (const float*)d_in[5];
    const float* Amat  = (const float*)d_in[6];
    const float* Bm    = (const float*)d_in[7];
    const float* init  = (const float*)d_in[8];
    float* out = (float*)d_out;

    float *WoutR, *WinT, *WinTR, *BmR, *AR, *Ht, *Gt, *G, *MwT, *Xsum, *xbar, *m, *q, *states, *r;
    cudaGetSymbolAddress((void**)&WoutR,  g_WoutR);
    cudaGetSymbolAddress((void**)&WinT,   g_WinT);
    cudaGetSymbolAddress((void**)&WinTR,  g_WinTR);
    cudaGetSymbolAddress((void**)&BmR,    g_BmR);
    cudaGetSymbolAddress((void**)&AR,     g_AR);
    cudaGetSymbolAddress((void**)&Ht,     g_Ht);
    cudaGetSymbolAddress((void**)&Gt,     g_Gt);
    cudaGetSymbolAddress((void**)&G,      g_G);
    cudaGetSymbolAddress((void**)&MwT,    g_MwT);
    cudaGetSymbolAddress((void**)&Xsum,   g_Xsum);
    cudaGetSymbolAddress((void**)&xbar,   g_xbar);
    cudaGetSymbolAddress((void**)&m,      g_m);
    cudaGetSymbolAddress((void**)&q,      g_q);
    cudaGetSymbolAddress((void**)&states, g_states);
    cudaGetSymbolAddress((void**)&r,      g_r);

    cudaFuncSetAttribute(tf32_gemm_nt<false, true>,
                         cudaFuncAttributeMaxDynamicSharedMemorySize, GEMM_SMEM);
    cudaFuncSetAttribute(tf32_gemm_nt<false, false>,
                         cudaFuncAttributeMaxDynamicSharedMemorySize, GEMM_SMEM);
    cudaFuncSetAttribute(tf32_gemm_nt<true, false>,
                         cudaFuncAttributeMaxDynamicSharedMemorySize, GEMM_SMEM);

    // prepass: Xsum = rna(x + pos)
    prepass_k<<<32768, 256>>>(x, pos);

    // weight preprocessing
    transpose_k<false><<<dim3(32, 32), dim3(32, 8)>>>(W_in, WinT);   // exact
    transpose_k<true ><<<dim3(32, 32), dim3(32, 8)>>>(W_in, WinTR);  // rna
    rna3_k<<<dim3(1024, 3), 256>>>(W_out, Bm, Amat);

    // Ht = rna(WoutR @ BmR^T), Gt = rna(WoutR @ AR^T)  [batched]
    tf32_gemm_nt<false, true><<<dim3(4, 8, 2), 256, GEMM_SMEM>>>(WoutR, BmR, AR, Ht, Gt);
    // MwT = rna(Ht @ WinTR^T)
    tf32_gemm_nt<false, false><<<dim3(4, 8), 256, GEMM_SMEM>>>(Ht, WinTR, nullptr, MwT, nullptr);

    // G = Gt^T for fp32 r-GEMM
    transpose_k<false><<<dim3(32, 32), dim3(32, 8)>>>(Gt, G);

    // c = b_in @ H + b_out
    cvec_k<<<1024, 256>>>(b_in, b_out);

    // xbar = mean_p Xsum
    xbar_k<<<dim3(4, 128), 256>>>();

    // m = xbar@WinT + b_in ; q = m@Bm  (exact fp32 path)
    sgemm_nn<32, 64, 32, 2, 4, true ><<<dim3(16, 4), 256>>>(128, 1024, 1024, xbar, WinT, m, b_in);
    sgemm_nn<32, 64, 32, 2, 4, false><<<dim3(16, 4), 256>>>(128, 1024, 1024, m,    Bm,   q, nullptr);

    // scan (64 CTAs per step)
    scan_init_k<<<4, 256>>>(init);
    for (int t = 0; t < 15; t++) scan_step_k<<<64, 256>>>(Amat, t);

    // r = states@G
    sgemm_nn<32, 64, 32, 2, 4, false><<<dim3(16, 4), 256>>>(128, 1024, 1024, states, G, r, nullptr);

    // main GEMM: out = Xsum @ MwT^T + r + c
    tf32_gemm_nt<true, false><<<dim3(4, 256), 256, GEMM_SMEM>>>(Xsum, MwT, nullptr, out, nullptr);
}

// round 7
// speedup vs baseline: 3.9527x; 1.4534x over previous
#include <cuda_runtime.h>
#include <cuda_fp16.h>
#include <cstdint>

#define DD   1024
#define SS   1024
#define TT   16
#define PP   256
#define BB   8
#define BT   128
#define MROWS 32768

// ---------------- device scratch ----------------
__device__ __half g_WoutRh[DD*SS];  // h(W_out)
__device__ __half g_BmRh [SS*SS];   // h(Bm)
__device__ __half g_ARh  [SS*SS];   // h(A)
__device__ __half g_WinTRh[DD*SS];  // h(W_in^T)
__device__ __half g_Hth  [DD*SS];   // h(W_out @ Bm^T)
__device__ __half g_Gth  [DD*SS];   // h(W_out @ A^T)
__device__ __half g_MwTh [DD*DD];   // h(Ht @ WinTR^T)
__device__ __half g_Xsumh[(size_t)MROWS*DD]; // h(x + pos)
__device__ float g_WinT [DD*SS];    // W_in^T exact fp32
__device__ float g_G    [SS*DD];    // Gt^T fp32
__device__ float g_xbar[BT*DD];
__device__ float g_m   [BT*SS];
__device__ float g_q   [BT*SS];
__device__ float g_states[BT*SS];
__device__ float g_r   [BT*DD];
__device__ float g_c   [DD];

// ---------------- helpers ----------------
__device__ __forceinline__ uint32_t smem_u32(const void* p) {
    uint32_t a;
    asm("{ .reg .u64 t; cvta.to.shared.u64 t, %1; cvt.u32.u64 %0, t; }" : "=r"(a) : "l"(p));
    return a;
}
__device__ __forceinline__ void cp_async16(uint32_t dst, const void* src) {
    asm volatile("cp.async.cg.shared.global [%0], [%1], 16;" :: "r"(dst), "l"(src) : "memory");
}
#define CP_COMMIT() asm volatile("cp.async.commit_group;" ::: "memory")
#define CP_WAIT2()  asm volatile("cp.async.wait_group 2;" ::: "memory")

__device__ __forceinline__ void ldsm_x4(uint32_t* r, uint32_t addr) {
    asm volatile("ldmatrix.sync.aligned.m8n8.x4.shared.b16 {%0,%1,%2,%3}, [%4];"
        : "=r"(r[0]), "=r"(r[1]), "=r"(r[2]), "=r"(r[3]) : "r"(addr));
}
__device__ __forceinline__ void mma_f16(float* d, const uint32_t* a, const uint32_t* b) {
    asm volatile(
        "mma.sync.aligned.m16n8k16.row.col.f32.f16.f16.f32 "
        "{%0,%1,%2,%3}, {%4,%5,%6,%7}, {%8,%9}, {%0,%1,%2,%3};"
        : "+f"(d[0]), "+f"(d[1]), "+f"(d[2]), "+f"(d[3])
        : "r"(a[0]), "r"(a[1]), "r"(a[2]), "r"(a[3]), "r"(b[0]), "r"(b[1]));
}

// ================= fp16 NT GEMM: C[M,N] = A[M,K] @ Bt[N,K]^T, fp32 accum =================
// CTA tile 128(M) x 256(N), K chunk 64 (halves), 4-stage cp.async, 8 warps (2m x 4n),
// warp tile 64x64, mma m16n8k16, 1 CTA/SM.
// smem row: 64 halves = 128B data + 16B pad = 144B
#define OPA_B   18432u              // 128 rows * 144B
#define STAGE_B 55296u              // 384 rows * 144B
#define NSTAGE  4
#define NCHUNK  16                  // 1024 / 64
#define GEMM_SMEM (NSTAGE * STAGE_B)

template <bool EPI_RC, bool DUAL, typename CT>
__global__ void __launch_bounds__(256, 1) f16_gemm_nt(
    const __half* __restrict__ Aop,
    const __half* __restrict__ Bop, const __half* __restrict__ Bop2,
    CT* __restrict__ Cop, CT* __restrict__ Cop2)
{
    extern __shared__ char smem[];
    const uint32_t sb = smem_u32(smem);

    const int tid  = threadIdx.x;
    const int lane = tid & 31;
    const int w    = tid >> 5;
    const int wm   = (w >> 2) * 64;
    const int wn   = (w & 3) * 64;
    const int g    = lane >> 2;
    const int tg   = lane & 3;

    const int rowBase = blockIdx.y * 128;
    const int colBase = blockIdx.x * 256;
    const __half* __restrict__ Bsel = (DUAL && blockIdx.z) ? Bop2 : Bop;
    CT* __restrict__ Csel           = (DUAL && blockIdx.z) ? Cop2 : Cop;
    const __half* __restrict__ Ag = Aop  + (size_t)rowBase * 1024;
    const __half* __restrict__ Bg = Bsel + (size_t)colBase * 1024;

    float acc[4][8][4];
#pragma unroll
    for (int i = 0; i < 4; i++)
#pragma unroll
        for (int j = 0; j < 8; j++)
#pragma unroll
            for (int k = 0; k < 4; k++) acc[i][j][k] = 0.f;

    auto load_stage = [&](int chunk, int st) {
        const uint32_t dA = sb + st * STAGE_B;
        const uint32_t dB = dA + OPA_B;
        const int k0 = chunk * 64;
#pragma unroll
        for (int i = 0; i < 4; i++) {           // A: 128 rows x 8 x 16B
            int idx = i * 256 + tid;
            int r = idx >> 3, c = idx & 7;
            cp_async16(dA + r * 144 + c * 16, Ag + (size_t)r * 1024 + k0 + c * 8);
        }
#pragma unroll
        for (int i = 0; i < 8; i++) {           // B: 256 rows x 8 x 16B
            int idx = i * 256 + tid;
            int r = idx >> 3, c = idx & 7;
            cp_async16(dB + r * 144 + c * 16, Bg + (size_t)r * 1024 + k0 + c * 8);
        }
        CP_COMMIT();
    };

    // ldmatrix per-lane byte offsets (same quad maps as tf32 version, halved elem size)
    const uint32_t aoff = (uint32_t)((wm + (lane & 15)) * 144 + ((lane >> 4) << 4));
    const uint32_t boff = (uint32_t)((wn + ((lane >> 4) << 3) + (lane & 7)) * 144 +
                                     (((lane >> 3) & 1) << 4));

    auto compute = [&](int st) {
        const uint32_t ab = sb + st * STAGE_B + aoff;
        const uint32_t bb = sb + st * STAGE_B + OPA_B + boff;
#pragma unroll
        for (int kk = 0; kk < 4; kk++) {        // 4 x k16 per 64-chunk
            const uint32_t kb = kk * 32;        // 16 halves = 32B
            uint32_t a[4][4], bq[4][4];
#pragma unroll
            for (int mi = 0; mi < 4; mi++) ldsm_x4(a[mi], ab + mi * 2304 + kb);
#pragma unroll
            for (int nj = 0; nj < 4; nj++) ldsm_x4(bq[nj], bb + nj * 2304 + kb);
#pragma unroll
            for (int mi = 0; mi < 4; mi++)
#pragma unroll
                for (int ni = 0; ni < 8; ni++)
                    mma_f16(acc[mi][ni], a[mi], &bq[ni >> 1][(ni & 1) * 2]);
        }
    };

    load_stage(0, 0);
    load_stage(1, 1);
    load_stage(2, 2);

#pragma unroll 1
    for (int c = 0; c < NCHUNK; c++) {
        CP_WAIT2();
        __syncthreads();
        if (c + 3 < NCHUNK) load_stage(c + 3, (c + 3) & 3);
        else CP_COMMIT();
        compute(c & 3);
    }

    // ---- epilogue ----
#pragma unroll
    for (int mi = 0; mi < 4; mi++) {
        const int row0 = rowBase + wm + mi * 16 + g;
        const int row1 = row0 + 8;
#pragma unroll
        for (int ni = 0; ni < 8; ni++) {
            const int col = colBase + wn + ni * 8 + tg * 2;
            float v0 = acc[mi][ni][0], v1 = acc[mi][ni][1];
            float v2 = acc[mi][ni][2], v3 = acc[mi][ni][3];
            if (EPI_RC) {
                const float* r0 = g_r + (size_t)(row0 >> 8) * 1024 + col;
                const float* r1 = g_r + (size_t)(row1 >> 8) * 1024 + col;
                float2 ra = *(const float2*)r0;
                float2 rb = *(const float2*)r1;
                float2 cc = *(const float2*)(g_c + col);
                *(float2*)((float*)Csel + (size_t)row0 * 1024 + col) =
                    make_float2(v0 + ra.x + cc.x, v1 + ra.y + cc.y);
                *(float2*)((float*)Csel + (size_t)row1 * 1024 + col) =
                    make_float2(v2 + rb.x + cc.x, v3 + rb.y + cc.y);
            } else {
                *(__half2*)((__half*)Csel + (size_t)row0 * 1024 + col) =
                    __floats2half2_rn(v0, v1);
                *(__half2*)((__half*)Csel + (size_t)row1 * 1024 + col) =
                    __floats2half2_rn(v2, v3);
            }
        }
    }
}

// ---------------- fused prepass: Xsumh = h(x+pos), xbar = mean_p(x+pos) ----------------
__global__ void prepass_k(const float* __restrict__ x, const float* __restrict__ pos) {
    const int bt = blockIdx.y;
    const int t  = bt & 15;
    const int d  = (blockIdx.x * 256 + threadIdx.x) * 2;
    const float* xp = x   + (size_t)bt * PP * DD + d;
    const float* pp = pos + (size_t)t  * PP * DD + d;
    __half* op = g_Xsumh + (size_t)bt * PP * DD + d;
    float sx = 0.f, sy = 0.f;
#pragma unroll 4
    for (int p = 0; p < PP; p++) {
        float2 a = *(const float2*)(xp + (size_t)p * DD);
        float2 b = *(const float2*)(pp + (size_t)p * DD);
        float vx = a.x + b.x, vy = a.y + b.y;
        sx += vx; sy += vy;
        *(__half2*)(op + (size_t)p * DD) = __floats2half2_rn(vx, vy);
    }
    g_xbar[(size_t)bt * DD + d]     = sx * (1.0f / PP);
    g_xbar[(size_t)bt * DD + d + 1] = sy * (1.0f / PP);
}

// ---------------- batched half copies: (W_out, Bm, A) -> half ----------------
__global__ void h3_k(const float* __restrict__ w0, const float* __restrict__ w1,
                     const float* __restrict__ w2) {
    const float* in = blockIdx.y == 0 ? w0 : (blockIdx.y == 1 ? w1 : w2);
    __half* out = blockIdx.y == 0 ? g_WoutRh : (blockIdx.y == 1 ? g_BmRh : g_ARh);
    int i = (blockIdx.x * 256 + threadIdx.x) * 4;
    float4 v = *(const float4*)(in + i);
    *(__half2*)(out + i)     = __floats2half2_rn(v.x, v.y);
    *(__half2*)(out + i + 2) = __floats2half2_rn(v.z, v.w);
}

// ---------------- transposes ----------------
__global__ void transpose_f(const float* __restrict__ in, float* __restrict__ out) {
    __shared__ float tile[32][33];
    int x = blockIdx.x * 32 + threadIdx.x;
    int y = blockIdx.y * 32 + threadIdx.y;
#pragma unroll
    for (int i = 0; i < 32; i += 8)
        tile[threadIdx.y + i][threadIdx.x] = in[(size_t)(y + i) * DD + x];
    __syncthreads();
    x = blockIdx.y * 32 + threadIdx.x;
    y = blockIdx.x * 32 + threadIdx.y;
#pragma unroll
    for (int i = 0; i < 32; i += 8)
        out[(size_t)(y + i) * DD + x] = tile[threadIdx.x][threadIdx.y + i];
}
__global__ void transpose_fh(const float* __restrict__ in, __half* __restrict__ out) {
    __shared__ float tile[32][33];
    int x = blockIdx.x * 32 + threadIdx.x;
    int y = blockIdx.y * 32 + threadIdx.y;
#pragma unroll
    for (int i = 0; i < 32; i += 8)
        tile[threadIdx.y + i][threadIdx.x] = in[(size_t)(y + i) * DD + x];
    __syncthreads();
    x = blockIdx.y * 32 + threadIdx.x;
    y = blockIdx.x * 32 + threadIdx.y;
#pragma unroll
    for (int i = 0; i < 32; i += 8)
        out[(size_t)(y + i) * DD + x] = __float2half_rn(tile[threadIdx.x][threadIdx.y + i]);
}
__global__ void transpose_hf(const __half* __restrict__ in, float* __restrict__ out) {
    __shared__ float tile[32][33];
    int x = blockIdx.x * 32 + threadIdx.x;
    int y = blockIdx.y * 32 + threadIdx.y;
#pragma unroll
    for (int i = 0; i < 32; i += 8)
        tile[threadIdx.y + i][threadIdx.x] = __half2float(in[(size_t)(y + i) * DD + x]);
    __syncthreads();
    x = blockIdx.y * 32 + threadIdx.x;
    y = blockIdx.x * 32 + threadIdx.y;
#pragma unroll
    for (int i = 0; i < 32; i += 8)
        out[(size_t)(y + i) * DD + x] = tile[threadIdx.x][threadIdx.y + i];
}

// ---------------- fp32 SGEMM (NN) for small matrices ----------------
template <int BM, int BN, int BK, int TM, int TN, bool BIAS>
__global__ void __launch_bounds__((BM / TM) * (BN / TN))
sgemm_nn(int M, int N, int K,
         const float* __restrict__ A, const float* __restrict__ B,
         float* __restrict__ C, const float* __restrict__ bias) {
    constexpr int THREADS = (BM / TM) * (BN / TN);
    __shared__ float As[BK][BM];
    __shared__ float Bs[BK][BN];
    const int tid = threadIdx.x;
    const int tx = tid % (BN / TN);
    const int ty = tid / (BN / TN);
    const float* Ag = A + (size_t)blockIdx.y * BM * K;
    const float* Bg = B + (size_t)blockIdx.x * BN;
    float acc[TM][TN] = {};
    constexpr int AIT = (BM * BK) / (THREADS * 4);
    constexpr int BIT = (BK * BN) / (THREADS * 4);
    static_assert(AIT >= 1 && BIT >= 1, "tile/thread mismatch");

    for (int k0 = 0; k0 < K; k0 += BK) {
#pragma unroll
        for (int it = 0; it < AIT; it++) {
            int i = tid * 4 + it * THREADS * 4;
            int r = i / BK, c = i % BK;
            float4 v = *(const float4*)(Ag + (size_t)r * K + k0 + c);
            As[c + 0][r] = v.x; As[c + 1][r] = v.y;
            As[c + 2][r] = v.z; As[c + 3][r] = v.w;
        }
#pragma unroll
        for (int it = 0; it < BIT; it++) {
            int i = tid * 4 + it * THREADS * 4;
            int r = i / BN, c = i % BN;
            *(float4*)(&Bs[r][c]) = *(const float4*)(Bg + (size_t)(k0 + r) * N + c);
        }
        __syncthreads();
#pragma unroll
        for (int k = 0; k < BK; k++) {
            float a[TM], bv[TN];
#pragma unroll
            for (int i = 0; i < TM; i++) a[i] = As[k][ty * TM + i];
#pragma unroll
            for (int j = 0; j < TN; j++) bv[j] = Bs[k][tx * TN + j];
#pragma unroll
            for (int i = 0; i < TM; i++)
#pragma unroll
                for (int j = 0; j < TN; j++) acc[i][j] += a[i] * bv[j];
        }
        __syncthreads();
    }
#pragma unroll
    for (int i = 0; i < TM; i++) {
        int row = blockIdx.y * BM + ty * TM + i;
#pragma unroll
        for (int j = 0; j < TN; j++) {
            int cn = blockIdx.x * BN + tx * TN + j;
            float v = acc[i][j];
            if (BIAS) v += bias[cn];
            C[(size_t)row * N + cn] = v;
        }
    }
}

// ---------------- c[d] = b_in @ H + b_out  (rows of Hth) ----------------
__global__ void cvec_k(const float* __restrict__ b_in, const float* __restrict__ b_out) {
    __shared__ float red[256];
    const int d = blockIdx.x;
    const int tid = threadIdx.x;
    const __half* row = g_Hth + (size_t)d * 1024;
    float s = 0.f;
    for (int j = tid; j < SS; j += 256) s += __half2float(row[j]) * b_in[j];
    red[tid] = s;
    __syncthreads();
    for (int o = 128; o > 0; o >>= 1) {
        if (tid < o) red[tid] += red[tid + o];
        __syncthreads();
    }
    if (tid == 0) g_c[d] = red[0] + b_out[d];
}

// ---------------- scan ----------------
__global__ void scan_init_k(const float* __restrict__ init) {
    int s = blockIdx.x * 256 + threadIdx.x;
    float v = init[s];
#pragma unroll
    for (int b = 0; b < BB; b++) g_states[(size_t)(b * 16) * SS + s] = v;
}

__global__ void __launch_bounds__(256) scan_step_k(const float* __restrict__ Amat, int t) {
    __shared__ float st[BB][SS];
    __shared__ float red[BB][256];
    const int tid = threadIdx.x;
    for (int i = tid; i < BB * SS; i += 256) {
        int b = i >> 10, s = i & 1023;
        st[b][s] = g_states[(size_t)(b * 16 + t) * SS + s];
    }
    __syncthreads();
    const int col  = blockIdx.x * 16 + (tid & 15);
    const int part = tid >> 4;
    float acc[BB] = {};
    const int k0 = part * 64;
#pragma unroll 4
    for (int k = k0; k < k0 + 64; k++) {
        float av = Amat[(size_t)k * SS + col];
#pragma unroll
        for (int b = 0; b < BB; b++) acc[b] += st[b][k] * av;
    }
#pragma unroll
    for (int b = 0; b < BB; b++) red[b][tid] = acc[b];
    __syncthreads();
    for (int o = 8; o > 0; o >>= 1) {
        if (part < o) {
#pragma unroll
            for (int b = 0; b < BB; b++) red[b][tid] += red[b][tid + (o << 4)];
        }
        __syncthreads();
    }
    if (part == 0) {
#pragma unroll
        for (int b = 0; b < BB; b++) {
            float v = red[b][tid] + g_q[(size_t)(b * 16 + t) * SS + col];
            g_states[(size_t)(b * 16 + t + 1) * SS + col] = v;
        }
    }
}

// ---------------- host ----------------
extern "C" void kernel_launch(void* const* d_in, const int* in_sizes, int n_in,
                              void* d_out, int out_size) {
    const float* x     = (const float*)d_in[0];
    const float* pos   = (const float*)d_in[1];
    const float* W_in  = (const float*)d_in[2];
    const float* b_in  = (const float*)d_in[3];
    const float* W_out = (const float*)d_in[4];
    const float* b_out = (const float*)d_in[5];
    const float* Amat  = (const float*)d_in[6];
    const float* Bm    = (const float*)d_in[7];
    const float* init  = (const float*)d_in[8];
    float* out = (float*)d_out;

    __half *WoutRh, *BmRh, *ARh, *WinTRh, *Hth, *Gth, *MwTh, *Xsumh;
    float *WinT, *G, *xbar, *m, *q, *states, *r;
    cudaGetSymbolAddress((void**)&WoutRh, g_WoutRh);
    cudaGetSymbolAddress((void**)&BmRh,   g_BmRh);
    cudaGetSymbolAddress((void**)&ARh,    g_ARh);
    cudaGetSymbolAddress((void**)&WinTRh, g_WinTRh);
    cudaGetSymbolAddress((void**)&Hth,    g_Hth);
    cudaGetSymbolAddress((void**)&Gth,    g_Gth);
    cudaGetSymbolAddress((void**)&MwTh,   g_MwTh);
    cudaGetSymbolAddress((void**)&Xsumh,  g_Xsumh);
    cudaGetSymbolAddress((void**)&WinT,   g_WinT);
    cudaGetSymbolAddress((void**)&G,      g_G);
    cudaGetSymbolAddress((void**)&xbar,   g_xbar);
    cudaGetSymbolAddress((void**)&m,      g_m);
    cudaGetSymbolAddress((void**)&q,      g_q);
    cudaGetSymbolAddress((void**)&states, g_states);
    cudaGetSymbolAddress((void**)&r,      g_r);

    cudaFuncSetAttribute((const void*)f16_gemm_nt<false, true, __half>,
                         cudaFuncAttributeMaxDynamicSharedMemorySize, GEMM_SMEM);
    cudaFuncSetAttribute((const void*)f16_gemm_nt<false, false, __half>,
                         cudaFuncAttributeMaxDynamicSharedMemorySize, GEMM_SMEM);
    cudaFuncSetAttribute((const void*)f16_gemm_nt<true, false, float>,
                         cudaFuncAttributeMaxDynamicSharedMemorySize, GEMM_SMEM);

    // fused prepass: Xsumh = h(x+pos), xbar = mean_p(x+pos)
    prepass_k<<<dim3(2, BT), 256>>>(x, pos);

    // weight preprocessing
    transpose_f <<<dim3(32, 32), dim3(32, 8)>>>(W_in, WinT);     // exact fp32
    transpose_fh<<<dim3(32, 32), dim3(32, 8)>>>(W_in, WinTRh);   // half
    h3_k<<<dim3(1024, 3), 256>>>(W_out, Bm, Amat);

    // Hth = h(WoutRh @ BmRh^T), Gth = h(WoutRh @ ARh^T)  [batched]
    f16_gemm_nt<false, true, __half><<<dim3(4, 8, 2), 256, GEMM_SMEM>>>(
        WoutRh, BmRh, ARh, Hth, Gth);
    // MwTh = h(Hth @ WinTRh^T)
    f16_gemm_nt<false, false, __half><<<dim3(4, 8), 256, GEMM_SMEM>>>(
        Hth, WinTRh, nullptr, MwTh, nullptr);

    // G = Gth^T fp32 for the r-GEMM
    transpose_hf<<<dim3(32, 32), dim3(32, 8)>>>(Gth, G);

    // c = b_in @ H + b_out
    cvec_k<<<1024, 256>>>(b_in, b_out);

    // m = xbar@WinT + b_in ; q = m@Bm  (exact fp32 path)
    sgemm_nn<32, 64, 32, 2, 4, true ><<<dim3(16, 4), 256>>>(128, 1024, 1024, xbar, WinT, m, b_in);
    sgemm_nn<32, 64, 32, 2, 4, false><<<dim3(16, 4), 256>>>(128, 1024, 1024, m,    Bm,   q, nullptr);

    // scan
    scan_init_k<<<4, 256>>>(init);
    for (int t = 0; t < 15; t++) scan_step_k<<<64, 256>>>(Amat, t);

    // r = states@G
    sgemm_nn<32, 64, 32, 2, 4, false><<<dim3(16, 4), 256>>>(128, 1024, 1024, states, G, r, nullptr);

    // main GEMM: out = Xsumh @ MwTh^T + r + c
    f16_gemm_nt<true, false, float><<<dim3(4, 256), 256, GEMM_SMEM>>>(
        Xsumh, MwTh, nullptr, out, nullptr);
}

// round 8
// speedup vs baseline: 4.6225x; 1.1695x over previous
#include <cuda_runtime.h>
#include <cuda_fp16.h>
#include <cstdint>

#define DD   1024
#define SS   1024
#define TT   16
#define PP   256
#define BB   8
#define BT   128
#define MROWS 32768

// ---------------- device scratch ----------------
__device__ __half g_WoutRh[DD*SS];   // h(W_out)
__device__ __half g_BmRh [SS*SS];    // h(Bm)
__device__ __half g_ARh  [SS*SS];    // h(A)
__device__ __half g_WinTRh[DD*SS];   // h(W_in^T)
__device__ __half g_BmTh [SS*SS];    // h(Bm^T)
__device__ __half g_Hth  [DD*SS];    // h(W_out @ Bm^T)
__device__ __half g_Gth  [DD*SS];    // h(W_out @ A^T)
__device__ __half g_MqTh [SS*DD];    // h((WinT@Bm)^T) = h(Bm^T @ W_in)
__device__ __half g_MwTh [DD*DD];    // h(Ht @ WinTR^T)
__device__ __half g_Xsumh[(size_t)MROWS*DD]; // h(x + pos)
__device__ __half g_xbarh[BT*DD];
__device__ __half g_statesh[BT*SS];
__device__ float g_qp  [4*BT*SS];    // q split-K partials
__device__ float g_rp  [4*BT*DD];    // r split-K partials
__device__ float g_q   [BT*SS];
__device__ float g_states[BT*SS];
__device__ float g_r   [BT*DD];
__device__ float g_c   [DD];
__device__ float g_bq  [SS];

// ---------------- helpers ----------------
__device__ __forceinline__ uint32_t smem_u32(const void* p) {
    uint32_t a;
    asm("{ .reg .u64 t; cvta.to.shared.u64 t, %1; cvt.u32.u64 %0, t; }" : "=r"(a) : "l"(p));
    return a;
}
__device__ __forceinline__ void cp_async16(uint32_t dst, const void* src) {
    asm volatile("cp.async.cg.shared.global [%0], [%1], 16;" :: "r"(dst), "l"(src) : "memory");
}
#define CP_COMMIT() asm volatile("cp.async.commit_group;" ::: "memory")
#define CP_WAIT2()  asm volatile("cp.async.wait_group 2;" ::: "memory")

__device__ __forceinline__ void ldsm_x4(uint32_t* r, uint32_t addr) {
    asm volatile("ldmatrix.sync.aligned.m8n8.x4.shared.b16 {%0,%1,%2,%3}, [%4];"
        : "=r"(r[0]), "=r"(r[1]), "=r"(r[2]), "=r"(r[3]) : "r"(addr));
}
__device__ __forceinline__ void mma_f16(float* d, const uint32_t* a, const uint32_t* b) {
    asm volatile(
        "mma.sync.aligned.m16n8k16.row.col.f32.f16.f16.f32 "
        "{%0,%1,%2,%3}, {%4,%5,%6,%7}, {%8,%9}, {%0,%1,%2,%3};"
        : "+f"(d[0]), "+f"(d[1]), "+f"(d[2]), "+f"(d[3])
        : "r"(a[0]), "r"(a[1]), "r"(a[2]), "r"(a[3]), "r"(b[0]), "r"(b[1]));
}

// ================= fp16 NT GEMM: C = A[M,K] @ Bt[N,K]^T, fp32 accum =================
// NTILE: 128 or 256 (CTA N-tile; M-tile fixed 128). 8 warps (2m x Xn), warp tile 64x(NTILE/4).
// EPI: 0 = write half; 1 = write float (split-K partial); 2 = float + g_r + g_c.
// KSPLIT: blockIdx.z%KSPLIT selects K range; blockIdx.z/KSPLIT selects (A,Bt,C) triple.
template <int NTILE, int EPI, int KSPLIT>
__global__ void __launch_bounds__(256, 1) f16g(
    const __half* __restrict__ A0, const __half* __restrict__ A1, const __half* __restrict__ A2,
    const __half* __restrict__ B0, const __half* __restrict__ B1, const __half* __restrict__ B2,
    void* __restrict__ C0, void* __restrict__ C1, void* __restrict__ C2)
{
    constexpr int NI  = NTILE / 32;          // mma n-frags per warp (8 or 4)
    constexpr int NB  = NTILE / 64;          // B ldsm.x4 per kk (4 or 2)
    constexpr uint32_t OPA_B = 128u * 144u;
    constexpr uint32_t STAGE_B = (128u + NTILE) * 144u;
    constexpr int CH = 16 / KSPLIT;          // K chunks (64 halves each) this CTA does

    extern __shared__ char smem[];
    const uint32_t sb = smem_u32(smem);

    const int tid  = threadIdx.x;
    const int lane = tid & 31;
    const int w    = tid >> 5;
    const int wm   = (w >> 2) * 64;
    const int wn   = (w & 3) * (NTILE / 4);
    const int g    = lane >> 2;
    const int tg   = lane & 3;

    const int zm = blockIdx.z / KSPLIT;
    const int ks = blockIdx.z % KSPLIT;
    const __half* __restrict__ Asel = zm == 0 ? A0 : (zm == 1 ? A1 : A2);
    const __half* __restrict__ Bsel = zm == 0 ? B0 : (zm == 1 ? B1 : B2);
    void* __restrict__ Csel         = zm == 0 ? C0 : (zm == 1 ? C1 : C2);

    const int rowBase = blockIdx.y * 128;
    const int colBase = blockIdx.x * NTILE;
    const __half* __restrict__ Ag = Asel + (size_t)rowBase * 1024;
    const __half* __restrict__ Bg = Bsel + (size_t)colBase * 1024;
    const int Mrows = gridDim.y * 128;

    float acc[4][NI][4];
#pragma unroll
    for (int i = 0; i < 4; i++)
#pragma unroll
        for (int j = 0; j < NI; j++)
#pragma unroll
            for (int k = 0; k < 4; k++) acc[i][j][k] = 0.f;

    auto load_stage = [&](int chunk, int st) {
        const uint32_t dA = sb + st * STAGE_B;
        const uint32_t dB = dA + OPA_B;
        const int k0 = chunk * 64;
#pragma unroll
        for (int i = 0; i < 4; i++) {
            int idx = i * 256 + tid;
            int r = idx >> 3, c = idx & 7;
            cp_async16(dA + r * 144 + c * 16, Ag + (size_t)r * 1024 + k0 + c * 8);
        }
#pragma unroll
        for (int i = 0; i < NTILE / 32; i++) {
            int idx = i * 256 + tid;
            int r = idx >> 3, c = idx & 7;
            cp_async16(dB + r * 144 + c * 16, Bg + (size_t)r * 1024 + k0 + c * 8);
        }
        CP_COMMIT();
    };

    const uint32_t aoff = (uint32_t)((wm + (lane & 15)) * 144 + ((lane >> 4) << 4));
    const uint32_t boff = (uint32_t)((wn + ((lane >> 4) << 3) + (lane & 7)) * 144 +
                                     (((lane >> 3) & 1) << 4));

    auto compute = [&](int st) {
        const uint32_t ab = sb + st * STAGE_B + aoff;
        const uint32_t bb = sb + st * STAGE_B + OPA_B + boff;
#pragma unroll
        for (int kk = 0; kk < 4; kk++) {
            const uint32_t kb = kk * 32;
            uint32_t a[4][4], bq[NB][4];
#pragma unroll
            for (int mi = 0; mi < 4; mi++) ldsm_x4(a[mi], ab + mi * 2304 + kb);
#pragma unroll
            for (int nj = 0; nj < NB; nj++) ldsm_x4(bq[nj], bb + nj * 2304 + kb);
#pragma unroll
            for (int mi = 0; mi < 4; mi++)
#pragma unroll
                for (int ni = 0; ni < NI; ni++)
                    mma_f16(acc[mi][ni], a[mi], &bq[ni >> 1][(ni & 1) * 2]);
        }
    };

    load_stage(ks * CH + 0, 0);
    load_stage(ks * CH + 1, 1);
    load_stage(ks * CH + 2, 2);

#pragma unroll 1
    for (int c = 0; c < CH; c++) {
        CP_WAIT2();
        __syncthreads();
        if (c + 3 < CH) load_stage(ks * CH + c + 3, (c + 3) & 3);
        else CP_COMMIT();
        compute(c & 3);
    }

    // ---- epilogue ----
#pragma unroll
    for (int mi = 0; mi < 4; mi++) {
        const int row0 = rowBase + wm + mi * 16 + g;
        const int row1 = row0 + 8;
#pragma unroll
        for (int ni = 0; ni < NI; ni++) {
            const int col = colBase + wn + ni * 8 + tg * 2;
            float v0 = acc[mi][ni][0], v1 = acc[mi][ni][1];
            float v2 = acc[mi][ni][2], v3 = acc[mi][ni][3];
            if (EPI == 2) {
                const float* r0 = g_r + (size_t)(row0 >> 8) * 1024 + col;
                const float* r1 = g_r + (size_t)(row1 >> 8) * 1024 + col;
                float2 ra = *(const float2*)r0;
                float2 rb = *(const float2*)r1;
                float2 cc = *(const float2*)(g_c + col);
                *(float2*)((float*)Csel + (size_t)row0 * 1024 + col) =
                    make_float2(v0 + ra.x + cc.x, v1 + ra.y + cc.y);
                *(float2*)((float*)Csel + (size_t)row1 * 1024 + col) =
                    make_float2(v2 + rb.x + cc.x, v3 + rb.y + cc.y);
            } else if (EPI == 1) {
                float* Cf = (float*)Csel + (size_t)ks * Mrows * 1024;
                *(float2*)(Cf + (size_t)row0 * 1024 + col) = make_float2(v0, v1);
                *(float2*)(Cf + (size_t)row1 * 1024 + col) = make_float2(v2, v3);
            } else {
                *(__half2*)((__half*)Csel + (size_t)row0 * 1024 + col) =
                    __floats2half2_rn(v0, v1);
                *(__half2*)((__half*)Csel + (size_t)row1 * 1024 + col) =
                    __floats2half2_rn(v2, v3);
            }
        }
    }
}

// ---------------- fused prepass: Xsumh = h(x+pos), xbarh = h(mean_p(x+pos)) ----------------
__global__ void prepass_k(const float* __restrict__ x, const float* __restrict__ pos) {
    const int bt = blockIdx.y;
    const int t  = bt & 15;
    const int d  = (blockIdx.x * 256 + threadIdx.x) * 2;
    const float* xp = x   + (size_t)bt * PP * DD + d;
    const float* pp = pos + (size_t)t  * PP * DD + d;
    __half* op = g_Xsumh + (size_t)bt * PP * DD + d;
    float sx = 0.f, sy = 0.f;
#pragma unroll 4
    for (int p = 0; p < PP; p++) {
        float2 a = *(const float2*)(xp + (size_t)p * DD);
        float2 b = *(const float2*)(pp + (size_t)p * DD);
        float vx = a.x + b.x, vy = a.y + b.y;
        sx += vx; sy += vy;
        *(__half2*)(op + (size_t)p * DD) = __floats2half2_rn(vx, vy);
    }
    *(__half2*)(g_xbarh + (size_t)bt * DD + d) =
        __floats2half2_rn(sx * (1.0f / PP), sy * (1.0f / PP));
}

// ---------------- batched half copies: (W_out, Bm, A) ----------------
__global__ void h3_k(const float* __restrict__ w0, const float* __restrict__ w1,
                     const float* __restrict__ w2) {
    const float* in = blockIdx.y == 0 ? w0 : (blockIdx.y == 1 ? w1 : w2);
    __half* out = blockIdx.y == 0 ? g_WoutRh : (blockIdx.y == 1 ? g_BmRh : g_ARh);
    int i = (blockIdx.x * 256 + threadIdx.x) * 4;
    float4 v = *(const float4*)(in + i);
    *(__half2*)(out + i)     = __floats2half2_rn(v.x, v.y);
    *(__half2*)(out + i + 2) = __floats2half2_rn(v.z, v.w);
}

// ---------------- transpose fp32 -> half, 1024x1024 ----------------
__global__ void transpose_fh(const float* __restrict__ in, __half* __restrict__ out) {
    __shared__ float tile[32][33];
    int x = blockIdx.x * 32 + threadIdx.x;
    int y = blockIdx.y * 32 + threadIdx.y;
#pragma unroll
    for (int i = 0; i < 32; i += 8)
        tile[threadIdx.y + i][threadIdx.x] = in[(size_t)(y + i) * DD + x];
    __syncthreads();
    x = blockIdx.y * 32 + threadIdx.x;
    y = blockIdx.x * 32 + threadIdx.y;
#pragma unroll
    for (int i = 0; i < 32; i += 8)
        out[(size_t)(y + i) * DD + x] = __float2half_rn(tile[threadIdx.x][threadIdx.y + i]);
}

// ---------------- out[d] = sum_s Mrows[d][s]*v[s] (+ addv[d]) ----------------
__global__ void dotrows_k(const __half* __restrict__ Mrows, const float* __restrict__ v,
                          const float* __restrict__ addv, float* __restrict__ out) {
    __shared__ float red[256];
    const int d = blockIdx.x;
    const int tid = threadIdx.x;
    const __half* row = Mrows + (size_t)d * 1024;
    float s = 0.f;
    for (int j = tid; j < SS; j += 256) s += __half2float(row[j]) * v[j];
    red[tid] = s;
    __syncthreads();
    for (int o = 128; o > 0; o >>= 1) {
        if (tid < o) red[tid] += red[tid + o];
        __syncthreads();
    }
    if (tid == 0) out[d] = red[0] + (addv ? addv[d] : 0.f);
}

// ---------------- sum 4 split-K partials (+ optional row-vector of length 1024) ----------------
__global__ void sum4_k(const float* __restrict__ in, const float* __restrict__ addv,
                       float* __restrict__ out) {
    const int n = BT * 1024;
    int i = (blockIdx.x * 256 + threadIdx.x) * 4;
    float4 a = *(const float4*)(in + i);
    float4 b = *(const float4*)(in + n + i);
    float4 c = *(const float4*)(in + 2 * n + i);
    float4 d = *(const float4*)(in + 3 * n + i);
    float4 o;
    o.x = a.x + b.x + c.x + d.x; o.y = a.y + b.y + c.y + d.y;
    o.z = a.z + b.z + c.z + d.z; o.w = a.w + b.w + c.w + d.w;
    if (addv) {
        int col = i & 1023;
        float4 av = *(const float4*)(addv + col);
        o.x += av.x; o.y += av.y; o.z += av.z; o.w += av.w;
    }
    *(float4*)(out + i) = o;
}

// ---------------- scan ----------------
__global__ void scan_init_k(const float* __restrict__ init) {
    int s = blockIdx.x * 256 + threadIdx.x;
    float v = init[s];
#pragma unroll
    for (int b = 0; b < BB; b++) {
        g_states[(size_t)(b * 16) * SS + s] = v;
        g_statesh[(size_t)(b * 16) * SS + s] = __float2half_rn(v);
    }
}

__global__ void __launch_bounds__(256) scan_step_k(const float* __restrict__ Amat, int t) {
    __shared__ float st[BB][SS];
    __shared__ float red[BB][256];
    const int tid = threadIdx.x;
    for (int i = tid; i < BB * SS; i += 256) {
        int b = i >> 10, s = i & 1023;
        st[b][s] = g_states[(size_t)(b * 16 + t) * SS + s];
    }
    __syncthreads();
    const int col  = blockIdx.x * 16 + (tid & 15);
    const int part = tid >> 4;
    float acc[BB] = {};
    const int k0 = part * 64;
#pragma unroll 4
    for (int k = k0; k < k0 + 64; k++) {
        float av = Amat[(size_t)k * SS + col];
#pragma unroll
        for (int b = 0; b < BB; b++) acc[b] += st[b][k] * av;
    }
#pragma unroll
    for (int b = 0; b < BB; b++) red[b][tid] = acc[b];
    __syncthreads();
    for (int o = 8; o > 0; o >>= 1) {
        if (part < o) {
#pragma unroll
            for (int b = 0; b < BB; b++) red[b][tid] += red[b][tid + (o << 4)];
        }
        __syncthreads();
    }
    if (part == 0) {
#pragma unroll
        for (int b = 0; b < BB; b++) {
            float v = red[b][tid] + g_q[(size_t)(b * 16 + t) * SS + col];
            g_states[(size_t)(b * 16 + t + 1) * SS + col] = v;
            g_statesh[(size_t)(b * 16 + t + 1) * SS + col] = __float2half_rn(v);
        }
    }
}

// ---------------- host ----------------
extern "C" void kernel_launch(void* const* d_in, const int* in_sizes, int n_in,
                              void* d_out, int out_size) {
    const float* x     = (const float*)d_in[0];
    const float* pos   = (const float*)d_in[1];
    const float* W_in  = (const float*)d_in[2];
    const float* b_in  = (const float*)d_in[3];
    const float* W_out = (const float*)d_in[4];
    const float* b_out = (const float*)d_in[5];
    const float* Amat  = (const float*)d_in[6];
    const float* Bm    = (const float*)d_in[7];
    const float* init  = (const float*)d_in[8];
    float* out = (float*)d_out;

    __half *WoutRh, *BmRh, *ARh, *WinTRh, *BmTh, *Hth, *Gth, *MqTh, *MwTh, *Xsumh, *xbarh, *statesh;
    float *qp, *rp, *q, *r, *c, *bq, *states;
    cudaGetSymbolAddress((void**)&WoutRh, g_WoutRh);
    cudaGetSymbolAddress((void**)&BmRh,   g_BmRh);
    cudaGetSymbolAddress((void**)&ARh,    g_ARh);
    cudaGetSymbolAddress((void**)&WinTRh, g_WinTRh);
    cudaGetSymbolAddress((void**)&BmTh,   g_BmTh);
    cudaGetSymbolAddress((void**)&Hth,    g_Hth);
    cudaGetSymbolAddress((void**)&Gth,    g_Gth);
    cudaGetSymbolAddress((void**)&MqTh,   g_MqTh);
    cudaGetSymbolAddress((void**)&MwTh,   g_MwTh);
    cudaGetSymbolAddress((void**)&Xsumh,  g_Xsumh);
    cudaGetSymbolAddress((void**)&xbarh,  g_xbarh);
    cudaGetSymbolAddress((void**)&statesh,g_statesh);
    cudaGetSymbolAddress((void**)&qp,     g_qp);
    cudaGetSymbolAddress((void**)&rp,     g_rp);
    cudaGetSymbolAddress((void**)&q,      g_q);
    cudaGetSymbolAddress((void**)&r,      g_r);
    cudaGetSymbolAddress((void**)&c,      g_c);
    cudaGetSymbolAddress((void**)&bq,     g_bq);
    cudaGetSymbolAddress((void**)&states, g_states);

    const int SM128 = 4 * (128 + 128) * 144;
    const int SM256 = 4 * (128 + 256) * 144;
    cudaFuncSetAttribute((const void*)f16g<128, 0, 1>,
                         cudaFuncAttributeMaxDynamicSharedMemorySize, SM128);
    cudaFuncSetAttribute((const void*)f16g<256, 1, 4>,
                         cudaFuncAttributeMaxDynamicSharedMemorySize, SM256);
    cudaFuncSetAttribute((const void*)f16g<256, 0, 1>,
                         cudaFuncAttributeMaxDynamicSharedMemorySize, SM256);
    cudaFuncSetAttribute((const void*)f16g<256, 2, 1>,
                         cudaFuncAttributeMaxDynamicSharedMemorySize, SM256);

    // prepass: Xsumh, xbarh
    prepass_k<<<dim3(2, BT), 256>>>(x, pos);

    // weight prep
    transpose_fh<<<dim3(32, 32), dim3(32, 8)>>>(W_in, WinTRh);
    transpose_fh<<<dim3(32, 32), dim3(32, 8)>>>(Bm,   BmTh);
    h3_k<<<dim3(1024, 3), 256>>>(W_out, Bm, Amat);

    // batched precompute (128x128 tiles, 192 CTAs):
    //   Hth = WoutRh@BmRh^T, Gth = WoutRh@ARh^T, MqTh = BmTh@WinTRh^T
    f16g<128, 0, 1><<<dim3(8, 8, 3), 256, SM128>>>(
        WoutRh, WoutRh, BmTh, BmRh, ARh, WinTRh, Hth, Gth, MqTh);

    // MwTh = Hth @ WinTRh^T  (256-tile, 32 CTAs — stays 1 wave)
    f16g<256, 0, 1><<<dim3(4, 8, 1), 256, SM256>>>(
        Hth, nullptr, nullptr, WinTRh, nullptr, nullptr, MwTh, nullptr, nullptr);

    // c = b_in@H + b_out ; bq = b_in@Bm
    dotrows_k<<<1024, 256>>>(Hth, b_in, b_out, c);
    dotrows_k<<<1024, 256>>>(BmTh, b_in, nullptr, bq);

    // q partials = xbarh @ MqTh^T (split-K 4), then q = sum + bq
    f16g<256, 1, 4><<<dim3(4, 1, 4), 256, SM256>>>(
        xbarh, nullptr, nullptr, MqTh, nullptr, nullptr, qp, nullptr, nullptr);
    sum4_k<<<128, 256>>>(qp, bq, q);

    // scan
    scan_init_k<<<4, 256>>>(init);
    for (int t = 0; t < 15; t++) scan_step_k<<<64, 256>>>(Amat, t);

    // r partials = statesh @ Gth^T (split-K 4), then r = sum
    f16g<256, 1, 4><<<dim3(4, 1, 4), 256, SM256>>>(
        statesh, nullptr, nullptr, Gth, nullptr, nullptr, rp, nullptr, nullptr);
    sum4_k<<<128, 256>>>(rp, nullptr, r);

    // main GEMM: out = Xsumh @ MwTh^T + r + c
    f16g<256, 2, 1><<<dim3(4, 256, 1), 256, SM256>>>(
        Xsumh, nullptr, nullptr, MwTh, nullptr, nullptr, out, nullptr, nullptr);
}

// round 9
// speedup vs baseline: 4.8394x; 1.0469x over previous
#include <cuda_runtime.h>
#include <cuda_fp16.h>
#include <cstdint>

#define DD   1024
#define SS   1024
#define TT   16
#define PP   256
#define BB   8
#define BT   128
#define MROWS 32768

// ---------------- device scratch ----------------
__device__ __half g_WoutRh[DD*SS];
__device__ __half g_BmRh [SS*SS];
__device__ __half g_ARh  [SS*SS];
__device__ __half g_WinTRh[DD*SS];
__device__ __half g_BmTh [SS*SS];
__device__ __half g_Hth  [DD*SS];
__device__ __half g_Gth  [DD*SS];
__device__ __half g_MqTh [SS*DD];
__device__ __half g_MwTh [DD*DD];
__device__ __half g_Xsumh[(size_t)MROWS*DD];
__device__ __half g_xbarh[BT*DD];
__device__ __half g_statesh[BT*SS];
__device__ float g_qp  [4*BT*SS];
__device__ float g_rp  [4*BT*DD];
__device__ float g_q   [BT*SS];
__device__ float g_states[BT*SS];
__device__ float g_r   [BT*DD];
__device__ float g_c   [DD];
__device__ float g_bq  [SS];

// ---------------- helpers ----------------
__device__ __forceinline__ uint32_t smem_u32(const void* p) {
    uint32_t a;
    asm("{ .reg .u64 t; cvta.to.shared.u64 t, %1; cvt.u32.u64 %0, t; }" : "=r"(a) : "l"(p));
    return a;
}
__device__ __forceinline__ void cp_async16(uint32_t dst, const void* src) {
    asm volatile("cp.async.cg.shared.global [%0], [%1], 16;" :: "r"(dst), "l"(src) : "memory");
}
#define CP_COMMIT() asm volatile("cp.async.commit_group;" ::: "memory")
#define CP_WAIT2()  asm volatile("cp.async.wait_group 2;" ::: "memory")

__device__ __forceinline__ void ldsm_x4(uint32_t* r, uint32_t addr) {
    asm volatile("ldmatrix.sync.aligned.m8n8.x4.shared.b16 {%0,%1,%2,%3}, [%4];"
        : "=r"(r[0]), "=r"(r[1]), "=r"(r[2]), "=r"(r[3]) : "r"(addr));
}
__device__ __forceinline__ void mma_f16(float* d, const uint32_t* a, const uint32_t* b) {
    asm volatile(
        "mma.sync.aligned.m16n8k16.row.col.f32.f16.f16.f32 "
        "{%0,%1,%2,%3}, {%4,%5,%6,%7}, {%8,%9}, {%0,%1,%2,%3};"
        : "+f"(d[0]), "+f"(d[1]), "+f"(d[2]), "+f"(d[3])
        : "r"(a[0]), "r"(a[1]), "r"(a[2]), "r"(a[3]), "r"(b[0]), "r"(b[1]));
}

// ================= fp16 NT GEMM: C = A[M,K] @ Bt[N,K]^T, fp32 accum =================
// EPI: 0 = write half; 1 = write float (split-K partial layout).
template <int NTILE, int EPI, int KSPLIT>
__global__ void __launch_bounds__(256, 1) f16g(
    const __half* __restrict__ A0, const __half* __restrict__ A1, const __half* __restrict__ A2,
    const __half* __restrict__ B0, const __half* __restrict__ B1, const __half* __restrict__ B2,
    void* __restrict__ C0, void* __restrict__ C1, void* __restrict__ C2)
{
    constexpr int NI  = NTILE / 32;
    constexpr int NB  = NTILE / 64;
    constexpr uint32_t OPA_B = 128u * 144u;
    constexpr uint32_t STAGE_B = (128u + NTILE) * 144u;
    constexpr int CH = 16 / KSPLIT;

    extern __shared__ char smem[];
    const uint32_t sb = smem_u32(smem);

    const int tid  = threadIdx.x;
    const int lane = tid & 31;
    const int w    = tid >> 5;
    const int wm   = (w >> 2) * 64;
    const int wn   = (w & 3) * (NTILE / 4);
    const int g    = lane >> 2;
    const int tg   = lane & 3;

    const int zm = blockIdx.z / KSPLIT;
    const int ks = blockIdx.z % KSPLIT;
    const __half* __restrict__ Asel = zm == 0 ? A0 : (zm == 1 ? A1 : A2);
    const __half* __restrict__ Bsel = zm == 0 ? B0 : (zm == 1 ? B1 : B2);
    void* __restrict__ Csel         = zm == 0 ? C0 : (zm == 1 ? C1 : C2);

    const int rowBase = blockIdx.y * 128;
    const int colBase = blockIdx.x * NTILE;
    const __half* __restrict__ Ag = Asel + (size_t)rowBase * 1024;
    const __half* __restrict__ Bg = Bsel + (size_t)colBase * 1024;
    const int Mrows = gridDim.y * 128;

    float acc[4][NI][4];
#pragma unroll
    for (int i = 0; i < 4; i++)
#pragma unroll
        for (int j = 0; j < NI; j++)
#pragma unroll
            for (int k = 0; k < 4; k++) acc[i][j][k] = 0.f;

    auto load_stage = [&](int chunk, int st) {
        const uint32_t dA = sb + st * STAGE_B;
        const uint32_t dB = dA + OPA_B;
        const int k0 = chunk * 64;
#pragma unroll
        for (int i = 0; i < 4; i++) {
            int idx = i * 256 + tid;
            int r = idx >> 3, c = idx & 7;
            cp_async16(dA + r * 144 + c * 16, Ag + (size_t)r * 1024 + k0 + c * 8);
        }
#pragma unroll
        for (int i = 0; i < NTILE / 32; i++) {
            int idx = i * 256 + tid;
            int r = idx >> 3, c = idx & 7;
            cp_async16(dB + r * 144 + c * 16, Bg + (size_t)r * 1024 + k0 + c * 8);
        }
        CP_COMMIT();
    };

    const uint32_t aoff = (uint32_t)((wm + (lane & 15)) * 144 + ((lane >> 4) << 4));
    const uint32_t boff = (uint32_t)((wn + ((lane >> 4) << 3) + (lane & 7)) * 144 +
                                     (((lane >> 3) & 1) << 4));

    auto compute = [&](int st) {
        const uint32_t ab = sb + st * STAGE_B + aoff;
        const uint32_t bb = sb + st * STAGE_B + OPA_B + boff;
#pragma unroll
        for (int kk = 0; kk < 4; kk++) {
            const uint32_t kb = kk * 32;
            uint32_t a[4][4], bq[NB][4];
#pragma unroll
            for (int mi = 0; mi < 4; mi++) ldsm_x4(a[mi], ab + mi * 2304 + kb);
#pragma unroll
            for (int nj = 0; nj < NB; nj++) ldsm_x4(bq[nj], bb + nj * 2304 + kb);
#pragma unroll
            for (int mi = 0; mi < 4; mi++)
#pragma unroll
                for (int ni = 0; ni < NI; ni++)
                    mma_f16(acc[mi][ni], a[mi], &bq[ni >> 1][(ni & 1) * 2]);
        }
    };

    load_stage(ks * CH + 0, 0);
    load_stage(ks * CH + 1, 1);
    load_stage(ks * CH + 2, 2);

#pragma unroll 1
    for (int c = 0; c < CH; c++) {
        CP_WAIT2();
        __syncthreads();
        if (c + 3 < CH) load_stage(ks * CH + c + 3, (c + 3) & 3);
        else CP_COMMIT();
        compute(c & 3);
    }

#pragma unroll
    for (int mi = 0; mi < 4; mi++) {
        const int row0 = rowBase + wm + mi * 16 + g;
        const int row1 = row0 + 8;
#pragma unroll
        for (int ni = 0; ni < NI; ni++) {
            const int col = colBase + wn + ni * 8 + tg * 2;
            float v0 = acc[mi][ni][0], v1 = acc[mi][ni][1];
            float v2 = acc[mi][ni][2], v3 = acc[mi][ni][3];
            if (EPI == 1) {
                float* Cf = (float*)Csel + (size_t)ks * Mrows * 1024;
                *(float2*)(Cf + (size_t)row0 * 1024 + col) = make_float2(v0, v1);
                *(float2*)(Cf + (size_t)row1 * 1024 + col) = make_float2(v2, v3);
            } else {
                *(__half2*)((__half*)Csel + (size_t)row0 * 1024 + col) =
                    __floats2half2_rn(v0, v1);
                *(__half2*)((__half*)Csel + (size_t)row1 * 1024 + col) =
                    __floats2half2_rn(v2, v3);
            }
        }
    }
}

// ---------------- prepass: Xsumh = h(x+pos), xbarh = h(mean_p(x+pos)) ----------------
__global__ void prepass_k(const float* __restrict__ x, const float* __restrict__ pos) {
    const int bt = blockIdx.y;
    const int t  = bt & 15;
    const int d  = (blockIdx.x * 256 + threadIdx.x) * 2;
    const float* xp = x   + (size_t)bt * PP * DD + d;
    const float* pp = pos + (size_t)t  * PP * DD + d;
    __half* op = g_Xsumh + (size_t)bt * PP * DD + d;
    float sx = 0.f, sy = 0.f;
#pragma unroll 4
    for (int p = 0; p < PP; p++) {
        float2 a = *(const float2*)(xp + (size_t)p * DD);
        float2 b = *(const float2*)(pp + (size_t)p * DD);
        float vx = a.x + b.x, vy = a.y + b.y;
        sx += vx; sy += vy;
        *(__half2*)(op + (size_t)p * DD) = __floats2half2_rn(vx, vy);
    }
    *(__half2*)(g_xbarh + (size_t)bt * DD + d) =
        __floats2half2_rn(sx * (1.0f / PP), sy * (1.0f / PP));
}

// ---------------- merged weight prep: 2 transposes + 3 converts ----------------
__global__ void wprep_k(const float* __restrict__ W_in, const float* __restrict__ Bm,
                        const float* __restrict__ W_out, const float* __restrict__ Amat) {
    const int z = blockIdx.z;
    if (z < 2) {
        __shared__ float tile[32][33];
        const float* in = z ? Bm : W_in;
        __half* out = z ? g_BmTh : g_WinTRh;
        int x = blockIdx.x * 32 + threadIdx.x;
        int y = blockIdx.y * 32 + threadIdx.y;
#pragma unroll
        for (int i = 0; i < 32; i += 8)
            tile[threadIdx.y + i][threadIdx.x] = in[(size_t)(y + i) * DD + x];
        __syncthreads();
        x = blockIdx.y * 32 + threadIdx.x;
        y = blockIdx.x * 32 + threadIdx.y;
#pragma unroll
        for (int i = 0; i < 32; i += 8)
            out[(size_t)(y + i) * DD + x] =
                __float2half_rn(tile[threadIdx.x][threadIdx.y + i]);
    } else {
        const float* in = z == 2 ? W_out : (z == 3 ? Bm : Amat);
        __half* out = z == 2 ? g_WoutRh : (z == 3 ? g_BmRh : g_ARh);
        int x = blockIdx.x * 32 + threadIdx.x;
        int y = blockIdx.y * 32 + threadIdx.y;
#pragma unroll
        for (int i = 0; i < 32; i += 8)
            out[(size_t)(y + i) * DD + x] = __float2half_rn(in[(size_t)(y + i) * DD + x]);
    }
}

// ---------------- c[d] = Hth[d]·b_in + b_out[d] ; bq[d] = BmTh[d]·b_in ----------------
__global__ void dotrows2_k(const float* __restrict__ b_in, const float* __restrict__ b_out) {
    __shared__ float red[256];
    const int which = blockIdx.x >> 10;
    const int d = blockIdx.x & 1023;
    const int tid = threadIdx.x;
    const __half* row = (which ? g_BmTh : g_Hth) + (size_t)d * 1024;
    float s = 0.f;
    for (int j = tid; j < SS; j += 256) s += __half2float(row[j]) * b_in[j];
    red[tid] = s;
    __syncthreads();
    for (int o = 128; o > 0; o >>= 1) {
        if (tid < o) red[tid] += red[tid + o];
        __syncthreads();
    }
    if (tid == 0) {
        if (which) g_bq[d] = red[0];
        else       g_c[d]  = red[0] + b_out[d];
    }
}

// ---------------- sum 4 split-K partials (+ optional row-vector) ----------------
__global__ void sum4_k(const float* __restrict__ in, const float* __restrict__ addv,
                       float* __restrict__ out) {
    const int n = BT * 1024;
    int i = (blockIdx.x * 256 + threadIdx.x) * 4;
    float4 a = *(const float4*)(in + i);
    float4 b = *(const float4*)(in + n + i);
    float4 c = *(const float4*)(in + 2 * n + i);
    float4 d = *(const float4*)(in + 3 * n + i);
    float4 o;
    o.x = a.x + b.x + c.x + d.x; o.y = a.y + b.y + c.y + d.y;
    o.z = a.z + b.z + c.z + d.z; o.w = a.w + b.w + c.w + d.w;
    if (addv) {
        int col = i & 1023;
        float4 av = *(const float4*)(addv + col);
        o.x += av.x; o.y += av.y; o.z += av.z; o.w += av.w;
    }
    *(float4*)(out + i) = o;
}

// ---------------- epilogue join: out += r[bt] + c ----------------
__global__ void addrc_k(float* __restrict__ out) {
    size_t i = ((size_t)blockIdx.x * 256 + threadIdx.x) * 4;
    const int col = (int)(i & 1023);
    const int bt  = (int)(i >> 18);
    float4 v  = *(float4*)(out + i);
    float4 rv = *(const float4*)(g_r + (size_t)bt * 1024 + col);
    float4 cv = *(const float4*)(g_c + col);
    v.x += rv.x + cv.x; v.y += rv.y + cv.y;
    v.z += rv.z + cv.z; v.w += rv.w + cv.w;
    *(float4*)(out + i) = v;
}

// ---------------- scan ----------------
__global__ void scan_init_k(const float* __restrict__ init) {
    int s = blockIdx.x * 256 + threadIdx.x;
    float v = init[s];
#pragma unroll
    for (int b = 0; b < BB; b++) {
        g_states[(size_t)(b * 16) * SS + s] = v;
        g_statesh[(size_t)(b * 16) * SS + s] = __float2half_rn(v);
    }
}

__global__ void __launch_bounds__(256) scan_step_k(const float* __restrict__ Amat, int t) {
    __shared__ float st[BB][SS];
    __shared__ float red[BB][256];
    const int tid = threadIdx.x;
    for (int i = tid; i < BB * SS; i += 256) {
        int b = i >> 10, s = i & 1023;
        st[b][s] = g_states[(size_t)(b * 16 + t) * SS + s];
    }
    __syncthreads();
    const int col  = blockIdx.x * 16 + (tid & 15);
    const int part = tid >> 4;
    float acc[BB] = {};
    const int k0 = part * 64;
#pragma unroll 4
    for (int k = k0; k < k0 + 64; k++) {
        float av = Amat[(size_t)k * SS + col];
#pragma unroll
        for (int b = 0; b < BB; b++) acc[b] += st[b][k] * av;
    }
#pragma unroll
    for (int b = 0; b < BB; b++) red[b][tid] = acc[b];
    __syncthreads();
    for (int o = 8; o > 0; o >>= 1) {
        if (part < o) {
#pragma unroll
            for (int b = 0; b < BB; b++) red[b][tid] += red[b][tid + (o << 4)];
        }
        __syncthreads();
    }
    if (part == 0) {
#pragma unroll
        for (int b = 0; b < BB; b++) {
            float v = red[b][tid] + g_q[(size_t)(b * 16 + t) * SS + col];
            g_states[(size_t)(b * 16 + t + 1) * SS + col] = v;
            g_statesh[(size_t)(b * 16 + t + 1) * SS + col] = __float2half_rn(v);
        }
    }
}

// ---------------- host ----------------
extern "C" void kernel_launch(void* const* d_in, const int* in_sizes, int n_in,
                              void* d_out, int out_size) {
    const float* x     = (const float*)d_in[0];
    const float* pos   = (const float*)d_in[1];
    const float* W_in  = (const float*)d_in[2];
    const float* b_in  = (const float*)d_in[3];
    const float* W_out = (const float*)d_in[4];
    const float* b_out = (const float*)d_in[5];
    const float* Amat  = (const float*)d_in[6];
    const float* Bm    = (const float*)d_in[7];
    const float* init  = (const float*)d_in[8];
    float* out = (float*)d_out;

    __half *WoutRh, *BmRh, *ARh, *WinTRh, *BmTh, *Hth, *Gth, *MqTh, *MwTh, *Xsumh, *xbarh, *statesh;
    float *qp, *rp, *q, *r;
    cudaGetSymbolAddress((void**)&WoutRh, g_WoutRh);
    cudaGetSymbolAddress((void**)&BmRh,   g_BmRh);
    cudaGetSymbolAddress((void**)&ARh,    g_ARh);
    cudaGetSymbolAddress((void**)&WinTRh, g_WinTRh);
    cudaGetSymbolAddress((void**)&BmTh,   g_BmTh);
    cudaGetSymbolAddress((void**)&Hth,    g_Hth);
    cudaGetSymbolAddress((void**)&Gth,    g_Gth);
    cudaGetSymbolAddress((void**)&MqTh,   g_MqTh);
    cudaGetSymbolAddress((void**)&MwTh,   g_MwTh);
    cudaGetSymbolAddress((void**)&Xsumh,  g_Xsumh);
    cudaGetSymbolAddress((void**)&xbarh,  g_xbarh);
    cudaGetSymbolAddress((void**)&statesh,g_statesh);
    cudaGetSymbolAddress((void**)&qp,     g_qp);
    cudaGetSymbolAddress((void**)&rp,     g_rp);
    cudaGetSymbolAddress((void**)&q,      g_q);
    cudaGetSymbolAddress((void**)&r,      g_r);
    float *bqv;
    cudaGetSymbolAddress((void**)&bqv, g_bq);

    const int SM128 = 4 * (128 + 128) * 144;
    const int SM256 = 4 * (128 + 256) * 144;

    static bool s_init = false;
    static cudaStream_t s2 = 0;
    static cudaEvent_t e0, eP, eW, eR;
    if (!s_init) {
        if (cudaStreamCreateWithFlags(&s2, cudaStreamNonBlocking) != cudaSuccess) s2 = 0;
        cudaEventCreateWithFlags(&e0, cudaEventDisableTiming);
        cudaEventCreateWithFlags(&eP, cudaEventDisableTiming);
        cudaEventCreateWithFlags(&eW, cudaEventDisableTiming);
        cudaEventCreateWithFlags(&eR, cudaEventDisableTiming);
        cudaFuncSetAttribute((const void*)f16g<128, 0, 1>,
                             cudaFuncAttributeMaxDynamicSharedMemorySize, SM128);
        cudaFuncSetAttribute((const void*)f16g<256, 1, 4>,
                             cudaFuncAttributeMaxDynamicSharedMemorySize, SM256);
        cudaFuncSetAttribute((const void*)f16g<256, 1, 1>,
                             cudaFuncAttributeMaxDynamicSharedMemorySize, SM256);
        s_init = true;
    }

    // ---- fork ----
    cudaEventRecord(e0, 0);
    // default stream: prepass (Xsumh + xbarh)
    prepass_k<<<dim3(2, BT), 256>>>(x, pos);
    cudaEventRecord(eP, 0);

    // side stream: weight prep + precompute + q/scan/r chain
    cudaStreamWaitEvent(s2, e0, 0);
    wprep_k<<<dim3(32, 32, 5), dim3(32, 8), 0, s2>>>(W_in, Bm, W_out, Amat);
    // Hth = WoutRh@BmRh^T, Gth = WoutRh@ARh^T, MqTh = BmTh@WinTRh^T
    f16g<128, 0, 1><<<dim3(8, 8, 3), 256, SM128, s2>>>(
        WoutRh, WoutRh, BmTh, BmRh, ARh, WinTRh, Hth, Gth, MqTh);
    // MwTh = Hth @ WinTRh^T
    f16g<128, 0, 1><<<dim3(8, 8, 1), 256, SM128, s2>>>(
        Hth, nullptr, nullptr, WinTRh, nullptr, nullptr, MwTh, nullptr, nullptr);
    cudaEventRecord(eW, s2);

    dotrows2_k<<<2048, 256, 0, s2>>>(b_in, b_out);
    cudaStreamWaitEvent(s2, eP, 0);
    // q = xbarh @ MqTh^T (split-K 4) + bq
    f16g<256, 1, 4><<<dim3(4, 1, 4), 256, SM256, s2>>>(
        xbarh, nullptr, nullptr, MqTh, nullptr, nullptr, qp, nullptr, nullptr);
    sum4_k<<<128, 256, 0, s2>>>(qp, bqv, q);
    scan_init_k<<<4, 256, 0, s2>>>(init);
    for (int t = 0; t < 15; t++) scan_step_k<<<64, 256, 0, s2>>>(Amat, t);
    // r = statesh @ Gth^T (split-K 4)
    f16g<256, 1, 4><<<dim3(4, 1, 4), 256, SM256, s2>>>(
        statesh, nullptr, nullptr, Gth, nullptr, nullptr, rp, nullptr, nullptr);
    sum4_k<<<128, 256, 0, s2>>>(rp, nullptr, r);
    cudaEventRecord(eR, s2);

    // ---- default stream: main GEMM raw, then join + epilogue add ----
    cudaStreamWaitEvent(0, eW, 0);
    f16g<256, 1, 1><<<dim3(4, 256, 1), 256, SM256>>>(
        Xsumh, nullptr, nullptr, MwTh, nullptr, nullptr, out, nullptr, nullptr);
    cudaStreamWaitEvent(0, eR, 0);
    addrc_k<<<32768, 256>>>(out);
}

// round 11
// speedup vs baseline: 5.3933x; 1.1144x over previous
#include <cuda_runtime.h>
#include <cuda_fp16.h>
#include <cstdint>

#define DD   1024
#define SS   1024
#define TT   16
#define PP   256
#define BB   8
#define BT   128
#define MROWS 32768

// ---------------- device scratch ----------------
__device__ __half g_WoutRh[DD*SS];
__device__ __half g_BmRh [SS*SS];
__device__ __half g_ARh  [SS*SS];
__device__ __half g_WinTRh[DD*SS];
__device__ __half g_BmTh [SS*SS];
__device__ __half g_Hth  [DD*SS];
__device__ __half g_Gth  [DD*SS];
__device__ __half g_MqTh [SS*DD];
__device__ __half g_MwTh [DD*DD];
__device__ __half g_Xsumh[(size_t)MROWS*DD];
__device__ __half g_xbarh[BT*DD];
__device__ __half g_statesh[BT*SS];
__device__ float g_xbarp[4*BT*DD];
__device__ float g_qp  [4*BT*SS];
__device__ float g_rp  [4*BT*DD];
__device__ float g_q   [BT*SS];
__device__ float g_states[BT*SS];
__device__ float g_r   [BT*DD];
__device__ float g_c   [DD];
__device__ float g_bq  [SS];

// ---------------- helpers ----------------
__device__ __forceinline__ uint32_t smem_u32(const void* p) {
    uint32_t a;
    asm("{ .reg .u64 t; cvta.to.shared.u64 t, %1; cvt.u32.u64 %0, t; }" : "=r"(a) : "l"(p));
    return a;
}
__device__ __forceinline__ void cp_async16(uint32_t dst, const void* src) {
    asm volatile("cp.async.cg.shared.global [%0], [%1], 16;" :: "r"(dst), "l"(src) : "memory");
}
#define CP_COMMIT() asm volatile("cp.async.commit_group;" ::: "memory")
#define CP_WAIT1()  asm volatile("cp.async.wait_group 1;" ::: "memory")

__device__ __forceinline__ void ldsm_x4(uint32_t* r, uint32_t addr) {
    asm volatile("ldmatrix.sync.aligned.m8n8.x4.shared.b16 {%0,%1,%2,%3}, [%4];"
        : "=r"(r[0]), "=r"(r[1]), "=r"(r[2]), "=r"(r[3]) : "r"(addr));
}
__device__ __forceinline__ void mma_f16(float* d, const uint32_t* a, const uint32_t* b) {
    asm volatile(
        "mma.sync.aligned.m16n8k16.row.col.f32.f16.f16.f32 "
        "{%0,%1,%2,%3}, {%4,%5,%6,%7}, {%8,%9}, {%0,%1,%2,%3};"
        : "+f"(d[0]), "+f"(d[1]), "+f"(d[2]), "+f"(d[3])
        : "r"(a[0]), "r"(a[1]), "r"(a[2]), "r"(a[3]), "r"(b[0]), "r"(b[1]));
}

// ================= fp16 NT GEMM: C = A[M,K] @ Bt[N,K]^T, fp32 accum =================
// CTA tile 128x128, 128 threads = 4 warps (2m x 2n), warp tile 64x64, 3-stage
// pipeline (2 chunks in flight), 2 CTAs/SM.
// EPI: 0 = half; 1 = float split-K partial; 2 = float + g_r[bt] + g_c.
#define OPA_B   18432u              // 128 rows * 144B
#define STAGE_B 36864u              // 256 rows * 144B
#define GEMM_SM (3 * 36864)

template <int EPI, int KSPLIT>
__global__ void __launch_bounds__(128, 2) f16g(
    const __half* __restrict__ A0, const __half* __restrict__ A1, const __half* __restrict__ A2,
    const __half* __restrict__ B0, const __half* __restrict__ B1, const __half* __restrict__ B2,
    void* __restrict__ C0, void* __restrict__ C1, void* __restrict__ C2)
{
    constexpr int CH = 16 / KSPLIT;

    extern __shared__ char smem[];
    const uint32_t sb = smem_u32(smem);

    const int tid  = threadIdx.x;
    const int lane = tid & 31;
    const int w    = tid >> 5;
    const int wm   = (w >> 1) * 64;
    const int wn   = (w & 1) * 64;
    const int g    = lane >> 2;
    const int tg   = lane & 3;

    const int zm = blockIdx.z / KSPLIT;
    const int ks = blockIdx.z % KSPLIT;
    const __half* __restrict__ Asel = zm == 0 ? A0 : (zm == 1 ? A1 : A2);
    const __half* __restrict__ Bsel = zm == 0 ? B0 : (zm == 1 ? B1 : B2);
    void* __restrict__ Csel         = zm == 0 ? C0 : (zm == 1 ? C1 : C2);

    const int rowBase = blockIdx.y * 128;
    const int colBase = blockIdx.x * 128;
    const __half* __restrict__ Ag = Asel + (size_t)rowBase * 1024;
    const __half* __restrict__ Bg = Bsel + (size_t)colBase * 1024;
    const int Mrows = gridDim.y * 128;

    float acc[4][8][4];
#pragma unroll
    for (int i = 0; i < 4; i++)
#pragma unroll
        for (int j = 0; j < 8; j++)
#pragma unroll
            for (int k = 0; k < 4; k++) acc[i][j][k] = 0.f;

    auto load_stage = [&](int chunk, int st) {
        const uint32_t dA = sb + st * STAGE_B;
        const uint32_t dB = dA + OPA_B;
        const int k0 = chunk * 64;
#pragma unroll
        for (int i = 0; i < 8; i++) {
            int idx = i * 128 + tid;
            int r = idx >> 3, c = idx & 7;
            cp_async16(dA + r * 144 + c * 16, Ag + (size_t)r * 1024 + k0 + c * 8);
        }
#pragma unroll
        for (int i = 0; i < 8; i++) {
            int idx = i * 128 + tid;
            int r = idx >> 3, c = idx & 7;
            cp_async16(dB + r * 144 + c * 16, Bg + (size_t)r * 1024 + k0 + c * 8);
        }
        CP_COMMIT();
    };

    const uint32_t aoff = (uint32_t)((wm + (lane & 15)) * 144 + ((lane >> 4) << 4));
    const uint32_t boff = (uint32_t)((wn + ((lane >> 4) << 3) + (lane & 7)) * 144 +
                                     (((lane >> 3) & 1) << 4));

    auto compute = [&](int st) {
        const uint32_t ab = sb + st * STAGE_B + aoff;
        const uint32_t bb = sb + st * STAGE_B + OPA_B + boff;
#pragma unroll
        for (int kk = 0; kk < 4; kk++) {
            const uint32_t kb = kk * 32;
            uint32_t a[4][4], bq[4][4];
#pragma unroll
            for (int mi = 0; mi < 4; mi++) ldsm_x4(a[mi], ab + mi * 2304 + kb);
#pragma unroll
            for (int nj = 0; nj < 4; nj++) ldsm_x4(bq[nj], bb + nj * 2304 + kb);
#pragma unroll
            for (int mi = 0; mi < 4; mi++)
#pragma unroll
                for (int ni = 0; ni < 8; ni++)
                    mma_f16(acc[mi][ni], a[mi], &bq[ni >> 1][(ni & 1) * 2]);
        }
    };

    // prologue: 2 chunks in flight
    load_stage(ks * CH + 0, 0);
    load_stage(ks * CH + 1, 1);

    int st = 0;     // stage of chunk c
#pragma unroll 1
    for (int c = 0; c < CH; c++) {
        CP_WAIT1();                  // chunk c landed (<=1 group pending)
        __syncthreads();             // all warps done with stage (c-1)%3
        if (c + 2 < CH) {
            int nst = st + 2; if (nst >= 3) nst -= 3;   // == (c-1)%3, now free
            load_stage(ks * CH + c + 2, nst);
        } else {
            CP_COMMIT();             // empty group keeps wait accounting exact
        }
        compute(st);
        if (++st == 3) st = 0;
    }

#pragma unroll
    for (int mi = 0; mi < 4; mi++) {
        const int row0 = rowBase + wm + mi * 16 + g;
        const int row1 = row0 + 8;
#pragma unroll
        for (int ni = 0; ni < 8; ni++) {
            const int col = colBase + wn + ni * 8 + tg * 2;
            float v0 = acc[mi][ni][0], v1 = acc[mi][ni][1];
            float v2 = acc[mi][ni][2], v3 = acc[mi][ni][3];
            if (EPI == 2) {
                float2 ra = *(const float2*)(g_r + (size_t)(row0 >> 8) * 1024 + col);
                float2 rb = *(const float2*)(g_r + (size_t)(row1 >> 8) * 1024 + col);
                float2 cc = *(const float2*)(g_c + col);
                *(float2*)((float*)Csel + (size_t)row0 * 1024 + col) =
                    make_float2(v0 + ra.x + cc.x, v1 + ra.y + cc.y);
                *(float2*)((float*)Csel + (size_t)row1 * 1024 + col) =
                    make_float2(v2 + rb.x + cc.x, v3 + rb.y + cc.y);
            } else if (EPI == 1) {
                float* Cf = (float*)Csel + (size_t)ks * Mrows * 1024;
                *(float2*)(Cf + (size_t)row0 * 1024 + col) = make_float2(v0, v1);
                *(float2*)(Cf + (size_t)row1 * 1024 + col) = make_float2(v2, v3);
            } else {
                *(__half2*)((__half*)Csel + (size_t)row0 * 1024 + col) =
                    __floats2half2_rn(v0, v1);
                *(__half2*)((__half*)Csel + (size_t)row1 * 1024 + col) =
                    __floats2half2_rn(v2, v3);
            }
        }
    }
}

// ---------------- prepass (p-split 4): Xsumh + partial xbar sums ----------------
__global__ void prepass_k(const float* __restrict__ x, const float* __restrict__ pos) {
    const int bt = blockIdx.y;
    const int t  = bt & 15;
    const int z  = blockIdx.z;
    const int d  = (blockIdx.x * 256 + threadIdx.x) * 2;
    const int p0 = z * 64;
    const float* xp = x   + ((size_t)bt * PP + p0) * DD + d;
    const float* pp = pos + ((size_t)t  * PP + p0) * DD + d;
    __half* op = g_Xsumh + ((size_t)bt * PP + p0) * DD + d;
    float sx = 0.f, sy = 0.f;
#pragma unroll 4
    for (int p = 0; p < 64; p++) {
        float2 a = *(const float2*)(xp + (size_t)p * DD);
        float2 b = *(const float2*)(pp + (size_t)p * DD);
        float vx = a.x + b.x, vy = a.y + b.y;
        sx += vx; sy += vy;
        *(__half2*)(op + (size_t)p * DD) = __floats2half2_rn(vx, vy);
    }
    float* xb = g_xbarp + ((size_t)z * BT + bt) * DD + d;
    xb[0] = sx; xb[1] = sy;
}

// ---------------- xbar reduce ----------------
__global__ void xred_k() {
    const int bt = blockIdx.y;
    const int d  = (blockIdx.x * 256 + threadIdx.x) * 2;
    float sx = 0.f, sy = 0.f;
#pragma unroll
    for (int z = 0; z < 4; z++) {
        const float* xb = g_xbarp + ((size_t)z * BT + bt) * DD + d;
        sx += xb[0]; sy += xb[1];
    }
    *(__half2*)(g_xbarh + (size_t)bt * DD + d) =
        __floats2half2_rn(sx * (1.0f / PP), sy * (1.0f / PP));
}

// ---------------- merged weight prep ----------------
__global__ void wprep_k(const float* __restrict__ W_in, const float* __restrict__ Bm,
                        const float* __restrict__ W_out, const float* __restrict__ Amat) {
    const int z = blockIdx.z;
    if (z < 2) {
        __shared__ float tile[32][33];
        const float* in = z ? Bm : W_in;
        __half* out = z ? g_BmTh : g_WinTRh;
        int x = blockIdx.x * 32 + threadIdx.x;
        int y = blockIdx.y * 32 + threadIdx.y;
#pragma unroll
        for (int i = 0; i < 32; i += 8)
            tile[threadIdx.y + i][threadIdx.x] = in[(size_t)(y + i) * DD + x];
        __syncthreads();
        x = blockIdx.y * 32 + threadIdx.x;
        y = blockIdx.x * 32 + threadIdx.y;
#pragma unroll
        for (int i = 0; i < 32; i += 8)
            out[(size_t)(y + i) * DD + x] =
                __float2half_rn(tile[threadIdx.x][threadIdx.y + i]);
    } else {
        const float* in = z == 2 ? W_out : (z == 3 ? Bm : Amat);
        __half* out = z == 2 ? g_WoutRh : (z == 3 ? g_BmRh : g_ARh);
        int x = blockIdx.x * 32 + threadIdx.x;
        int y = blockIdx.y * 32 + threadIdx.y;
#pragma unroll
        for (int i = 0; i < 32; i += 8)
            out[(size_t)(y + i) * DD + x] = __float2half_rn(in[(size_t)(y + i) * DD + x]);
    }
}

// ---------------- c / bq vectors ----------------
__global__ void dotrows2_k(const float* __restrict__ b_in, const float* __restrict__ b_out) {
    __shared__ float red[256];
    const int which = blockIdx.x >> 10;
    const int d = blockIdx.x & 1023;
    const int tid = threadIdx.x;
    const __half* row = (which ? g_BmTh : g_Hth) + (size_t)d * 1024;
    float s = 0.f;
    for (int j = tid; j < SS; j += 256) s += __half2float(row[j]) * b_in[j];
    red[tid] = s;
    __syncthreads();
    for (int o = 128; o > 0; o >>= 1) {
        if (tid < o) red[tid] += red[tid + o];
        __syncthreads();
    }
    if (tid == 0) {
        if (which) g_bq[d] = red[0];
        else       g_c[d]  = red[0] + b_out[d];
    }
}

// ---------------- sum 4 split-K partials ----------------
__global__ void sum4_k(const float* __restrict__ in, const float* __restrict__ addv,
                       float* __restrict__ out) {
    const int n = BT * 1024;
    int i = (blockIdx.x * 256 + threadIdx.x) * 4;
    float4 a = *(const float4*)(in + i);
    float4 b = *(const float4*)(in + n + i);
    float4 c = *(const float4*)(in + 2 * n + i);
    float4 d = *(const float4*)(in + 3 * n + i);
    float4 o;
    o.x = a.x + b.x + c.x + d.x; o.y = a.y + b.y + c.y + d.y;
    o.z = a.z + b.z + c.z + d.z; o.w = a.w + b.w + c.w + d.w;
    if (addv) {
        int col = i & 1023;
        float4 av = *(const float4*)(addv + col);
        o.x += av.x; o.y += av.y; o.z += av.z; o.w += av.w;
    }
    *(float4*)(out + i) = o;
}

// ---------------- scan ----------------
__global__ void scan_init_k(const float* __restrict__ init) {
    int s = blockIdx.x * 256 + threadIdx.x;
    float v = init[s];
#pragma unroll
    for (int b = 0; b < BB; b++) {
        g_states[(size_t)(b * 16) * SS + s] = v;
        g_statesh[(size_t)(b * 16) * SS + s] = __float2half_rn(v);
    }
}

__global__ void __launch_bounds__(256) scan_step_k(const float* __restrict__ Amat, int t) {
    __shared__ float st[BB][SS];
    __shared__ float red[BB][256];
    const int tid = threadIdx.x;
    for (int i = tid; i < BB * SS; i += 256) {
        int b = i >> 10, s = i & 1023;
        st[b][s] = g_states[(size_t)(b * 16 + t) * SS + s];
    }
    __syncthreads();
    const int col  = blockIdx.x * 16 + (tid & 15);
    const int part = tid >> 4;
    float acc[BB] = {};
    const int k0 = part * 64;
#pragma unroll 4
    for (int k = k0; k < k0 + 64; k++) {
        float av = Amat[(size_t)k * SS + col];
#pragma unroll
        for (int b = 0; b < BB; b++) acc[b] += st[b][k] * av;
    }
#pragma unroll
    for (int b = 0; b < BB; b++) red[b][tid] = acc[b];
    __syncthreads();
    for (int o = 8; o > 0; o >>= 1) {
        if (part < o) {
#pragma unroll
            for (int b = 0; b < BB; b++) red[b][tid] += red[b][tid + (o << 4)];
        }
        __syncthreads();
    }
    if (part == 0) {
#pragma unroll
        for (int b = 0; b < BB; b++) {
            float v = red[b][tid] + g_q[(size_t)(b * 16 + t) * SS + col];
            g_states[(size_t)(b * 16 + t + 1) * SS + col] = v;
            g_statesh[(size_t)(b * 16 + t + 1) * SS + col] = __float2half_rn(v);
        }
    }
}

// ---------------- host ----------------
extern "C" void kernel_launch(void* const* d_in, const int* in_sizes, int n_in,
                              void* d_out, int out_size) {
    const float* x     = (const float*)d_in[0];
    const float* pos   = (const float*)d_in[1];
    const float* W_in  = (const float*)d_in[2];
    const float* b_in  = (const float*)d_in[3];
    const float* W_out = (const float*)d_in[4];
    const float* b_out = (const float*)d_in[5];
    const float* Amat  = (const float*)d_in[6];
    const float* Bm    = (const float*)d_in[7];
    const float* init  = (const float*)d_in[8];
    float* out = (float*)d_out;

    __half *WoutRh, *BmRh, *ARh, *WinTRh, *BmTh, *Hth, *Gth, *MqTh, *MwTh, *Xsumh, *xbarh, *statesh;
    float *qp, *rp, *q, *r, *bqv;
    cudaGetSymbolAddress((void**)&WoutRh, g_WoutRh);
    cudaGetSymbolAddress((void**)&BmRh,   g_BmRh);
    cudaGetSymbolAddress((void**)&ARh,    g_ARh);
    cudaGetSymbolAddress((void**)&WinTRh, g_WinTRh);
    cudaGetSymbolAddress((void**)&BmTh,   g_BmTh);
    cudaGetSymbolAddress((void**)&Hth,    g_Hth);
    cudaGetSymbolAddress((void**)&Gth,    g_Gth);
    cudaGetSymbolAddress((void**)&MqTh,   g_MqTh);
    cudaGetSymbolAddress((void**)&MwTh,   g_MwTh);
    cudaGetSymbolAddress((void**)&Xsumh,  g_Xsumh);
    cudaGetSymbolAddress((void**)&xbarh,  g_xbarh);
    cudaGetSymbolAddress((void**)&statesh,g_statesh);
    cudaGetSymbolAddress((void**)&qp,     g_qp);
    cudaGetSymbolAddress((void**)&rp,     g_rp);
    cudaGetSymbolAddress((void**)&q,      g_q);
    cudaGetSymbolAddress((void**)&r,      g_r);
    cudaGetSymbolAddress((void**)&bqv,    g_bq);

    static bool s_init = false;
    static cudaStream_t s2 = 0;
    static cudaEvent_t e0, eP, eW, eR;
    if (!s_init) {
        if (cudaStreamCreateWithFlags(&s2, cudaStreamNonBlocking) != cudaSuccess) s2 = 0;
        cudaEventCreateWithFlags(&e0, cudaEventDisableTiming);
        cudaEventCreateWithFlags(&eP, cudaEventDisableTiming);
        cudaEventCreateWithFlags(&eW, cudaEventDisableTiming);
        cudaEventCreateWithFlags(&eR, cudaEventDisableTiming);
        cudaFuncSetAttribute((const void*)f16g<0, 1>,
                             cudaFuncAttributeMaxDynamicSharedMemorySize, GEMM_SM);
        cudaFuncSetAttribute((const void*)f16g<1, 4>,
                             cudaFuncAttributeMaxDynamicSharedMemorySize, GEMM_SM);
        cudaFuncSetAttribute((const void*)f16g<2, 1>,
                             cudaFuncAttributeMaxDynamicSharedMemorySize, GEMM_SM);
        s_init = true;
    }

    // ---- fork ----
    cudaEventRecord(e0, 0);
    prepass_k<<<dim3(2, BT, 4), 256>>>(x, pos);
    xred_k<<<dim3(2, BT), 256>>>();
    cudaEventRecord(eP, 0);

    cudaStreamWaitEvent(s2, e0, 0);
    wprep_k<<<dim3(32, 32, 5), dim3(32, 8), 0, s2>>>(W_in, Bm, W_out, Amat);
    f16g<0, 1><<<dim3(8, 8, 3), 128, GEMM_SM, s2>>>(
        WoutRh, WoutRh, BmTh, BmRh, ARh, WinTRh, Hth, Gth, MqTh);
    f16g<0, 1><<<dim3(8, 8, 1), 128, GEMM_SM, s2>>>(
        Hth, nullptr, nullptr, WinTRh, nullptr, nullptr, MwTh, nullptr, nullptr);
    cudaEventRecord(eW, s2);

    dotrows2_k<<<2048, 256, 0, s2>>>(b_in, b_out);
    cudaStreamWaitEvent(s2, eP, 0);
    f16g<1, 4><<<dim3(8, 1, 4), 128, GEMM_SM, s2>>>(
        xbarh, nullptr, nullptr, MqTh, nullptr, nullptr, qp, nullptr, nullptr);
    sum4_k<<<128, 256, 0, s2>>>(qp, bqv, q);
    scan_init_k<<<4, 256, 0, s2>>>(init);
    for (int t = 0; t < 15; t++) scan_step_k<<<64, 256, 0, s2>>>(Amat, t);
    f16g<1, 4><<<dim3(8, 1, 4), 128, GEMM_SM, s2>>>(
        statesh, nullptr, nullptr, Gth, nullptr, nullptr, rp, nullptr, nullptr);
    sum4_k<<<128, 256, 0, s2>>>(rp, nullptr, r);
    cudaEventRecord(eR, s2);

    // ---- main GEMM fused with r+c epilogue ----
    cudaStreamWaitEvent(0, eW, 0);
    cudaStreamWaitEvent(0, eR, 0);
    f16g<2, 1><<<dim3(8, 256, 1), 128, GEMM_SM>>>(
        Xsumh, nullptr, nullptr, MwTh, nullptr, nullptr, out, nullptr, nullptr);
}

// round 12
// speedup vs baseline: 5.5159x; 1.0227x over previous
#include <cuda_runtime.h>
#include <cuda_fp16.h>
#include <cstdint>

#define DD   1024
#define SS   1024
#define TT   16
#define PP   256
#define BB   8
#define BT   128
#define MROWS 32768

// ---------------- device scratch ----------------
__device__ __half g_WoutRh[DD*SS];
__device__ __half g_BmRh [SS*SS];
__device__ __half g_ARh  [SS*SS];
__device__ __half g_WinTRh[DD*SS];
__device__ __half g_BmTh [SS*SS];
__device__ __half g_Hth  [DD*SS];
__device__ __half g_Gth  [DD*SS];
__device__ __half g_MqTh [SS*DD];
__device__ __half g_MwTh [DD*DD];
__device__ __half g_Xsumh[(size_t)MROWS*DD];
__device__ __half g_xbarh[BT*DD];
__device__ __half g_statesh[BT*SS];
__device__ float g_xbarp[4*BT*DD];
__device__ float g_qp  [4*BT*SS];
__device__ float g_rp  [4*BT*DD];
__device__ float g_q   [BT*SS];
__device__ float g_states[BT*SS];
__device__ float g_r   [BT*DD];
__device__ float g_c   [DD];
__device__ float g_bq  [SS];

// ---------------- helpers ----------------
__device__ __forceinline__ uint32_t smem_u32(const void* p) {
    uint32_t a;
    asm("{ .reg .u64 t; cvta.to.shared.u64 t, %1; cvt.u32.u64 %0, t; }" : "=r"(a) : "l"(p));
    return a;
}
__device__ __forceinline__ void cp_async16(uint32_t dst, const void* src) {
    asm volatile("cp.async.cg.shared.global [%0], [%1], 16;" :: "r"(dst), "l"(src) : "memory");
}
#define CP_COMMIT() asm volatile("cp.async.commit_group;" ::: "memory")
#define CP_WAIT1()  asm volatile("cp.async.wait_group 1;" ::: "memory")

__device__ __forceinline__ void ldsm_x4(uint32_t* r, uint32_t addr) {
    asm volatile("ldmatrix.sync.aligned.m8n8.x4.shared.b16 {%0,%1,%2,%3}, [%4];"
        : "=r"(r[0]), "=r"(r[1]), "=r"(r[2]), "=r"(r[3]) : "r"(addr));
}
__device__ __forceinline__ void mma_f16(float* d, const uint32_t* a, const uint32_t* b) {
    asm volatile(
        "mma.sync.aligned.m16n8k16.row.col.f32.f16.f16.f32 "
        "{%0,%1,%2,%3}, {%4,%5,%6,%7}, {%8,%9}, {%0,%1,%2,%3};"
        : "+f"(d[0]), "+f"(d[1]), "+f"(d[2]), "+f"(d[3])
        : "r"(a[0]), "r"(a[1]), "r"(a[2]), "r"(a[3]), "r"(b[0]), "r"(b[1]));
}

// ================= fp16 NT GEMM: C = A[M,K] @ Bt[N,K]^T, fp32 accum =================
// CTA tile 128x128, 128 threads = 4 warps (2m x 2n), warp tile 64x64, 3-stage
// pipeline (2 chunks in flight), 2 CTAs/SM, register-double-buffered fragments.
// EPI: 0 = half; 1 = float split-K partial; 2 = float + g_r[bt] + g_c.
#define OPA_B   18432u              // 128 rows * 144B
#define STAGE_B 36864u              // 256 rows * 144B
#define GEMM_SM (3 * 36864)

template <int EPI, int KSPLIT>
__global__ void __launch_bounds__(128, 2) f16g(
    const __half* __restrict__ A0, const __half* __restrict__ A1, const __half* __restrict__ A2,
    const __half* __restrict__ B0, const __half* __restrict__ B1, const __half* __restrict__ B2,
    void* __restrict__ C0, void* __restrict__ C1, void* __restrict__ C2)
{
    constexpr int CH = 16 / KSPLIT;

    extern __shared__ char smem[];
    const uint32_t sb = smem_u32(smem);

    const int tid  = threadIdx.x;
    const int lane = tid & 31;
    const int w    = tid >> 5;
    const int wm   = (w >> 1) * 64;
    const int wn   = (w & 1) * 64;
    const int g    = lane >> 2;
    const int tg   = lane & 3;

    const int zm = blockIdx.z / KSPLIT;
    const int ks = blockIdx.z % KSPLIT;
    const __half* __restrict__ Asel = zm == 0 ? A0 : (zm == 1 ? A1 : A2);
    const __half* __restrict__ Bsel = zm == 0 ? B0 : (zm == 1 ? B1 : B2);
    void* __restrict__ Csel         = zm == 0 ? C0 : (zm == 1 ? C1 : C2);

    const int rowBase = blockIdx.y * 128;
    const int colBase = blockIdx.x * 128;
    const __half* __restrict__ Ag = Asel + (size_t)rowBase * 1024;
    const __half* __restrict__ Bg = Bsel + (size_t)colBase * 1024;
    const int Mrows = gridDim.y * 128;

    float acc[4][8][4];
#pragma unroll
    for (int i = 0; i < 4; i++)
#pragma unroll
        for (int j = 0; j < 8; j++)
#pragma unroll
            for (int k = 0; k < 4; k++) acc[i][j][k] = 0.f;

    auto load_stage = [&](int chunk, int st) {
        const uint32_t dA = sb + st * STAGE_B;
        const uint32_t dB = dA + OPA_B;
        const int k0 = chunk * 64;
#pragma unroll
        for (int i = 0; i < 8; i++) {
            int idx = i * 128 + tid;
            int r = idx >> 3, c = idx & 7;
            cp_async16(dA + r * 144 + c * 16, Ag + (size_t)r * 1024 + k0 + c * 8);
        }
#pragma unroll
        for (int i = 0; i < 8; i++) {
            int idx = i * 128 + tid;
            int r = idx >> 3, c = idx & 7;
            cp_async16(dB + r * 144 + c * 16, Bg + (size_t)r * 1024 + k0 + c * 8);
        }
        CP_COMMIT();
    };

    const uint32_t aoff = (uint32_t)((wm + (lane & 15)) * 144 + ((lane >> 4) << 4));
    const uint32_t boff = (uint32_t)((wn + ((lane >> 4) << 3) + (lane & 7)) * 144 +
                                     (((lane >> 3) & 1) << 4));

    auto compute = [&](int st) {
        const uint32_t ab = sb + st * STAGE_B + aoff;
        const uint32_t bb = sb + st * STAGE_B + OPA_B + boff;
        uint32_t a[2][4][4], bq[2][4][4];
        // prefetch kk=0 fragments
#pragma unroll
        for (int mi = 0; mi < 4; mi++) ldsm_x4(a[0][mi], ab + mi * 2304);
#pragma unroll
        for (int nj = 0; nj < 4; nj++) ldsm_x4(bq[0][nj], bb + nj * 2304);
#pragma unroll
        for (int kk = 0; kk < 4; kk++) {
            const int cur = kk & 1, nxt = cur ^ 1;
            if (kk < 3) {
                const uint32_t kb = (kk + 1) * 32;
#pragma unroll
                for (int mi = 0; mi < 4; mi++) ldsm_x4(a[nxt][mi], ab + mi * 2304 + kb);
#pragma unroll
                for (int nj = 0; nj < 4; nj++) ldsm_x4(bq[nxt][nj], bb + nj * 2304 + kb);
            }
#pragma unroll
            for (int mi = 0; mi < 4; mi++)
#pragma unroll
                for (int ni = 0; ni < 8; ni++)
                    mma_f16(acc[mi][ni], a[cur][mi], &bq[cur][ni >> 1][(ni & 1) * 2]);
        }
    };

    // prologue: 2 chunks in flight
    load_stage(ks * CH + 0, 0);
    load_stage(ks * CH + 1, 1);

    int st = 0;
#pragma unroll 1
    for (int c = 0; c < CH; c++) {
        CP_WAIT1();
        __syncthreads();
        if (c + 2 < CH) {
            int nst = st + 2; if (nst >= 3) nst -= 3;
            load_stage(ks * CH + c + 2, nst);
        } else {
            CP_COMMIT();
        }
        compute(st);
        if (++st == 3) st = 0;
    }

#pragma unroll
    for (int mi = 0; mi < 4; mi++) {
        const int row0 = rowBase + wm + mi * 16 + g;
        const int row1 = row0 + 8;
#pragma unroll
        for (int ni = 0; ni < 8; ni++) {
            const int col = colBase + wn + ni * 8 + tg * 2;
            float v0 = acc[mi][ni][0], v1 = acc[mi][ni][1];
            float v2 = acc[mi][ni][2], v3 = acc[mi][ni][3];
            if (EPI == 2) {
                float2 ra = *(const float2*)(g_r + (size_t)(row0 >> 8) * 1024 + col);
                float2 rb = *(const float2*)(g_r + (size_t)(row1 >> 8) * 1024 + col);
                float2 cc = *(const float2*)(g_c + col);
                *(float2*)((float*)Csel + (size_t)row0 * 1024 + col) =
                    make_float2(v0 + ra.x + cc.x, v1 + ra.y + cc.y);
                *(float2*)((float*)Csel + (size_t)row1 * 1024 + col) =
                    make_float2(v2 + rb.x + cc.x, v3 + rb.y + cc.y);
            } else if (EPI == 1) {
                float* Cf = (float*)Csel + (size_t)ks * Mrows * 1024;
                *(float2*)(Cf + (size_t)row0 * 1024 + col) = make_float2(v0, v1);
                *(float2*)(Cf + (size_t)row1 * 1024 + col) = make_float2(v2, v3);
            } else {
                *(__half2*)((__half*)Csel + (size_t)row0 * 1024 + col) =
                    __floats2half2_rn(v0, v1);
                *(__half2*)((__half*)Csel + (size_t)row1 * 1024 + col) =
                    __floats2half2_rn(v2, v3);
            }
        }
    }
}

// ---------------- prepass (p-split 4): Xsumh + partial xbar sums ----------------
__global__ void prepass_k(const float* __restrict__ x, const float* __restrict__ pos) {
    const int bt = blockIdx.y;
    const int t  = bt & 15;
    const int z  = blockIdx.z;
    const int d  = (blockIdx.x * 256 + threadIdx.x) * 2;
    const int p0 = z * 64;
    const float* xp = x   + ((size_t)bt * PP + p0) * DD + d;
    const float* pp = pos + ((size_t)t  * PP + p0) * DD + d;
    __half* op = g_Xsumh + ((size_t)bt * PP + p0) * DD + d;
    float sx = 0.f, sy = 0.f;
#pragma unroll 4
    for (int p = 0; p < 64; p++) {
        float2 a = *(const float2*)(xp + (size_t)p * DD);
        float2 b = *(const float2*)(pp + (size_t)p * DD);
        float vx = a.x + b.x, vy = a.y + b.y;
        sx += vx; sy += vy;
        *(__half2*)(op + (size_t)p * DD) = __floats2half2_rn(vx, vy);
    }
    float* xb = g_xbarp + ((size_t)z * BT + bt) * DD + d;
    xb[0] = sx; xb[1] = sy;
}

// ---------------- xbar reduce ----------------
__global__ void xred_k() {
    const int bt = blockIdx.y;
    const int d  = (blockIdx.x * 256 + threadIdx.x) * 2;
    float sx = 0.f, sy = 0.f;
#pragma unroll
    for (int z = 0; z < 4; z++) {
        const float* xb = g_xbarp + ((size_t)z * BT + bt) * DD + d;
        sx += xb[0]; sy += xb[1];
    }
    *(__half2*)(g_xbarh + (size_t)bt * DD + d) =
        __floats2half2_rn(sx * (1.0f / PP), sy * (1.0f / PP));
}

// ---------------- merged weight prep ----------------
__global__ void wprep_k(const float* __restrict__ W_in, const float* __restrict__ Bm,
                        const float* __restrict__ W_out, const float* __restrict__ Amat) {
    const int z = blockIdx.z;
    if (z < 2) {
        __shared__ float tile[32][33];
        const float* in = z ? Bm : W_in;
        __half* out = z ? g_BmTh : g_WinTRh;
        int x = blockIdx.x * 32 + threadIdx.x;
        int y = blockIdx.y * 32 + threadIdx.y;
#pragma unroll
        for (int i = 0; i < 32; i += 8)
            tile[threadIdx.y + i][threadIdx.x] = in[(size_t)(y + i) * DD + x];
        __syncthreads();
        x = blockIdx.y * 32 + threadIdx.x;
        y = blockIdx.x * 32 + threadIdx.y;
#pragma unroll
        for (int i = 0; i < 32; i += 8)
            out[(size_t)(y + i) * DD + x] =
                __float2half_rn(tile[threadIdx.x][threadIdx.y + i]);
    } else {
        const float* in = z == 2 ? W_out : (z == 3 ? Bm : Amat);
        __half* out = z == 2 ? g_WoutRh : (z == 3 ? g_BmRh : g_ARh);
        int x = blockIdx.x * 32 + threadIdx.x;
        int y = blockIdx.y * 32 + threadIdx.y;
#pragma unroll
        for (int i = 0; i < 32; i += 8)
            out[(size_t)(y + i) * DD + x] = __float2half_rn(in[(size_t)(y + i) * DD + x]);
    }
}

// ---------------- c / bq vectors ----------------
__global__ void dotrows2_k(const float* __restrict__ b_in, const float* __restrict__ b_out) {
    __shared__ float red[256];
    const int which = blockIdx.x >> 10;
    const int d = blockIdx.x & 1023;
    const int tid = threadIdx.x;
    const __half* row = (which ? g_BmTh : g_Hth) + (size_t)d * 1024;
    float s = 0.f;
    for (int j = tid; j < SS; j += 256) s += __half2float(row[j]) * b_in[j];
    red[tid] = s;
    __syncthreads();
    for (int o = 128; o > 0; o >>= 1) {
        if (tid < o) red[tid] += red[tid + o];
        __syncthreads();
    }
    if (tid == 0) {
        if (which) g_bq[d] = red[0];
        else       g_c[d]  = red[0] + b_out[d];
    }
}

// ---------------- sum 4 split-K partials ----------------
__global__ void sum4_k(const float* __restrict__ in, const float* __restrict__ addv,
                       float* __restrict__ out) {
    const int n = BT * 1024;
    int i = (blockIdx.x * 256 + threadIdx.x) * 4;
    float4 a = *(const float4*)(in + i);
    float4 b = *(const float4*)(in + n + i);
    float4 c = *(const float4*)(in + 2 * n + i);
    float4 d = *(const float4*)(in + 3 * n + i);
    float4 o;
    o.x = a.x + b.x + c.x + d.x; o.y = a.y + b.y + c.y + d.y;
    o.z = a.z + b.z + c.z + d.z; o.w = a.w + b.w + c.w + d.w;
    if (addv) {
        int col = i & 1023;
        float4 av = *(const float4*)(addv + col);
        o.x += av.x; o.y += av.y; o.z += av.z; o.w += av.w;
    }
    *(float4*)(out + i) = o;
}

// ---------------- scan ----------------
__global__ void scan_init_k(const float* __restrict__ init) {
    int s = blockIdx.x * 256 + threadIdx.x;
    float v = init[s];
#pragma unroll
    for (int b = 0; b < BB; b++) {
        g_states[(size_t)(b * 16) * SS + s] = v;
        g_statesh[(size_t)(b * 16) * SS + s] = __float2half_rn(v);
    }
}

__global__ void __launch_bounds__(256) scan_step_k(const float* __restrict__ Amat, int t) {
    __shared__ float st[BB][SS];
    __shared__ float red[BB][256];
    const int tid = threadIdx.x;
    for (int i = tid; i < BB * SS; i += 256) {
        int b = i >> 10, s = i & 1023;
        st[b][s] = g_states[(size_t)(b * 16 + t) * SS + s];
    }
    __syncthreads();
    const int col  = blockIdx.x * 16 + (tid & 15);
    const int part = tid >> 4;
    float acc[BB] = {};
    const int k0 = part * 64;
#pragma unroll 4
    for (int k = k0; k < k0 + 64; k++) {
        float av = Amat[(size_t)k * SS + col];
#pragma unroll
        for (int b = 0; b < BB; b++) acc[b] += st[b][k] * av;
    }
#pragma unroll
    for (int b = 0; b < BB; b++) red[b][tid] = acc[b];
    __syncthreads();
    for (int o = 8; o > 0; o >>= 1) {
        if (part < o) {
#pragma unroll
            for (int b = 0; b < BB; b++) red[b][tid] += red[b][tid + (o << 4)];
        }
        __syncthreads();
    }
    if (part == 0) {
#pragma unroll
        for (int b = 0; b < BB; b++) {
            float v = red[b][tid] + g_q[(size_t)(b * 16 + t) * SS + col];
            g_states[(size_t)(b * 16 + t + 1) * SS + col] = v;
            g_statesh[(size_t)(b * 16 + t + 1) * SS + col] = __float2half_rn(v);
        }
    }
}

// ---------------- host ----------------
extern "C" void kernel_launch(void* const* d_in, const int* in_sizes, int n_in,
                              void* d_out, int out_size) {
    const float* x     = (const float*)d_in[0];
    const float* pos   = (const float*)d_in[1];
    const float* W_in  = (const float*)d_in[2];
    const float* b_in  = (const float*)d_in[3];
    const float* W_out = (const float*)d_in[4];
    const float* b_out = (const float*)d_in[5];
    const float* Amat  = (const float*)d_in[6];
    const float* Bm    = (const float*)d_in[7];
    const float* init  = (const float*)d_in[8];
    float* out = (float*)d_out;

    __half *WoutRh, *BmRh, *ARh, *WinTRh, *BmTh, *Hth, *Gth, *MqTh, *MwTh, *Xsumh, *xbarh, *statesh;
    float *qp, *rp, *q, *r, *bqv;
    cudaGetSymbolAddress((void**)&WoutRh, g_WoutRh);
    cudaGetSymbolAddress((void**)&BmRh,   g_BmRh);
    cudaGetSymbolAddress((void**)&ARh,    g_ARh);
    cudaGetSymbolAddress((void**)&WinTRh, g_WinTRh);
    cudaGetSymbolAddress((void**)&BmTh,   g_BmTh);
    cudaGetSymbolAddress((void**)&Hth,    g_Hth);
    cudaGetSymbolAddress((void**)&Gth,    g_Gth);
    cudaGetSymbolAddress((void**)&MqTh,   g_MqTh);
    cudaGetSymbolAddress((void**)&MwTh,   g_MwTh);
    cudaGetSymbolAddress((void**)&Xsumh,  g_Xsumh);
    cudaGetSymbolAddress((void**)&xbarh,  g_xbarh);
    cudaGetSymbolAddress((void**)&statesh,g_statesh);
    cudaGetSymbolAddress((void**)&qp,     g_qp);
    cudaGetSymbolAddress((void**)&rp,     g_rp);
    cudaGetSymbolAddress((void**)&q,      g_q);
    cudaGetSymbolAddress((void**)&r,      g_r);
    cudaGetSymbolAddress((void**)&bqv,    g_bq);

    static bool s_init = false;
    static cudaStream_t s2 = 0, s3 = 0;
    static cudaEvent_t e0, eP, eB, eW, eR;
    if (!s_init) {
        if (cudaStreamCreateWithFlags(&s2, cudaStreamNonBlocking) != cudaSuccess) s2 = 0;
        if (cudaStreamCreateWithFlags(&s3, cudaStreamNonBlocking) != cudaSuccess) s3 = s2;
        cudaEventCreateWithFlags(&e0, cudaEventDisableTiming);
        cudaEventCreateWithFlags(&eP, cudaEventDisableTiming);
        cudaEventCreateWithFlags(&eB, cudaEventDisableTiming);
        cudaEventCreateWithFlags(&eW, cudaEventDisableTiming);
        cudaEventCreateWithFlags(&eR, cudaEventDisableTiming);
        cudaFuncSetAttribute((const void*)f16g<0, 1>,
                             cudaFuncAttributeMaxDynamicSharedMemorySize, GEMM_SM);
        cudaFuncSetAttribute((const void*)f16g<1, 4>,
                             cudaFuncAttributeMaxDynamicSharedMemorySize, GEMM_SM);
        cudaFuncSetAttribute((const void*)f16g<2, 1>,
                             cudaFuncAttributeMaxDynamicSharedMemorySize, GEMM_SM);
        s_init = true;
    }

    // ---- fork ----
    cudaEventRecord(e0, 0);
    prepass_k<<<dim3(2, BT, 4), 256>>>(x, pos);
    xred_k<<<dim3(2, BT), 256>>>();
    cudaEventRecord(eP, 0);

    // s2: weight prep + 3-batch precompute, then q/scan/r chain
    cudaStreamWaitEvent(s2, e0, 0);
    wprep_k<<<dim3(32, 32, 5), dim3(32, 8), 0, s2>>>(W_in, Bm, W_out, Amat);
    f16g<0, 1><<<dim3(8, 8, 3), 128, GEMM_SM, s2>>>(
        WoutRh, WoutRh, BmTh, BmRh, ARh, WinTRh, Hth, Gth, MqTh);
    cudaEventRecord(eB, s2);

    // s3: MwTh GEMM + c/bq vectors (gates main via eW, off the eR path)
    cudaStreamWaitEvent(s3, eB, 0);
    dotrows2_k<<<2048, 256, 0, s3>>>(b_in, b_out);
    f16g<0, 1><<<dim3(8, 8, 1), 128, GEMM_SM, s3>>>(
        Hth, nullptr, nullptr, WinTRh, nullptr, nullptr, MwTh, nullptr, nullptr);
    cudaEventRecord(eW, s3);

    // s2 continues: q -> scan -> r  (needs MqTh from eB, xbar from eP)
    cudaStreamWaitEvent(s2, eP, 0);
    f16g<1, 4><<<dim3(8, 1, 4), 128, GEMM_SM, s2>>>(
        xbarh, nullptr, nullptr, MqTh, nullptr, nullptr, qp, nullptr, nullptr);
    sum4_k<<<128, 256, 0, s2>>>(qp, bqv, q);            // bq ready? -> see note
    scan_init_k<<<4, 256, 0, s2>>>(init);
    for (int t = 0; t < 15; t++) scan_step_k<<<64, 256, 0, s2>>>(Amat, t);
    f16g<1, 4><<<dim3(8, 1, 4), 128, GEMM_SM, s2>>>(
        statesh, nullptr, nullptr, Gth, nullptr, nullptr, rp, nullptr, nullptr);
    sum4_k<<<128, 256, 0, s2>>>(rp, nullptr, r);
    cudaEventRecord(eR, s2);

    // ---- main GEMM fused with r+c epilogue ----
    cudaStreamWaitEvent(0, eW, 0);
    cudaStreamWaitEvent(0, eR, 0);
    f16g<2, 1><<<dim3(8, 256, 1), 128, GEMM_SM>>>(
        Xsumh, nullptr, nullptr, MwTh, nullptr, nullptr, out, nullptr, nullptr);
}